// round 1
// baseline (speedup 1.0000x reference)
#include <cuda_runtime.h>
#include <math.h>
#include <stdint.h>

#define N_NODES 50000
#define N_EDGES 1600000
#define DIM     128
#define EDGE_DIM 16
#define IN_DIM  272          // 2*DIM + EDGE_DIM
#define TE      16           // edges per tile
#define NT      (N_EDGES / TE)   // 100000 tiles

// ---------------- shared memory layout (floats) ----------------
// W1s : [272][128] = 34816
// W2s : [128][128] = 16384
// xs  : [272][16]  =  4352   (x transposed: xs[k][e])
// hdn : [16][129]  =  2064   (padded row for conflict-free scalar reads)
// b1s : 128, b2s : 128
// sidx/didx : 32 ints
#define OFF_W1  0
#define OFF_W2  34816
#define OFF_XS  51200
#define OFF_HDN 55552
#define OFF_B1  57616
#define OFF_B2  57744
#define OFF_IDX 57872
#define SMEM_FLOATS (57872 + 32)
#define SMEM_BYTES  (SMEM_FLOATS * 4)   // 231,616 B <= 227KB dyn max

// scratch accumulator (allocation-free: __device__ global)
__device__ float g_agg[(size_t)N_NODES * DIM];

// ---------------------------------------------------------------
__global__ void zero_agg_kernel() {
    float4* p = reinterpret_cast<float4*>(g_agg);
    const int n = N_NODES * DIM / 4;
    for (int i = blockIdx.x * blockDim.x + threadIdx.x; i < n;
         i += gridDim.x * blockDim.x)
        p[i] = make_float4(0.f, 0.f, 0.f, 0.f);
}

__device__ __forceinline__ float gelu_exact(float v) {
    return 0.5f * v * (1.0f + erff(v * 0.70710678118654752440f));
}

// ---------------------------------------------------------------
__global__ __launch_bounds__(256, 1)
void edge_mlp_kernel(const float* __restrict__ h,
                     const int*   __restrict__ src,
                     const int*   __restrict__ dst,
                     const float* __restrict__ ea,
                     const float* __restrict__ W1,
                     const float* __restrict__ b1,
                     const float* __restrict__ W2,
                     const float* __restrict__ b2) {
    extern __shared__ float sm[];
    float* W1s = sm + OFF_W1;
    float* W2s = sm + OFF_W2;
    float* xs  = sm + OFF_XS;
    float* hdn = sm + OFF_HDN;
    float* b1s = sm + OFF_B1;
    float* b2s = sm + OFF_B2;
    int*   sidx = reinterpret_cast<int*>(sm + OFF_IDX);
    int*   didx = sidx + TE;

    const int t = threadIdx.x;

    // ---- stage weights & biases once per (persistent) block ----
    {
        const float4* W1g = reinterpret_cast<const float4*>(W1);
        float4*       W1d = reinterpret_cast<float4*>(W1s);
        for (int i = t; i < IN_DIM * 32; i += 256) W1d[i] = W1g[i];
        const float4* W2g = reinterpret_cast<const float4*>(W2);
        float4*       W2d = reinterpret_cast<float4*>(W2s);
        for (int i = t; i < DIM * 32; i += 256) W2d[i] = W2g[i];
        if (t < DIM) { b1s[t] = b1[t]; b2s[t] = b2[t]; }
    }

    const int lane = t & 31;
    const int warp = t >> 5;
    // thread tile: 2 edges (m0, m0+1) x 4 outputs (n0..n0+3)
    const int m0 = 2 * (lane & 7);
    const int n0 = warp * 16 + 4 * (lane >> 3);

    const float2* xp  = reinterpret_cast<const float2*>(xs) + (m0 >> 1);  // + k*8
    const float4* w1p = reinterpret_cast<const float4*>(W1s) + (n0 >> 2); // + k*32
    const float4* w2p = reinterpret_cast<const float4*>(W2s) + (n0 >> 2); // + k*32

    const int e_of_t = t & 15;
    const int c0     = t >> 4;   // 0..15

    for (int tile = blockIdx.x; tile < NT; tile += gridDim.x) {
        __syncthreads();   // previous tile fully consumed (also covers weight staging)
        const int e0 = tile * TE;
        if (t < TE) { sidx[t] = src[e0 + t]; didx[t] = dst[e0 + t]; }
        __syncthreads();

        // ---- gather x -> xs[k][e] (transposed) ----
        {
            const int s = sidx[e_of_t];
            const int d = didx[e_of_t];
            const float4* hs  = reinterpret_cast<const float4*>(h) + (size_t)s * 32;
            const float4* hd  = reinterpret_cast<const float4*>(h) + (size_t)d * 32;
            const float4* eap = reinterpret_cast<const float4*>(ea) +
                                (size_t)(e0 + e_of_t) * 4;
            #pragma unroll
            for (int c = c0; c < 68; c += 16) {
                float4 v = (c < 32) ? hs[c] : (c < 64) ? hd[c - 32] : eap[c - 64];
                const int kb = 4 * c;
                xs[(kb + 0) * TE + e_of_t] = v.x;
                xs[(kb + 1) * TE + e_of_t] = v.y;
                xs[(kb + 2) * TE + e_of_t] = v.z;
                xs[(kb + 3) * TE + e_of_t] = v.w;
            }
        }
        __syncthreads();

        // ---- GEMM1: hdn = gelu(x @ W1 + b1) ----
        float acc00 = 0.f, acc01 = 0.f, acc02 = 0.f, acc03 = 0.f;
        float acc10 = 0.f, acc11 = 0.f, acc12 = 0.f, acc13 = 0.f;
        #pragma unroll 4
        for (int k = 0; k < IN_DIM; ++k) {
            const float2 xv = xp[k * 8];
            const float4 wv = w1p[k * 32];
            acc00 += xv.x * wv.x; acc01 += xv.x * wv.y;
            acc02 += xv.x * wv.z; acc03 += xv.x * wv.w;
            acc10 += xv.y * wv.x; acc11 += xv.y * wv.y;
            acc12 += xv.y * wv.z; acc13 += xv.y * wv.w;
        }
        {
            const float bb0 = b1s[n0 + 0], bb1 = b1s[n0 + 1];
            const float bb2 = b1s[n0 + 2], bb3 = b1s[n0 + 3];
            float* r0 = hdn + m0 * 129 + n0;
            float* r1 = hdn + (m0 + 1) * 129 + n0;
            r0[0] = gelu_exact(acc00 + bb0);
            r0[1] = gelu_exact(acc01 + bb1);
            r0[2] = gelu_exact(acc02 + bb2);
            r0[3] = gelu_exact(acc03 + bb3);
            r1[0] = gelu_exact(acc10 + bb0);
            r1[1] = gelu_exact(acc11 + bb1);
            r1[2] = gelu_exact(acc12 + bb2);
            r1[3] = gelu_exact(acc13 + bb3);
        }
        __syncthreads();

        // ---- GEMM2: msg = hdn @ W2 + b2 ----
        float d00 = 0.f, d01 = 0.f, d02 = 0.f, d03 = 0.f;
        float d10 = 0.f, d11 = 0.f, d12 = 0.f, d13 = 0.f;
        const float* h0 = hdn + m0 * 129;
        const float* h1 = hdn + (m0 + 1) * 129;
        #pragma unroll 4
        for (int k = 0; k < DIM; ++k) {
            const float x0 = h0[k];
            const float x1 = h1[k];
            const float4 wv = w2p[k * 32];
            d00 += x0 * wv.x; d01 += x0 * wv.y; d02 += x0 * wv.z; d03 += x0 * wv.w;
            d10 += x1 * wv.x; d11 += x1 * wv.y; d12 += x1 * wv.z; d13 += x1 * wv.w;
        }
        {
            const float bb0 = b2s[n0 + 0], bb1 = b2s[n0 + 1];
            const float bb2 = b2s[n0 + 2], bb3 = b2s[n0 + 3];
            float* p0 = g_agg + (size_t)didx[m0] * DIM + n0;
            asm volatile("red.global.add.v4.f32 [%0], {%1,%2,%3,%4};"
                         :: "l"(p0), "f"(d00 + bb0), "f"(d01 + bb1),
                            "f"(d02 + bb2), "f"(d03 + bb3) : "memory");
            float* p1 = g_agg + (size_t)didx[m0 + 1] * DIM + n0;
            asm volatile("red.global.add.v4.f32 [%0], {%1,%2,%3,%4};"
                         :: "l"(p1), "f"(d10 + bb0), "f"(d11 + bb1),
                            "f"(d12 + bb2), "f"(d13 + bb3) : "memory");
        }
    }
}

// ---------------------------------------------------------------
// LayerNorm(h + agg): one warp per row, 4 floats per lane.
__global__ __launch_bounds__(256)
void ln_kernel(const float* __restrict__ h,
               const float* __restrict__ gamma,
               const float* __restrict__ beta,
               float* __restrict__ out) {
    const int row  = (blockIdx.x * blockDim.x + threadIdx.x) >> 5;
    const int lane = threadIdx.x & 31;
    if (row >= N_NODES) return;

    const float4 hv = reinterpret_cast<const float4*>(h)[(size_t)row * 32 + lane];
    const float4 av = reinterpret_cast<const float4*>(g_agg)[(size_t)row * 32 + lane];
    float4 x;
    x.x = hv.x + av.x; x.y = hv.y + av.y; x.z = hv.z + av.z; x.w = hv.w + av.w;

    float s = x.x + x.y + x.z + x.w;
    #pragma unroll
    for (int o = 16; o > 0; o >>= 1) s += __shfl_xor_sync(0xffffffffu, s, o);
    const float mu = s * (1.0f / 128.0f);

    const float dx = x.x - mu, dy = x.y - mu, dz = x.z - mu, dw = x.w - mu;
    float q = dx * dx + dy * dy + dz * dz + dw * dw;
    #pragma unroll
    for (int o = 16; o > 0; o >>= 1) q += __shfl_xor_sync(0xffffffffu, q, o);
    const float inv = rsqrtf(q * (1.0f / 128.0f) + 1e-5f);

    const float4 g = reinterpret_cast<const float4*>(gamma)[lane];
    const float4 b = reinterpret_cast<const float4*>(beta)[lane];
    float4 o4;
    o4.x = dx * inv * g.x + b.x;
    o4.y = dy * inv * g.y + b.y;
    o4.z = dz * inv * g.z + b.z;
    o4.w = dw * inv * g.w + b.w;
    reinterpret_cast<float4*>(out)[(size_t)row * 32 + lane] = o4;
}

// ---------------------------------------------------------------
extern "C" void kernel_launch(void* const* d_in, const int* in_sizes, int n_in,
                              void* d_out, int out_size) {
    const float* h     = (const float*)d_in[0];
    const int*   src   = (const int*)  d_in[1];
    const int*   dst   = (const int*)  d_in[2];
    const float* ea    = (const float*)d_in[3];
    const float* W1    = (const float*)d_in[4];
    const float* b1    = (const float*)d_in[5];
    const float* W2    = (const float*)d_in[6];
    const float* b2    = (const float*)d_in[7];
    const float* gamma = (const float*)d_in[8];
    const float* beta  = (const float*)d_in[9];
    float*       out   = (float*)d_out;

    static int sm_count = []() {
        int dev = 0, c = 148;
        cudaGetDevice(&dev);
        cudaDeviceGetAttribute(&c, cudaDevAttrMultiProcessorCount, dev);
        return c;
    }();
    static bool attr_ok = []() {
        cudaFuncSetAttribute(edge_mlp_kernel,
                             cudaFuncAttributeMaxDynamicSharedMemorySize,
                             SMEM_BYTES);
        return true;
    }();
    (void)attr_ok;

    zero_agg_kernel<<<2048, 256>>>();
    edge_mlp_kernel<<<sm_count, 256, SMEM_BYTES>>>(h, src, dst, ea,
                                                   W1, b1, W2, b2);
    ln_kernel<<<(N_NODES * 32 + 255) / 256, 256>>>(h, gamma, beta, out);
}

// round 3
// speedup vs baseline: 4.0191x; 4.0191x over previous
#include <cuda_runtime.h>
#include <cuda_fp16.h>
#include <math.h>
#include <stdint.h>

#define N_NODES 50000
#define N_EDGES 1600000
#define NT      12500       // tiles of 128 edges

// ---- SMEM pitches (bytes). All multiples of 16 (ldmatrix) and chosen so
// ---- 8-row LDSM phases cover all 32 banks: (P/4 mod 32)*q distinct.
#define PB1  560    // W1s [n=128][k=272 pad] fp16   (140 mod 32 = 12)
#define PB2  272    // X0/X1/hdn/W2s [128][k=128 pad] (68 mod 32 = 4)
#define PBEA 48     // EA [128][k=16 pad]             (12)

// ---- SMEM offsets (bytes)
#define SM_W1   0           // 71680
#define SM_W2   71680       // 34816
#define SM_X0   106496      // 34816
#define SM_X1   141312      // 34816
#define SM_HDN  176128      // 34816
#define SM_EA   210944      // 6144
#define SM_B1   217088      // 512
#define SM_B2   217600      // 512
#define SM_SIDX 218112      // 512
#define SM_DIDX 218624      // 512
#define SMEM_BYTES 219136

__device__ float g_agg[(size_t)N_NODES * 128];

// ---------------------------------------------------------------- helpers
__device__ __forceinline__ uint32_t smem_u32(const void* p) {
    uint32_t a;
    asm("{ .reg .u64 t; cvta.to.shared.u64 t, %1; cvt.u32.u64 %0, t; }"
        : "=r"(a) : "l"(p));
    return a;
}
__device__ __forceinline__ void ldsm4(uint32_t* r, uint32_t addr) {
    asm volatile("ldmatrix.sync.aligned.m8n8.x4.shared.b16 {%0,%1,%2,%3}, [%4];"
                 : "=r"(r[0]), "=r"(r[1]), "=r"(r[2]), "=r"(r[3]) : "r"(addr));
}
__device__ __forceinline__ void mma16816(float* c, const uint32_t* a,
                                         const uint32_t* b) {
    asm volatile("mma.sync.aligned.m16n8k16.row.col.f32.f16.f16.f32 "
                 "{%0,%1,%2,%3}, {%4,%5,%6,%7}, {%8,%9}, {%0,%1,%2,%3};"
                 : "+f"(c[0]), "+f"(c[1]), "+f"(c[2]), "+f"(c[3])
                 : "r"(a[0]), "r"(a[1]), "r"(a[2]), "r"(a[3]),
                   "r"(b[0]), "r"(b[1]));
}
__device__ __forceinline__ uint32_t h2bits(float a, float b) {
    __half2 h = __floats2half2_rn(a, b);
    return *reinterpret_cast<uint32_t*>(&h);
}
__device__ __forceinline__ float gelu_exact(float v) {
    return 0.5f * v * (1.0f + erff(v * 0.70710678118654752440f));
}

// one GEMM pass: NCH k16-chunks, A base/B base advance 32B per chunk
template <int NCH>
__device__ __forceinline__ void gemm_pass(float (&c)[2][8][4],
                                          uint32_t abase, uint32_t amstep,
                                          uint32_t bbase, uint32_t bnstep) {
    #pragma unroll
    for (int kc = 0; kc < NCH; ++kc) {
        uint32_t a[2][4], b[4][4];
        ldsm4(a[0], abase);
        ldsm4(a[1], abase + amstep);
        ldsm4(b[0], bbase);
        ldsm4(b[1], bbase + bnstep);
        ldsm4(b[2], bbase + 2 * bnstep);
        ldsm4(b[3], bbase + 3 * bnstep);
        #pragma unroll
        for (int mt = 0; mt < 2; ++mt)
            #pragma unroll
            for (int j = 0; j < 8; ++j)
                mma16816(c[mt][j], a[mt], &b[j >> 1][(j & 1) * 2]);
        abase += 32;
        bbase += 32;
    }
}

// ---------------------------------------------------------------- aux
__global__ void zero_agg_kernel() {
    float4* p = reinterpret_cast<float4*>(g_agg);
    const int n = N_NODES * 128 / 4;
    for (int i = blockIdx.x * blockDim.x + threadIdx.x; i < n;
         i += gridDim.x * blockDim.x)
        p[i] = make_float4(0.f, 0.f, 0.f, 0.f);
}

// ---------------------------------------------------------------- main
__global__ __launch_bounds__(256, 1)
void edge_mma_kernel(const float* __restrict__ h,
                     const int*   __restrict__ src,
                     const int*   __restrict__ dst,
                     const float* __restrict__ ea,
                     const float* __restrict__ W1,
                     const float* __restrict__ b1,
                     const float* __restrict__ W2,
                     const float* __restrict__ b2) {
    extern __shared__ char smbuf[];
    const uint32_t sb = smem_u32(smbuf);
    float* b1s = reinterpret_cast<float*>(smbuf + SM_B1);
    float* b2s = reinterpret_cast<float*>(smbuf + SM_B2);
    int* sidx  = reinterpret_cast<int*>(smbuf + SM_SIDX);
    int* didx  = reinterpret_cast<int*>(smbuf + SM_DIDX);

    const int t = threadIdx.x, l = t & 31, warp = t >> 5;
    const int wm = warp & 3;          // m-row of warp grid (4)
    const int wn = warp >> 2;         // n-col of warp grid (2)

    // ---- stage W1^T, W2^T (fp16) + biases ----
    for (int i = t; i < 272 * 128; i += 256) {
        int k = i >> 7, n = i & 127;
        *reinterpret_cast<__half*>(smbuf + SM_W1 + n * PB1 + k * 2) =
            __float2half_rn(W1[i]);
    }
    for (int i = t; i < 128 * 128; i += 256) {
        int k = i >> 7, n = i & 127;
        *reinterpret_cast<__half*>(smbuf + SM_W2 + n * PB2 + k * 2) =
            __float2half_rn(W2[i]);
    }
    if (t < 128) { b1s[t] = b1[t]; b2s[t] = b2[t]; }

    // ldmatrix lane offsets
    const uint32_t aoff272 = ((l & 7) + 8 * ((l >> 3) & 1)) * PB2 + (l >> 4) * 16;
    const uint32_t aoff48  = ((l & 7) + 8 * ((l >> 3) & 1)) * PBEA + (l >> 4) * 16;
    const uint32_t boff560 = ((l & 7) + 8 * (l >> 4)) * PB1 + ((l >> 3) & 1) * 16;
    const uint32_t boff272 = ((l & 7) + 8 * (l >> 4)) * PB2 + ((l >> 3) & 1) * 16;

    const uint32_t aX0  = sb + SM_X0  + 32 * wm * PB2 + aoff272;
    const uint32_t aX1  = sb + SM_X1  + 32 * wm * PB2 + aoff272;
    const uint32_t aEA  = sb + SM_EA  + 32 * wm * PBEA + aoff48;
    const uint32_t aHDN = sb + SM_HDN + 32 * wm * PB2 + aoff272;
    const uint32_t bW1  = sb + SM_W1  + 64 * wn * PB1 + boff560;
    const uint32_t bW2  = sb + SM_W2  + 64 * wn * PB2 + boff272;

    const int rbase = 32 * wm + (l >> 2);
    const int cbase = 64 * wn + 2 * (l & 3);

    __syncthreads();

    for (int tile = blockIdx.x; tile < NT; tile += gridDim.x) {
        const int e0 = tile << 7;
        __syncthreads();                       // prev tile fully consumed
        if (t < 128) sidx[t] = src[e0 + t];
        else         didx[t - 128] = dst[e0 + t - 128];
        __syncthreads();

        // ---- gather: X0 = h[src], X1 = h[dst], EA = edge_attr (fp16) ----
        {
            const int row = t >> 1, hf = t & 1;
            const float4* ps = reinterpret_cast<const float4*>(
                h + (size_t)sidx[row] * 128 + 64 * hf);
            const float4* pd = reinterpret_cast<const float4*>(
                h + (size_t)didx[row] * 128 + 64 * hf);
            char* x0 = smbuf + SM_X0 + row * PB2 + hf * 128;
            char* x1 = smbuf + SM_X1 + row * PB2 + hf * 128;
            #pragma unroll
            for (int q = 0; q < 16; ++q) {
                float4 v = ps[q];
                *reinterpret_cast<uint2*>(x0 + q * 8) =
                    make_uint2(h2bits(v.x, v.y), h2bits(v.z, v.w));
            }
            #pragma unroll
            for (int q = 0; q < 16; ++q) {
                float4 v = pd[q];
                *reinterpret_cast<uint2*>(x1 + q * 8) =
                    make_uint2(h2bits(v.x, v.y), h2bits(v.z, v.w));
            }
            if (t < 128) {
                const float4* pe = reinterpret_cast<const float4*>(
                    ea + (size_t)(e0 + t) * 16);
                char* eb = smbuf + SM_EA + t * PBEA;
                #pragma unroll
                for (int q = 0; q < 4; ++q) {
                    float4 v = pe[q];
                    *reinterpret_cast<uint2*>(eb + q * 8) =
                        make_uint2(h2bits(v.x, v.y), h2bits(v.z, v.w));
                }
            }
        }
        __syncthreads();

        // ---- GEMM1: C = [X0 | X1 | EA] @ W1^T ----
        float c[2][8][4];
        #pragma unroll
        for (int mt = 0; mt < 2; ++mt)
            #pragma unroll
            for (int j = 0; j < 8; ++j)
                #pragma unroll
                for (int i = 0; i < 4; ++i) c[mt][j][i] = 0.f;

        gemm_pass<8>(c, aX0, 16 * PB2, bW1,       16 * PB1);
        gemm_pass<8>(c, aX1, 16 * PB2, bW1 + 256, 16 * PB1);
        gemm_pass<1>(c, aEA, 16 * PBEA, bW1 + 512, 16 * PB1);

        // ---- epilogue 1: +b1, exact GELU, fp16 -> hdn ----
        #pragma unroll
        for (int mt = 0; mt < 2; ++mt)
            #pragma unroll
            for (int j = 0; j < 8; ++j) {
                const int col = cbase + 8 * j;
                const float bb0 = b1s[col], bb1 = b1s[col + 1];
                #pragma unroll
                for (int rh = 0; rh < 2; ++rh) {
                    float v0 = gelu_exact(c[mt][j][2 * rh] + bb0);
                    float v1 = gelu_exact(c[mt][j][2 * rh + 1] + bb1);
                    const int row = rbase + 16 * mt + 8 * rh;
                    *reinterpret_cast<uint32_t*>(
                        smbuf + SM_HDN + row * PB2 + col * 2) = h2bits(v0, v1);
                }
            }
        __syncthreads();

        // ---- GEMM2: D = hdn @ W2^T ----
        #pragma unroll
        for (int mt = 0; mt < 2; ++mt)
            #pragma unroll
            for (int j = 0; j < 8; ++j)
                #pragma unroll
                for (int i = 0; i < 4; ++i) c[mt][j][i] = 0.f;
        gemm_pass<8>(c, aHDN, 16 * PB2, bW2, 16 * PB2);

        // ---- epilogue 2: +b2, scatter-add to g_agg ----
        #pragma unroll
        for (int mt = 0; mt < 2; ++mt) {
            #pragma unroll
            for (int rh = 0; rh < 2; ++rh) {
                const int row = rbase + 16 * mt + 8 * rh;
                const int node = didx[row];
                float* gb = g_agg + (size_t)node * 128;
                #pragma unroll
                for (int j = 0; j < 8; ++j) {
                    const int col = cbase + 8 * j;
                    float v0 = c[mt][j][2 * rh] + b2s[col];
                    float v1 = c[mt][j][2 * rh + 1] + b2s[col + 1];
                    asm volatile("red.global.add.v2.f32 [%0], {%1,%2};"
                                 :: "l"(gb + col), "f"(v0), "f"(v1) : "memory");
                }
            }
        }
    }
}

// ---------------------------------------------------------------- LayerNorm
__global__ __launch_bounds__(256)
void ln_kernel(const float* __restrict__ h,
               const float* __restrict__ gamma,
               const float* __restrict__ beta,
               float* __restrict__ out) {
    const int row  = (blockIdx.x * blockDim.x + threadIdx.x) >> 5;
    const int lane = threadIdx.x & 31;
    if (row >= N_NODES) return;

    const float4 hv = reinterpret_cast<const float4*>(h)[(size_t)row * 32 + lane];
    const float4 av = reinterpret_cast<const float4*>(g_agg)[(size_t)row * 32 + lane];
    float4 x;
    x.x = hv.x + av.x; x.y = hv.y + av.y; x.z = hv.z + av.z; x.w = hv.w + av.w;

    float s = x.x + x.y + x.z + x.w;
    #pragma unroll
    for (int o = 16; o > 0; o >>= 1) s += __shfl_xor_sync(0xffffffffu, s, o);
    const float mu = s * (1.0f / 128.0f);

    const float dx = x.x - mu, dy = x.y - mu, dz = x.z - mu, dw = x.w - mu;
    float q = dx * dx + dy * dy + dz * dz + dw * dw;
    #pragma unroll
    for (int o = 16; o > 0; o >>= 1) q += __shfl_xor_sync(0xffffffffu, q, o);
    const float inv = rsqrtf(q * (1.0f / 128.0f) + 1e-5f);

    const float4 g = reinterpret_cast<const float4*>(gamma)[lane];
    const float4 b = reinterpret_cast<const float4*>(beta)[lane];
    float4 o4;
    o4.x = dx * inv * g.x + b.x;
    o4.y = dy * inv * g.y + b.y;
    o4.z = dz * inv * g.z + b.z;
    o4.w = dw * inv * g.w + b.w;
    reinterpret_cast<float4*>(out)[(size_t)row * 32 + lane] = o4;
}

// ----------------------------------------------------------------
extern "C" void kernel_launch(void* const* d_in, const int* in_sizes, int n_in,
                              void* d_out, int out_size) {
    const float* h     = (const float*)d_in[0];
    const int*   src   = (const int*)  d_in[1];
    const int*   dst   = (const int*)  d_in[2];
    const float* ea    = (const float*)d_in[3];
    const float* W1    = (const float*)d_in[4];
    const float* b1    = (const float*)d_in[5];
    const float* W2    = (const float*)d_in[6];
    const float* b2    = (const float*)d_in[7];
    const float* gamma = (const float*)d_in[8];
    const float* beta  = (const float*)d_in[9];
    float*       out   = (float*)d_out;

    static int sm_count = []() {
        int dev = 0, c = 148;
        cudaGetDevice(&dev);
        cudaDeviceGetAttribute(&c, cudaDevAttrMultiProcessorCount, dev);
        return c;
    }();
    static bool attr_ok = []() {
        cudaFuncSetAttribute(edge_mma_kernel,
                             cudaFuncAttributeMaxDynamicSharedMemorySize,
                             SMEM_BYTES);
        return true;
    }();
    (void)attr_ok;

    zero_agg_kernel<<<2048, 256>>>();
    edge_mma_kernel<<<sm_count, 256, SMEM_BYTES>>>(h, src, dst, ea,
                                                   W1, b1, W2, b2);
    ln_kernel<<<(N_NODES * 32 + 255) / 256, 256>>>(h, gamma, beta, out);
}

// round 4
// speedup vs baseline: 4.7024x; 1.1700x over previous
#include <cuda_runtime.h>
#include <cuda_fp16.h>
#include <math.h>
#include <stdint.h>

#define N_NODES 50000
#define N_EDGES 1600000
#define NT      12500       // tiles of 128 edges

// ---- SMEM pitches (bytes)
#define PB1  560    // W1s [n=128][k=272 pad] fp16
#define PB2  272    // X0/X1/hdn/W2s [128][k=128 pad] fp16
#define PBEA 48     // EA [128][k=16 pad] fp16
#define PD   544    // D staging [128][128 pad to 136 words] f32

// ---- SMEM offsets (bytes)
#define SM_W1   0           // 71680
#define SM_W2   71680       // 34816
#define SM_X0   106496      // 34816  } also D staging region (69632B)
#define SM_X1   141312      // 34816  }
#define SM_D    SM_X0
#define SM_HDN  176128      // 34816
#define SM_EA   210944      // 6144
#define SM_B1   217088      // 512
#define SM_B2   217600      // 512
#define SM_SIDX 218112      // 512
#define SM_DIDX 218624      // 512
#define SMEM_BYTES 219136

__device__ float   g_agg[(size_t)N_NODES * 128];
__device__ __half  g_h16[(size_t)N_NODES * 128];

// ---------------------------------------------------------------- helpers
__device__ __forceinline__ uint32_t smem_u32(const void* p) {
    uint32_t a;
    asm("{ .reg .u64 t; cvta.to.shared.u64 t, %1; cvt.u32.u64 %0, t; }"
        : "=r"(a) : "l"(p));
    return a;
}
__device__ __forceinline__ void ldsm4(uint32_t* r, uint32_t addr) {
    asm volatile("ldmatrix.sync.aligned.m8n8.x4.shared.b16 {%0,%1,%2,%3}, [%4];"
                 : "=r"(r[0]), "=r"(r[1]), "=r"(r[2]), "=r"(r[3]) : "r"(addr));
}
__device__ __forceinline__ void mma16816(float* c, const uint32_t* a,
                                         const uint32_t* b) {
    asm volatile("mma.sync.aligned.m16n8k16.row.col.f32.f16.f16.f32 "
                 "{%0,%1,%2,%3}, {%4,%5,%6,%7}, {%8,%9}, {%0,%1,%2,%3};"
                 : "+f"(c[0]), "+f"(c[1]), "+f"(c[2]), "+f"(c[3])
                 : "r"(a[0]), "r"(a[1]), "r"(a[2]), "r"(a[3]),
                   "r"(b[0]), "r"(b[1]));
}
__device__ __forceinline__ uint32_t h2bits(float a, float b) {
    __half2 h = __floats2half2_rn(a, b);
    return *reinterpret_cast<uint32_t*>(&h);
}
__device__ __forceinline__ float gelu_exact(float v) {
    return 0.5f * v * (1.0f + erff(v * 0.70710678118654752440f));
}

template <int NCH>
__device__ __forceinline__ void gemm_pass(float (&c)[2][8][4],
                                          uint32_t abase, uint32_t amstep,
                                          uint32_t bbase, uint32_t bnstep) {
    #pragma unroll
    for (int kc = 0; kc < NCH; ++kc) {
        uint32_t a[2][4], b[4][4];
        ldsm4(a[0], abase);
        ldsm4(a[1], abase + amstep);
        ldsm4(b[0], bbase);
        ldsm4(b[1], bbase + bnstep);
        ldsm4(b[2], bbase + 2 * bnstep);
        ldsm4(b[3], bbase + 3 * bnstep);
        #pragma unroll
        for (int mt = 0; mt < 2; ++mt)
            #pragma unroll
            for (int j = 0; j < 8; ++j)
                mma16816(c[mt][j], a[mt], &b[j >> 1][(j & 1) * 2]);
        abase += 32;
        bbase += 32;
    }
}

// ---------------------------------------------------------------- prep:
// zero g_agg AND convert h -> fp16 in one pass
__global__ void prep_kernel(const float* __restrict__ h) {
    const int n4 = N_NODES * 128 / 4;                 // float4 count
    for (int i = blockIdx.x * blockDim.x + threadIdx.x; i < n4;
         i += gridDim.x * blockDim.x) {
        reinterpret_cast<float4*>(g_agg)[i] = make_float4(0.f, 0.f, 0.f, 0.f);
        float4 v = reinterpret_cast<const float4*>(h)[i];
        reinterpret_cast<uint2*>(g_h16)[i] =
            make_uint2(h2bits(v.x, v.y), h2bits(v.z, v.w));
    }
}

// ---------------------------------------------------------------- main
__global__ __launch_bounds__(256, 1)
void edge_mma_kernel(const int*   __restrict__ src,
                     const int*   __restrict__ dst,
                     const float* __restrict__ ea,
                     const float* __restrict__ W1,
                     const float* __restrict__ b1,
                     const float* __restrict__ W2,
                     const float* __restrict__ b2) {
    extern __shared__ char smbuf[];
    const uint32_t sb = smem_u32(smbuf);
    float* b1s = reinterpret_cast<float*>(smbuf + SM_B1);
    float* b2s = reinterpret_cast<float*>(smbuf + SM_B2);
    int* sidx  = reinterpret_cast<int*>(smbuf + SM_SIDX);
    int* didx  = reinterpret_cast<int*>(smbuf + SM_DIDX);

    const int t = threadIdx.x, l = t & 31, warp = t >> 5;
    const int wm = warp & 3;
    const int wn = warp >> 2;

    // ---- stage W1^T, W2^T (fp16) + biases ----
    for (int i = t; i < 272 * 128; i += 256) {
        int k = i >> 7, n = i & 127;
        *reinterpret_cast<__half*>(smbuf + SM_W1 + n * PB1 + k * 2) =
            __float2half_rn(W1[i]);
    }
    for (int i = t; i < 128 * 128; i += 256) {
        int k = i >> 7, n = i & 127;
        *reinterpret_cast<__half*>(smbuf + SM_W2 + n * PB2 + k * 2) =
            __float2half_rn(W2[i]);
    }
    if (t < 128) { b1s[t] = b1[t]; b2s[t] = b2[t]; }

    // ldmatrix lane offsets
    const uint32_t aoff272 = ((l & 7) + 8 * ((l >> 3) & 1)) * PB2 + (l >> 4) * 16;
    const uint32_t aoff48  = ((l & 7) + 8 * ((l >> 3) & 1)) * PBEA + (l >> 4) * 16;
    const uint32_t boff560 = ((l & 7) + 8 * (l >> 4)) * PB1 + ((l >> 3) & 1) * 16;
    const uint32_t boff272 = ((l & 7) + 8 * (l >> 4)) * PB2 + ((l >> 3) & 1) * 16;

    const uint32_t aX0  = sb + SM_X0  + 32 * wm * PB2 + aoff272;
    const uint32_t aX1  = sb + SM_X1  + 32 * wm * PB2 + aoff272;
    const uint32_t aEA  = sb + SM_EA  + 32 * wm * PBEA + aoff48;
    const uint32_t aHDN = sb + SM_HDN + 32 * wm * PB2 + aoff272;
    const uint32_t bW1  = sb + SM_W1  + 64 * wn * PB1 + boff560;
    const uint32_t bW2  = sb + SM_W2  + 64 * wn * PB2 + boff272;

    const int rbase = 32 * wm + (l >> 2);
    const int cbase = 64 * wn + 2 * (l & 3);

    const int grow = t & 127;        // gather/scatter row
    const int ghf  = t >> 7;         // half (0/1)

    __syncthreads();

    for (int tile = blockIdx.x; tile < NT; tile += gridDim.x) {
        const int e0 = tile << 7;
        __syncthreads();                       // prev tile fully consumed
        if (t < 128) sidx[t] = src[e0 + t];
        else         didx[t - 128] = dst[e0 + t - 128];
        __syncthreads();

        // ---- gather: X0 = h16[src], X1 = h16[dst], EA = edge_attr ----
        {
            const uint4* ps = reinterpret_cast<const uint4*>(
                g_h16 + (size_t)sidx[grow] * 128 + ghf * 64);
            const uint4* pd = reinterpret_cast<const uint4*>(
                g_h16 + (size_t)didx[grow] * 128 + ghf * 64);
            char* x0 = smbuf + SM_X0 + grow * PB2 + ghf * 128;
            char* x1 = smbuf + SM_X1 + grow * PB2 + ghf * 128;
            #pragma unroll
            for (int q = 0; q < 8; ++q)
                *reinterpret_cast<uint4*>(x0 + q * 16) = ps[q];
            #pragma unroll
            for (int q = 0; q < 8; ++q)
                *reinterpret_cast<uint4*>(x1 + q * 16) = pd[q];
            if (t < 128) {
                const float4* pe = reinterpret_cast<const float4*>(
                    ea + (size_t)(e0 + t) * 16);
                char* eb = smbuf + SM_EA + t * PBEA;
                #pragma unroll
                for (int q = 0; q < 4; ++q) {
                    float4 v = pe[q];
                    *reinterpret_cast<uint2*>(eb + q * 8) =
                        make_uint2(h2bits(v.x, v.y), h2bits(v.z, v.w));
                }
            }
        }
        __syncthreads();

        // ---- GEMM1: C = [X0 | X1 | EA] @ W1^T ----
        float c[2][8][4];
        #pragma unroll
        for (int mt = 0; mt < 2; ++mt)
            #pragma unroll
            for (int j = 0; j < 8; ++j)
                #pragma unroll
                for (int i = 0; i < 4; ++i) c[mt][j][i] = 0.f;

        gemm_pass<8>(c, aX0, 16 * PB2, bW1,       16 * PB1);
        gemm_pass<8>(c, aX1, 16 * PB2, bW1 + 256, 16 * PB1);
        gemm_pass<1>(c, aEA, 16 * PBEA, bW1 + 512, 16 * PB1);

        // ---- epilogue 1: +b1, exact GELU, fp16 -> hdn ----
        #pragma unroll
        for (int mt = 0; mt < 2; ++mt)
            #pragma unroll
            for (int j = 0; j < 8; ++j) {
                const int col = cbase + 8 * j;
                const float bb0 = b1s[col], bb1 = b1s[col + 1];
                #pragma unroll
                for (int rh = 0; rh < 2; ++rh) {
                    float v0 = gelu_exact(c[mt][j][2 * rh] + bb0);
                    float v1 = gelu_exact(c[mt][j][2 * rh + 1] + bb1);
                    const int row = rbase + 16 * mt + 8 * rh;
                    *reinterpret_cast<uint32_t*>(
                        smbuf + SM_HDN + row * PB2 + col * 2) = h2bits(v0, v1);
                }
            }
        __syncthreads();   // hdn ready; X0/X1 free (becomes D staging)

        // ---- GEMM2: D = hdn @ W2^T ----
        #pragma unroll
        for (int mt = 0; mt < 2; ++mt)
            #pragma unroll
            for (int j = 0; j < 8; ++j)
                #pragma unroll
                for (int i = 0; i < 4; ++i) c[mt][j][i] = 0.f;
        gemm_pass<8>(c, aHDN, 16 * PB2, bW2, 16 * PB2);

        // ---- epilogue 2a: +b2, stage D (f32) in SMEM ----
        #pragma unroll
        for (int mt = 0; mt < 2; ++mt)
            #pragma unroll
            for (int j = 0; j < 8; ++j) {
                const int col = cbase + 8 * j;
                const float bb0 = b2s[col], bb1 = b2s[col + 1];
                #pragma unroll
                for (int rh = 0; rh < 2; ++rh) {
                    const int row = rbase + 16 * mt + 8 * rh;
                    float2 v = make_float2(c[mt][j][2 * rh] + bb0,
                                           c[mt][j][2 * rh + 1] + bb1);
                    *reinterpret_cast<float2*>(
                        smbuf + SM_D + row * PD + col * 4) = v;
                }
            }
        __syncthreads();

        // ---- epilogue 2b: scatter with red.global.add.v4 ----
        {
            float* gb = g_agg + (size_t)didx[grow] * 128 + ghf * 64;
            const float4* ds = reinterpret_cast<const float4*>(
                smbuf + SM_D + grow * PD + ghf * 256);
            #pragma unroll
            for (int q = 0; q < 16; ++q) {
                float4 v = ds[q];
                asm volatile("red.global.add.v4.f32 [%0], {%1,%2,%3,%4};"
                             :: "l"(gb + 4 * q),
                                "f"(v.x), "f"(v.y), "f"(v.z), "f"(v.w)
                             : "memory");
            }
        }
    }
}

// ---------------------------------------------------------------- LayerNorm
__global__ __launch_bounds__(256)
void ln_kernel(const float* __restrict__ h,
               const float* __restrict__ gamma,
               const float* __restrict__ beta,
               float* __restrict__ out) {
    const int row  = (blockIdx.x * blockDim.x + threadIdx.x) >> 5;
    const int lane = threadIdx.x & 31;
    if (row >= N_NODES) return;

    const float4 hv = reinterpret_cast<const float4*>(h)[(size_t)row * 32 + lane];
    const float4 av = reinterpret_cast<const float4*>(g_agg)[(size_t)row * 32 + lane];
    float4 x;
    x.x = hv.x + av.x; x.y = hv.y + av.y; x.z = hv.z + av.z; x.w = hv.w + av.w;

    float s = x.x + x.y + x.z + x.w;
    #pragma unroll
    for (int o = 16; o > 0; o >>= 1) s += __shfl_xor_sync(0xffffffffu, s, o);
    const float mu = s * (1.0f / 128.0f);

    const float dx = x.x - mu, dy = x.y - mu, dz = x.z - mu, dw = x.w - mu;
    float q = dx * dx + dy * dy + dz * dz + dw * dw;
    #pragma unroll
    for (int o = 16; o > 0; o >>= 1) q += __shfl_xor_sync(0xffffffffu, q, o);
    const float inv = rsqrtf(q * (1.0f / 128.0f) + 1e-5f);

    const float4 g = reinterpret_cast<const float4*>(gamma)[lane];
    const float4 b = reinterpret_cast<const float4*>(beta)[lane];
    float4 o4;
    o4.x = dx * inv * g.x + b.x;
    o4.y = dy * inv * g.y + b.y;
    o4.z = dz * inv * g.z + b.z;
    o4.w = dw * inv * g.w + b.w;
    reinterpret_cast<float4*>(out)[(size_t)row * 32 + lane] = o4;
}

// ----------------------------------------------------------------
extern "C" void kernel_launch(void* const* d_in, const int* in_sizes, int n_in,
                              void* d_out, int out_size) {
    const float* h     = (const float*)d_in[0];
    const int*   src   = (const int*)  d_in[1];
    const int*   dst   = (const int*)  d_in[2];
    const float* ea    = (const float*)d_in[3];
    const float* W1    = (const float*)d_in[4];
    const float* b1    = (const float*)d_in[5];
    const float* W2    = (const float*)d_in[6];
    const float* b2    = (const float*)d_in[7];
    const float* gamma = (const float*)d_in[8];
    const float* beta  = (const float*)d_in[9];
    float*       out   = (float*)d_out;

    static int sm_count = []() {
        int dev = 0, c = 148;
        cudaGetDevice(&dev);
        cudaDeviceGetAttribute(&c, cudaDevAttrMultiProcessorCount, dev);
        return c;
    }();
    static bool attr_ok = []() {
        cudaFuncSetAttribute(edge_mma_kernel,
                             cudaFuncAttributeMaxDynamicSharedMemorySize,
                             SMEM_BYTES);
        return true;
    }();
    (void)attr_ok;

    prep_kernel<<<2048, 256>>>(h);
    edge_mma_kernel<<<sm_count, 256, SMEM_BYTES>>>(src, dst, ea,
                                                   W1, b1, W2, b2);
    ln_kernel<<<(N_NODES * 32 + 255) / 256, 256>>>(h, gamma, beta, out);
}

// round 5
// speedup vs baseline: 7.2501x; 1.5418x over previous
#include <cuda_runtime.h>
#include <cuda_fp16.h>
#include <math.h>
#include <stdint.h>

#define N_NODES 50000
#define N_EDGES 1600000
#define NT      12500       // edge tiles of 128
#define NNT     391         // node tiles of 128 (ceil 50000/128)

// ---- pitches (bytes)
#define PB2  272    // fp16 [128][k=128 pad]
#define PBEA 48     // fp16 [128][k=16 pad]
#define PD   528    // f32 staging [128][132 words]

// ---- edge-kernel SMEM offsets
#define SM_W2   0           // 34816
#define SM_HDN  34816       // 34816
#define SM_D    69632       // 67584 (E1 then D staging)
#define SM_EA   137216      // 6144
#define SM_W1C  143360      // 6144
#define SM_B2   149504      // 512
#define SM_SIDX 150016      // 512
#define SM_DIDX 150528      // 512
#define SMEM_E  151040

// ---- node-kernel SMEM offsets
#define NSM_X   0           // 34816
#define NSM_B0  34816       // 34816
#define NSM_B1  69632       // 34816
#define NSM_OUT 104448      // 34816
#define NSM_B1S 139264      // 512
#define SMEM_N  139776

__device__ float   g_agg[(size_t)N_NODES * 128];
__device__ __half  g_h16[(size_t)N_NODES * 128];
__device__ __half  g_pq [(size_t)N_NODES * 256];   // [node][0:128]=P=h@W1a+b1, [128:256]=Q=h@W1b

// ---------------------------------------------------------------- helpers
__device__ __forceinline__ uint32_t smem_u32(const void* p) {
    uint32_t a;
    asm("{ .reg .u64 t; cvta.to.shared.u64 t, %1; cvt.u32.u64 %0, t; }"
        : "=r"(a) : "l"(p));
    return a;
}
__device__ __forceinline__ void ldsm4(uint32_t* r, uint32_t addr) {
    asm volatile("ldmatrix.sync.aligned.m8n8.x4.shared.b16 {%0,%1,%2,%3}, [%4];"
                 : "=r"(r[0]), "=r"(r[1]), "=r"(r[2]), "=r"(r[3]) : "r"(addr));
}
__device__ __forceinline__ void mma16816(float* c, const uint32_t* a,
                                         const uint32_t* b) {
    asm volatile("mma.sync.aligned.m16n8k16.row.col.f32.f16.f16.f32 "
                 "{%0,%1,%2,%3}, {%4,%5,%6,%7}, {%8,%9}, {%0,%1,%2,%3};"
                 : "+f"(c[0]), "+f"(c[1]), "+f"(c[2]), "+f"(c[3])
                 : "r"(a[0]), "r"(a[1]), "r"(a[2]), "r"(a[3]),
                   "r"(b[0]), "r"(b[1]));
}
__device__ __forceinline__ uint32_t h2bits(float a, float b) {
    __half2 h = __floats2half2_rn(a, b);
    return *reinterpret_cast<uint32_t*>(&h);
}
__device__ __forceinline__ float gelu_exact(float v) {
    return 0.5f * v * (1.0f + erff(v * 0.70710678118654752440f));
}

template <int NCH>
__device__ __forceinline__ void gemm_pass(float (&c)[2][8][4],
                                          uint32_t abase, uint32_t amstep,
                                          uint32_t bbase, uint32_t bnstep) {
    #pragma unroll
    for (int kc = 0; kc < NCH; ++kc) {
        uint32_t a[2][4], b[4][4];
        ldsm4(a[0], abase);
        ldsm4(a[1], abase + amstep);
        ldsm4(b[0], bbase);
        ldsm4(b[1], bbase + bnstep);
        ldsm4(b[2], bbase + 2 * bnstep);
        ldsm4(b[3], bbase + 3 * bnstep);
        #pragma unroll
        for (int mt = 0; mt < 2; ++mt)
            #pragma unroll
            for (int j = 0; j < 8; ++j)
                mma16816(c[mt][j], a[mt], &b[j >> 1][(j & 1) * 2]);
        abase += 32;
        bbase += 32;
    }
}
__device__ __forceinline__ void zero_c(float (&c)[2][8][4]) {
    #pragma unroll
    for (int mt = 0; mt < 2; ++mt)
        #pragma unroll
        for (int j = 0; j < 8; ++j)
            #pragma unroll
            for (int i = 0; i < 4; ++i) c[mt][j][i] = 0.f;
}

// ---------------------------------------------------------------- prep
__global__ void prep_kernel(const float* __restrict__ h) {
    const int n4 = N_NODES * 128 / 4;
    for (int i = blockIdx.x * blockDim.x + threadIdx.x; i < n4;
         i += gridDim.x * blockDim.x) {
        reinterpret_cast<float4*>(g_agg)[i] = make_float4(0.f, 0.f, 0.f, 0.f);
        float4 v = reinterpret_cast<const float4*>(h)[i];
        reinterpret_cast<uint2*>(g_h16)[i] =
            make_uint2(h2bits(v.x, v.y), h2bits(v.z, v.w));
    }
}

// ---------------------------------------------------------------- node kernel:
// g_pq[n] = [ h@W1a + b1 | h@W1b ]   (fp16 in/out, f32 accum)
__global__ __launch_bounds__(256, 1)
void node_kernel(const float* __restrict__ W1, const float* __restrict__ b1) {
    extern __shared__ char smbuf[];
    const uint32_t sb = smem_u32(smbuf);
    float* b1s = reinterpret_cast<float*>(smbuf + NSM_B1S);

    const int t = threadIdx.x, l = t & 31, warp = t >> 5;
    const int wm = warp & 3, wn = warp >> 2;
    const int grow = t & 127, ghf = t >> 7;

    for (int i = t; i < 128 * 128; i += 256) {
        int k = i >> 7, n = i & 127;
        *reinterpret_cast<__half*>(smbuf + NSM_B0 + n * PB2 + k * 2) =
            __float2half_rn(W1[k * 128 + n]);
        *reinterpret_cast<__half*>(smbuf + NSM_B1 + n * PB2 + k * 2) =
            __float2half_rn(W1[(k + 128) * 128 + n]);
    }
    if (t < 128) b1s[t] = b1[t];

    const uint32_t aoff = ((l & 7) + 8 * ((l >> 3) & 1)) * PB2 + (l >> 4) * 16;
    const uint32_t boff = ((l & 7) + 8 * (l >> 4)) * PB2 + ((l >> 3) & 1) * 16;
    const uint32_t aX  = sb + NSM_X + 32 * wm * PB2 + aoff;
    const uint32_t bB0 = sb + NSM_B0 + 64 * wn * PB2 + boff;
    const uint32_t bB1 = sb + NSM_B1 + 64 * wn * PB2 + boff;
    const int rbase = 32 * wm + (l >> 2);
    const int cbase = 64 * wn + 2 * (l & 3);

    const int m0 = blockIdx.x * 128;
    const int node = m0 + grow;
    const int nc = node < N_NODES ? node : N_NODES - 1;

    // stage X = h16[node tile]
    {
        const uint4* ps = reinterpret_cast<const uint4*>(
            g_h16 + (size_t)nc * 128 + ghf * 64);
        char* xr = smbuf + NSM_X + grow * PB2 + ghf * 128;
        #pragma unroll
        for (int q = 0; q < 8; ++q)
            *reinterpret_cast<uint4*>(xr + q * 16) = ps[q];
    }
    __syncthreads();

    #pragma unroll
    for (int pass = 0; pass < 2; ++pass) {
        float c[2][8][4];
        zero_c(c);
        gemm_pass<8>(c, aX, 16 * PB2, pass ? bB1 : bB0, 16 * PB2);
        #pragma unroll
        for (int mt = 0; mt < 2; ++mt)
            #pragma unroll
            for (int j = 0; j < 8; ++j) {
                const int col = cbase + 8 * j;
                const float bb0 = pass ? 0.f : b1s[col];
                const float bb1 = pass ? 0.f : b1s[col + 1];
                #pragma unroll
                for (int rh = 0; rh < 2; ++rh) {
                    const int row = rbase + 16 * mt + 8 * rh;
                    *reinterpret_cast<uint32_t*>(
                        smbuf + NSM_OUT + row * PB2 + col * 2) =
                        h2bits(c[mt][j][2 * rh] + bb0, c[mt][j][2 * rh + 1] + bb1);
                }
            }
        __syncthreads();
        if (node < N_NODES) {
            const uint4* os = reinterpret_cast<const uint4*>(
                smbuf + NSM_OUT + grow * PB2 + ghf * 128);
            uint4* po = reinterpret_cast<uint4*>(
                g_pq + (size_t)node * 256 + pass * 128 + ghf * 64);
            #pragma unroll
            for (int q = 0; q < 8; ++q) po[q] = os[q];
        }
        __syncthreads();
    }
}

// ---------------------------------------------------------------- edge kernel
__global__ __launch_bounds__(256, 1)
void edge_mma_kernel(const int*   __restrict__ src,
                     const int*   __restrict__ dst,
                     const float* __restrict__ ea,
                     const float* __restrict__ W1,
                     const float* __restrict__ W2,
                     const float* __restrict__ b2) {
    extern __shared__ char smbuf[];
    const uint32_t sb = smem_u32(smbuf);
    float* b2s = reinterpret_cast<float*>(smbuf + SM_B2);
    int* sidx  = reinterpret_cast<int*>(smbuf + SM_SIDX);
    int* didx  = reinterpret_cast<int*>(smbuf + SM_DIDX);

    const int t = threadIdx.x, l = t & 31, warp = t >> 5;
    const int wm = warp & 3, wn = warp >> 2;
    const int grow = t & 127, ghf = t >> 7;

    // ---- stage W2^T and W1c^T (fp16) + b2 ----
    for (int i = t; i < 128 * 128; i += 256) {
        int k = i >> 7, n = i & 127;
        *reinterpret_cast<__half*>(smbuf + SM_W2 + n * PB2 + k * 2) =
            __float2half_rn(W2[i]);
    }
    for (int i = t; i < 16 * 128; i += 256) {
        int k = i >> 7, n = i & 127;
        *reinterpret_cast<__half*>(smbuf + SM_W1C + n * PBEA + k * 2) =
            __float2half_rn(W1[(k + 256) * 128 + n]);
    }
    if (t < 128) b2s[t] = b2[t];

    const uint32_t aoff272 = ((l & 7) + 8 * ((l >> 3) & 1)) * PB2 + (l >> 4) * 16;
    const uint32_t aoff48  = ((l & 7) + 8 * ((l >> 3) & 1)) * PBEA + (l >> 4) * 16;
    const uint32_t boff272 = ((l & 7) + 8 * (l >> 4)) * PB2 + ((l >> 3) & 1) * 16;
    const uint32_t boff48  = ((l & 7) + 8 * (l >> 4)) * PBEA + ((l >> 3) & 1) * 16;

    const uint32_t aEA  = sb + SM_EA  + 32 * wm * PBEA + aoff48;
    const uint32_t aHDN = sb + SM_HDN + 32 * wm * PB2 + aoff272;
    const uint32_t bW1C = sb + SM_W1C + 64 * wn * PBEA + boff48;
    const uint32_t bW2  = sb + SM_W2  + 64 * wn * PB2 + boff272;
    const int rbase = 32 * wm + (l >> 2);
    const int cbase = 64 * wn + 2 * (l & 3);

    __syncthreads();

    for (int tile = blockIdx.x; tile < NT; tile += gridDim.x) {
        const int e0 = tile << 7;
        __syncthreads();                       // prev tile fully consumed
        if (t < 128) sidx[t] = src[e0 + t];
        else         didx[t - 128] = dst[e0 + t - 128];
        __syncthreads();

        // ---- gather EA -> SMEM fp16 ----
        if (t < 128) {
            const float4* pe = reinterpret_cast<const float4*>(
                ea + (size_t)(e0 + t) * 16);
            char* eb = smbuf + SM_EA + t * PBEA;
            #pragma unroll
            for (int q = 0; q < 4; ++q) {
                float4 v = pe[q];
                *reinterpret_cast<uint2*>(eb + q * 8) =
                    make_uint2(h2bits(v.x, v.y), h2bits(v.z, v.w));
            }
        }
        __syncthreads();

        // ---- E1 = ea @ W1c^T  (K=16), stage f32 in SM_D ----
        float c[2][8][4];
        zero_c(c);
        gemm_pass<1>(c, aEA, 16 * PBEA, bW1C, 16 * PBEA);
        #pragma unroll
        for (int mt = 0; mt < 2; ++mt)
            #pragma unroll
            for (int j = 0; j < 8; ++j) {
                const int col = cbase + 8 * j;
                #pragma unroll
                for (int rh = 0; rh < 2; ++rh) {
                    const int row = rbase + 16 * mt + 8 * rh;
                    *reinterpret_cast<float2*>(
                        smbuf + SM_D + row * PD + col * 4) =
                        make_float2(c[mt][j][2 * rh], c[mt][j][2 * rh + 1]);
                }
            }
        __syncthreads();

        // ---- elementwise: hdn = gelu(P[src] + Q[dst] + E1) (fp16) ----
        {
            const uint4* pp = reinterpret_cast<const uint4*>(
                g_pq + (size_t)sidx[grow] * 256 + ghf * 64);
            const uint4* qq = reinterpret_cast<const uint4*>(
                g_pq + (size_t)didx[grow] * 256 + 128 + ghf * 64);
            const float4* e1 = reinterpret_cast<const float4*>(
                smbuf + SM_D + grow * PD + ghf * 256);
            char* hr = smbuf + SM_HDN + grow * PB2 + ghf * 128;
            #pragma unroll
            for (int q = 0; q < 8; ++q) {
                const uint4 pv = pp[q];
                const uint4 qv = qq[q];
                const float4 ev0 = e1[2 * q];
                const float4 ev1 = e1[2 * q + 1];
                const __half2* ph = reinterpret_cast<const __half2*>(&pv);
                const __half2* qh = reinterpret_cast<const __half2*>(&qv);
                float2 p0 = __half22float2(ph[0]), q0 = __half22float2(qh[0]);
                float2 p1 = __half22float2(ph[1]), q1 = __half22float2(qh[1]);
                float2 p2 = __half22float2(ph[2]), q2 = __half22float2(qh[2]);
                float2 p3 = __half22float2(ph[3]), q3 = __half22float2(qh[3]);
                uint4 o;
                o.x = h2bits(gelu_exact(p0.x + q0.x + ev0.x),
                             gelu_exact(p0.y + q0.y + ev0.y));
                o.y = h2bits(gelu_exact(p1.x + q1.x + ev0.z),
                             gelu_exact(p1.y + q1.y + ev0.w));
                o.z = h2bits(gelu_exact(p2.x + q2.x + ev1.x),
                             gelu_exact(p2.y + q2.y + ev1.y));
                o.w = h2bits(gelu_exact(p3.x + q3.x + ev1.z),
                             gelu_exact(p3.y + q3.y + ev1.w));
                *reinterpret_cast<uint4*>(hr + q * 16) = o;
            }
        }
        __syncthreads();

        // ---- GEMM2: D = hdn @ W2^T ----
        zero_c(c);
        gemm_pass<8>(c, aHDN, 16 * PB2, bW2, 16 * PB2);

        // ---- +b2, stage D f32 ----
        #pragma unroll
        for (int mt = 0; mt < 2; ++mt)
            #pragma unroll
            for (int j = 0; j < 8; ++j) {
                const int col = cbase + 8 * j;
                const float bb0 = b2s[col], bb1 = b2s[col + 1];
                #pragma unroll
                for (int rh = 0; rh < 2; ++rh) {
                    const int row = rbase + 16 * mt + 8 * rh;
                    *reinterpret_cast<float2*>(
                        smbuf + SM_D + row * PD + col * 4) =
                        make_float2(c[mt][j][2 * rh] + bb0,
                                    c[mt][j][2 * rh + 1] + bb1);
                }
            }
        __syncthreads();

        // ---- scatter red.global.add.v4 ----
        {
            float* gb = g_agg + (size_t)didx[grow] * 128 + ghf * 64;
            const float4* ds = reinterpret_cast<const float4*>(
                smbuf + SM_D + grow * PD + ghf * 256);
            #pragma unroll
            for (int q = 0; q < 16; ++q) {
                float4 v = ds[q];
                asm volatile("red.global.add.v4.f32 [%0], {%1,%2,%3,%4};"
                             :: "l"(gb + 4 * q),
                                "f"(v.x), "f"(v.y), "f"(v.z), "f"(v.w)
                             : "memory");
            }
        }
    }
}

// ---------------------------------------------------------------- LayerNorm
__global__ __launch_bounds__(256)
void ln_kernel(const float* __restrict__ h,
               const float* __restrict__ gamma,
               const float* __restrict__ beta,
               float* __restrict__ out) {
    const int row  = (blockIdx.x * blockDim.x + threadIdx.x) >> 5;
    const int lane = threadIdx.x & 31;
    if (row >= N_NODES) return;

    const float4 hv = reinterpret_cast<const float4*>(h)[(size_t)row * 32 + lane];
    const float4 av = reinterpret_cast<const float4*>(g_agg)[(size_t)row * 32 + lane];
    float4 x;
    x.x = hv.x + av.x; x.y = hv.y + av.y; x.z = hv.z + av.z; x.w = hv.w + av.w;

    float s = x.x + x.y + x.z + x.w;
    #pragma unroll
    for (int o = 16; o > 0; o >>= 1) s += __shfl_xor_sync(0xffffffffu, s, o);
    const float mu = s * (1.0f / 128.0f);

    const float dx = x.x - mu, dy = x.y - mu, dz = x.z - mu, dw = x.w - mu;
    float q = dx * dx + dy * dy + dz * dz + dw * dw;
    #pragma unroll
    for (int o = 16; o > 0; o >>= 1) q += __shfl_xor_sync(0xffffffffu, q, o);
    const float inv = rsqrtf(q * (1.0f / 128.0f) + 1e-5f);

    const float4 g = reinterpret_cast<const float4*>(gamma)[lane];
    const float4 b = reinterpret_cast<const float4*>(beta)[lane];
    float4 o4;
    o4.x = dx * inv * g.x + b.x;
    o4.y = dy * inv * g.y + b.y;
    o4.z = dz * inv * g.z + b.z;
    o4.w = dw * inv * g.w + b.w;
    reinterpret_cast<float4*>(out)[(size_t)row * 32 + lane] = o4;
}

// ----------------------------------------------------------------
extern "C" void kernel_launch(void* const* d_in, const int* in_sizes, int n_in,
                              void* d_out, int out_size) {
    const float* h     = (const float*)d_in[0];
    const int*   src   = (const int*)  d_in[1];
    const int*   dst   = (const int*)  d_in[2];
    const float* ea    = (const float*)d_in[3];
    const float* W1    = (const float*)d_in[4];
    const float* b1    = (const float*)d_in[5];
    const float* W2    = (const float*)d_in[6];
    const float* b2    = (const float*)d_in[7];
    const float* gamma = (const float*)d_in[8];
    const float* beta  = (const float*)d_in[9];
    float*       out   = (float*)d_out;

    static int sm_count = []() {
        int dev = 0, c = 148;
        cudaGetDevice(&dev);
        cudaDeviceGetAttribute(&c, cudaDevAttrMultiProcessorCount, dev);
        return c;
    }();
    static bool attr_ok = []() {
        cudaFuncSetAttribute(edge_mma_kernel,
                             cudaFuncAttributeMaxDynamicSharedMemorySize, SMEM_E);
        cudaFuncSetAttribute(node_kernel,
                             cudaFuncAttributeMaxDynamicSharedMemorySize, SMEM_N);
        return true;
    }();
    (void)attr_ok;

    prep_kernel<<<2048, 256>>>(h);
    node_kernel<<<NNT, 256, SMEM_N>>>(W1, b1);
    edge_mma_kernel<<<sm_count, 256, SMEM_E>>>(src, dst, ea, W1, W2, b2);
    ln_kernel<<<(N_NODES * 32 + 255) / 256, 256>>>(h, gamma, beta, out);
}

// round 6
// speedup vs baseline: 7.2600x; 1.0014x over previous
#include <cuda_runtime.h>
#include <cuda_fp16.h>
#include <math.h>
#include <stdint.h>

#define N_NODES 50000
#define N_EDGES 1600000
#define NT      12500       // edge tiles of 128
#define NNT     391         // node tiles of 128

// ---- pitches (bytes)
#define PB2  272    // fp16 [128][k=128 pad]
#define PBEA 48     // fp16 [128][k=16 pad]
#define PD   528    // f32 staging [128][132 words]

// ---- edge-kernel SMEM offsets
#define SM_W2   0           // 34816
#define SM_HDN  34816       // 34816
#define SM_D    69632       // 67584 (E1 then D staging)
#define SM_EA   137216      // 6144
#define SM_W1C  143360      // 6144
#define SM_B2   149504      // 512
#define SM_SIDX 150016      // 512
#define SM_DIDX 150528      // 512
#define SMEM_E  151040

// ---- node-kernel SMEM offsets
#define NSM_X   0           // 34816
#define NSM_B0  34816       // 34816
#define NSM_B1  69632       // 34816
#define NSM_OUT 104448      // 34816
#define NSM_B1S 139264      // 512
#define SMEM_N  139776

__device__ float   g_agg[(size_t)N_NODES * 128];
__device__ __half  g_pq [(size_t)N_NODES * 256];   // [node][0:128]=P=h@W1a+b1, [128:256]=Q=h@W1b

// ---------------------------------------------------------------- helpers
__device__ __forceinline__ uint32_t smem_u32(const void* p) {
    uint32_t a;
    asm("{ .reg .u64 t; cvta.to.shared.u64 t, %1; cvt.u32.u64 %0, t; }"
        : "=r"(a) : "l"(p));
    return a;
}
__device__ __forceinline__ void ldsm4(uint32_t* r, uint32_t addr) {
    asm volatile("ldmatrix.sync.aligned.m8n8.x4.shared.b16 {%0,%1,%2,%3}, [%4];"
                 : "=r"(r[0]), "=r"(r[1]), "=r"(r[2]), "=r"(r[3]) : "r"(addr));
}
__device__ __forceinline__ void mma16816(float* c, const uint32_t* a,
                                         const uint32_t* b) {
    asm volatile("mma.sync.aligned.m16n8k16.row.col.f32.f16.f16.f32 "
                 "{%0,%1,%2,%3}, {%4,%5,%6,%7}, {%8,%9}, {%0,%1,%2,%3};"
                 : "+f"(c[0]), "+f"(c[1]), "+f"(c[2]), "+f"(c[3])
                 : "r"(a[0]), "r"(a[1]), "r"(a[2]), "r"(a[3]),
                   "r"(b[0]), "r"(b[1]));
}
__device__ __forceinline__ uint32_t h2bits(float a, float b) {
    __half2 h = __floats2half2_rn(a, b);
    return *reinterpret_cast<uint32_t*>(&h);
}
__device__ __forceinline__ float gelu_exact(float v) {
    return 0.5f * v * (1.0f + erff(v * 0.70710678118654752440f));
}

// 4x4 warp-grid pass: warp tile 32m x 32n, NCH k16-chunks
template <int NCH>
__device__ __forceinline__ void gemm_pass44(float (&c)[2][4][4],
                                            uint32_t abase, uint32_t amstep,
                                            uint32_t bbase, uint32_t bnstep) {
    #pragma unroll
    for (int kc = 0; kc < NCH; ++kc) {
        uint32_t a[2][4], b[2][4];
        ldsm4(a[0], abase);
        ldsm4(a[1], abase + amstep);
        ldsm4(b[0], bbase);
        ldsm4(b[1], bbase + bnstep);
        #pragma unroll
        for (int mt = 0; mt < 2; ++mt)
            #pragma unroll
            for (int j = 0; j < 4; ++j)
                mma16816(c[mt][j], a[mt], &b[j >> 1][(j & 1) * 2]);
        abase += 32;
        bbase += 32;
    }
}
__device__ __forceinline__ void zero_c44(float (&c)[2][4][4]) {
    #pragma unroll
    for (int mt = 0; mt < 2; ++mt)
        #pragma unroll
        for (int j = 0; j < 4; ++j)
            #pragma unroll
            for (int i = 0; i < 4; ++i) c[mt][j][i] = 0.f;
}
// 4x2 warp-grid pass (node kernel, 8 warps): warp tile 32m x 64n
template <int NCH>
__device__ __forceinline__ void gemm_pass42(float (&c)[2][8][4],
                                            uint32_t abase, uint32_t amstep,
                                            uint32_t bbase, uint32_t bnstep) {
    #pragma unroll
    for (int kc = 0; kc < NCH; ++kc) {
        uint32_t a[2][4], b[4][4];
        ldsm4(a[0], abase);
        ldsm4(a[1], abase + amstep);
        ldsm4(b[0], bbase);
        ldsm4(b[1], bbase + bnstep);
        ldsm4(b[2], bbase + 2 * bnstep);
        ldsm4(b[3], bbase + 3 * bnstep);
        #pragma unroll
        for (int mt = 0; mt < 2; ++mt)
            #pragma unroll
            for (int j = 0; j < 8; ++j)
                mma16816(c[mt][j], a[mt], &b[j >> 1][(j & 1) * 2]);
        abase += 32;
        bbase += 32;
    }
}

// ---------------------------------------------------------------- prep: zero agg
__global__ void prep_kernel() {
    float4* p = reinterpret_cast<float4*>(g_agg);
    const int n = N_NODES * 128 / 4;
    for (int i = blockIdx.x * blockDim.x + threadIdx.x; i < n;
         i += gridDim.x * blockDim.x)
        p[i] = make_float4(0.f, 0.f, 0.f, 0.f);
}

// ---------------------------------------------------------------- node kernel:
// g_pq[n] = [ h@W1a + b1 | h@W1b ]   (f32 in, fp16 out, f32 accum)
__global__ __launch_bounds__(256, 1)
void node_kernel(const float* __restrict__ h,
                 const float* __restrict__ W1, const float* __restrict__ b1) {
    extern __shared__ char smbuf[];
    const uint32_t sb = smem_u32(smbuf);
    float* b1s = reinterpret_cast<float*>(smbuf + NSM_B1S);

    const int t = threadIdx.x, l = t & 31, warp = t >> 5;
    const int wm = warp & 3, wn = warp >> 2;
    const int grow = t & 127, ghf = t >> 7;

    for (int i = t; i < 128 * 128; i += 256) {
        int k = i >> 7, n = i & 127;
        *reinterpret_cast<__half*>(smbuf + NSM_B0 + n * PB2 + k * 2) =
            __float2half_rn(W1[k * 128 + n]);
        *reinterpret_cast<__half*>(smbuf + NSM_B1 + n * PB2 + k * 2) =
            __float2half_rn(W1[(k + 128) * 128 + n]);
    }
    if (t < 128) b1s[t] = b1[t];

    const uint32_t aoff = ((l & 7) + 8 * ((l >> 3) & 1)) * PB2 + (l >> 4) * 16;
    const uint32_t boff = ((l & 7) + 8 * (l >> 4)) * PB2 + ((l >> 3) & 1) * 16;
    const uint32_t aX  = sb + NSM_X + 32 * wm * PB2 + aoff;
    const uint32_t bB0 = sb + NSM_B0 + 64 * wn * PB2 + boff;
    const uint32_t bB1 = sb + NSM_B1 + 64 * wn * PB2 + boff;
    const int rbase = 32 * wm + (l >> 2);
    const int cbase = 64 * wn + 2 * (l & 3);

    const int m0 = blockIdx.x * 128;
    const int node = m0 + grow;
    const int nc = node < N_NODES ? node : N_NODES - 1;

    // stage X = fp16(h[node tile])
    {
        const float4* ps = reinterpret_cast<const float4*>(
            h + (size_t)nc * 128 + ghf * 64);
        char* xr = smbuf + NSM_X + grow * PB2 + ghf * 128;
        #pragma unroll
        for (int q = 0; q < 16; ++q) {
            float4 v = ps[q];
            *reinterpret_cast<uint2*>(xr + q * 8) =
                make_uint2(h2bits(v.x, v.y), h2bits(v.z, v.w));
        }
    }
    __syncthreads();

    #pragma unroll
    for (int pass = 0; pass < 2; ++pass) {
        float c[2][8][4];
        #pragma unroll
        for (int mt = 0; mt < 2; ++mt)
            #pragma unroll
            for (int j = 0; j < 8; ++j)
                #pragma unroll
                for (int i = 0; i < 4; ++i) c[mt][j][i] = 0.f;
        gemm_pass42<8>(c, aX, 16 * PB2, pass ? bB1 : bB0, 16 * PB2);
        #pragma unroll
        for (int mt = 0; mt < 2; ++mt)
            #pragma unroll
            for (int j = 0; j < 8; ++j) {
                const int col = cbase + 8 * j;
                const float bb0 = pass ? 0.f : b1s[col];
                const float bb1 = pass ? 0.f : b1s[col + 1];
                #pragma unroll
                for (int rh = 0; rh < 2; ++rh) {
                    const int row = rbase + 16 * mt + 8 * rh;
                    *reinterpret_cast<uint32_t*>(
                        smbuf + NSM_OUT + row * PB2 + col * 2) =
                        h2bits(c[mt][j][2 * rh] + bb0, c[mt][j][2 * rh + 1] + bb1);
                }
            }
        __syncthreads();
        if (node < N_NODES) {
            const uint4* os = reinterpret_cast<const uint4*>(
                smbuf + NSM_OUT + grow * PB2 + ghf * 128);
            uint4* po = reinterpret_cast<uint4*>(
                g_pq + (size_t)node * 256 + pass * 128 + ghf * 64);
            #pragma unroll
            for (int q = 0; q < 8; ++q) po[q] = os[q];
        }
        __syncthreads();
    }
}

// ---------------------------------------------------------------- edge kernel (512 thr)
__global__ __launch_bounds__(512, 1)
void edge_mma_kernel(const int*   __restrict__ src,
                     const int*   __restrict__ dst,
                     const float* __restrict__ ea,
                     const float* __restrict__ W1,
                     const float* __restrict__ W2,
                     const float* __restrict__ b2) {
    extern __shared__ char smbuf[];
    const uint32_t sb = smem_u32(smbuf);
    float* b2s = reinterpret_cast<float*>(smbuf + SM_B2);
    int* sidx  = reinterpret_cast<int*>(smbuf + SM_SIDX);
    int* didx  = reinterpret_cast<int*>(smbuf + SM_DIDX);

    const int t = threadIdx.x, l = t & 31, warp = t >> 5;
    const int wm = warp & 3, wn = warp >> 2;     // 4x4 warp grid
    const int grow = t & 127, gq = t >> 7;       // row + quarter for gather/scatter

    // ---- stage W2^T and W1c^T (fp16) + b2 ----
    for (int i = t; i < 128 * 128; i += 512) {
        int k = i >> 7, n = i & 127;
        *reinterpret_cast<__half*>(smbuf + SM_W2 + n * PB2 + k * 2) =
            __float2half_rn(W2[i]);
    }
    for (int i = t; i < 16 * 128; i += 512) {
        int k = i >> 7, n = i & 127;
        *reinterpret_cast<__half*>(smbuf + SM_W1C + n * PBEA + k * 2) =
            __float2half_rn(W1[(k + 256) * 128 + n]);
    }
    if (t < 128) b2s[t] = b2[t];

    const uint32_t aoff272 = ((l & 7) + 8 * ((l >> 3) & 1)) * PB2 + (l >> 4) * 16;
    const uint32_t aoff48  = ((l & 7) + 8 * ((l >> 3) & 1)) * PBEA + (l >> 4) * 16;
    const uint32_t boff272 = ((l & 7) + 8 * (l >> 4)) * PB2 + ((l >> 3) & 1) * 16;
    const uint32_t boff48  = ((l & 7) + 8 * (l >> 4)) * PBEA + ((l >> 3) & 1) * 16;

    const uint32_t aEA  = sb + SM_EA  + 32 * wm * PBEA + aoff48;
    const uint32_t aHDN = sb + SM_HDN + 32 * wm * PB2 + aoff272;
    const uint32_t bW1C = sb + SM_W1C + 32 * wn * PBEA + boff48;
    const uint32_t bW2  = sb + SM_W2  + 32 * wn * PB2 + boff272;
    const int rbase = 32 * wm + (l >> 2);
    const int cbase = 32 * wn + 2 * (l & 3);

    __syncthreads();

    // preload W1c B-fragments (constant across tiles)
    uint32_t bE1[2][4];
    ldsm4(bE1[0], bW1C);
    ldsm4(bE1[1], bW1C + 16 * PBEA);

    for (int tile = blockIdx.x; tile < NT; tile += gridDim.x) {
        const int e0 = tile << 7;
        __syncthreads();                       // prev tile fully consumed
        if (t < 128) sidx[t] = src[e0 + t];
        else if (t < 256) didx[t - 128] = dst[e0 + t - 128];
        __syncthreads();

        // ---- gather EA -> SMEM fp16 (1 float4/thread) ----
        {
            const int ee = t >> 2, qq = t & 3;
            float4 v = reinterpret_cast<const float4*>(
                ea + (size_t)(e0 + ee) * 16)[qq];
            *reinterpret_cast<uint2*>(smbuf + SM_EA + ee * PBEA + qq * 8) =
                make_uint2(h2bits(v.x, v.y), h2bits(v.z, v.w));
        }
        __syncthreads();

        // ---- E1 = ea @ W1c^T (K=16, preloaded B), stage f32 in SM_D ----
        float c[2][4][4];
        zero_c44(c);
        {
            uint32_t a[2][4];
            ldsm4(a[0], aEA);
            ldsm4(a[1], aEA + 16 * PBEA);
            #pragma unroll
            for (int mt = 0; mt < 2; ++mt)
                #pragma unroll
                for (int j = 0; j < 4; ++j)
                    mma16816(c[mt][j], a[mt], &bE1[j >> 1][(j & 1) * 2]);
        }
        #pragma unroll
        for (int mt = 0; mt < 2; ++mt)
            #pragma unroll
            for (int j = 0; j < 4; ++j) {
                const int col = cbase + 8 * j;
                #pragma unroll
                for (int rh = 0; rh < 2; ++rh) {
                    const int row = rbase + 16 * mt + 8 * rh;
                    *reinterpret_cast<float2*>(
                        smbuf + SM_D + row * PD + col * 4) =
                        make_float2(c[mt][j][2 * rh], c[mt][j][2 * rh + 1]);
                }
            }
        __syncthreads();

        // ---- elementwise: hdn = gelu(P[src] + Q[dst] + E1) (fp16) ----
        {
            const uint4* pp = reinterpret_cast<const uint4*>(
                g_pq + (size_t)sidx[grow] * 256 + gq * 32);
            const uint4* qq = reinterpret_cast<const uint4*>(
                g_pq + (size_t)didx[grow] * 256 + 128 + gq * 32);
            const float4* e1 = reinterpret_cast<const float4*>(
                smbuf + SM_D + grow * PD + gq * 128);
            char* hr = smbuf + SM_HDN + grow * PB2 + gq * 64;
            #pragma unroll
            for (int q = 0; q < 4; ++q) {
                const uint4 pv = pp[q];
                const uint4 qv = qq[q];
                const float4 ev0 = e1[2 * q];
                const float4 ev1 = e1[2 * q + 1];
                const __half2* ph = reinterpret_cast<const __half2*>(&pv);
                const __half2* qh = reinterpret_cast<const __half2*>(&qv);
                float2 p0 = __half22float2(ph[0]), q0 = __half22float2(qh[0]);
                float2 p1 = __half22float2(ph[1]), q1 = __half22float2(qh[1]);
                float2 p2 = __half22float2(ph[2]), q2 = __half22float2(qh[2]);
                float2 p3 = __half22float2(ph[3]), q3 = __half22float2(qh[3]);
                uint4 o;
                o.x = h2bits(gelu_exact(p0.x + q0.x + ev0.x),
                             gelu_exact(p0.y + q0.y + ev0.y));
                o.y = h2bits(gelu_exact(p1.x + q1.x + ev0.z),
                             gelu_exact(p1.y + q1.y + ev0.w));
                o.z = h2bits(gelu_exact(p2.x + q2.x + ev1.x),
                             gelu_exact(p2.y + q2.y + ev1.y));
                o.w = h2bits(gelu_exact(p3.x + q3.x + ev1.z),
                             gelu_exact(p3.y + q3.y + ev1.w));
                *reinterpret_cast<uint4*>(hr + q * 16) = o;
            }
        }
        __syncthreads();

        // ---- GEMM2: D = hdn @ W2^T ----
        zero_c44(c);
        gemm_pass44<8>(c, aHDN, 16 * PB2, bW2, 16 * PB2);

        // ---- +b2, stage D f32 ----
        #pragma unroll
        for (int mt = 0; mt < 2; ++mt)
            #pragma unroll
            for (int j = 0; j < 4; ++j) {
                const int col = cbase + 8 * j;
                const float bb0 = b2s[col], bb1 = b2s[col + 1];
                #pragma unroll
                for (int rh = 0; rh < 2; ++rh) {
                    const int row = rbase + 16 * mt + 8 * rh;
                    *reinterpret_cast<float2*>(
                        smbuf + SM_D + row * PD + col * 4) =
                        make_float2(c[mt][j][2 * rh] + bb0,
                                    c[mt][j][2 * rh + 1] + bb1);
                }
            }
        __syncthreads();

        // ---- scatter red.global.add.v4 (8 per thread) ----
        {
            float* gb = g_agg + (size_t)didx[grow] * 128 + gq * 32;
            const float4* ds = reinterpret_cast<const float4*>(
                smbuf + SM_D + grow * PD + gq * 128);
            #pragma unroll
            for (int q = 0; q < 8; ++q) {
                float4 v = ds[q];
                asm volatile("red.global.add.v4.f32 [%0], {%1,%2,%3,%4};"
                             :: "l"(gb + 4 * q),
                                "f"(v.x), "f"(v.y), "f"(v.z), "f"(v.w)
                             : "memory");
            }
        }
    }
}

// ---------------------------------------------------------------- LayerNorm
__global__ __launch_bounds__(256)
void ln_kernel(const float* __restrict__ h,
               const float* __restrict__ gamma,
               const float* __restrict__ beta,
               float* __restrict__ out) {
    const int row  = (blockIdx.x * blockDim.x + threadIdx.x) >> 5;
    const int lane = threadIdx.x & 31;
    if (row >= N_NODES) return;

    const float4 hv = reinterpret_cast<const float4*>(h)[(size_t)row * 32 + lane];
    const float4 av = reinterpret_cast<const float4*>(g_agg)[(size_t)row * 32 + lane];
    float4 x;
    x.x = hv.x + av.x; x.y = hv.y + av.y; x.z = hv.z + av.z; x.w = hv.w + av.w;

    float s = x.x + x.y + x.z + x.w;
    #pragma unroll
    for (int o = 16; o > 0; o >>= 1) s += __shfl_xor_sync(0xffffffffu, s, o);
    const float mu = s * (1.0f / 128.0f);

    const float dx = x.x - mu, dy = x.y - mu, dz = x.z - mu, dw = x.w - mu;
    float q = dx * dx + dy * dy + dz * dz + dw * dw;
    #pragma unroll
    for (int o = 16; o > 0; o >>= 1) q += __shfl_xor_sync(0xffffffffu, q, o);
    const float inv = rsqrtf(q * (1.0f / 128.0f) + 1e-5f);

    const float4 g = reinterpret_cast<const float4*>(gamma)[lane];
    const float4 b = reinterpret_cast<const float4*>(beta)[lane];
    float4 o4;
    o4.x = dx * inv * g.x + b.x;
    o4.y = dy * inv * g.y + b.y;
    o4.z = dz * inv * g.z + b.z;
    o4.w = dw * inv * g.w + b.w;
    reinterpret_cast<float4*>(out)[(size_t)row * 32 + lane] = o4;
}

// ----------------------------------------------------------------
extern "C" void kernel_launch(void* const* d_in, const int* in_sizes, int n_in,
                              void* d_out, int out_size) {
    const float* h     = (const float*)d_in[0];
    const int*   src   = (const int*)  d_in[1];
    const int*   dst   = (const int*)  d_in[2];
    const float* ea    = (const float*)d_in[3];
    const float* W1    = (const float*)d_in[4];
    const float* b1    = (const float*)d_in[5];
    const float* W2    = (const float*)d_in[6];
    const float* b2    = (const float*)d_in[7];
    const float* gamma = (const float*)d_in[8];
    const float* beta  = (const float*)d_in[9];
    float*       out   = (float*)d_out;

    static int sm_count = []() {
        int dev = 0, c = 148;
        cudaGetDevice(&dev);
        cudaDeviceGetAttribute(&c, cudaDevAttrMultiProcessorCount, dev);
        return c;
    }();
    static bool attr_ok = []() {
        cudaFuncSetAttribute(edge_mma_kernel,
                             cudaFuncAttributeMaxDynamicSharedMemorySize, SMEM_E);
        cudaFuncSetAttribute(node_kernel,
                             cudaFuncAttributeMaxDynamicSharedMemorySize, SMEM_N);
        return true;
    }();
    (void)attr_ok;

    prep_kernel<<<2048, 256>>>();
    node_kernel<<<NNT, 256, SMEM_N>>>(h, W1, b1);
    edge_mma_kernel<<<sm_count, 512, SMEM_E>>>(src, dst, ea, W1, W2, b2);
    ln_kernel<<<(N_NODES * 32 + 255) / 256, 256>>>(h, gamma, beta, out);
}

// round 7
// speedup vs baseline: 7.4725x; 1.0293x over previous
#include <cuda_runtime.h>
#include <cuda_fp16.h>
#include <math.h>
#include <stdint.h>

#define N_NODES 50000
#define N_EDGES 1600000
#define NT      12500       // edge tiles of 128
#define NNT     391         // node tiles of 128

// ---- pitches (bytes)
#define PB2  272    // fp16 [128][k=128 pad]
#define PBEA 48     // fp16 [128][k=16 pad]
#define PD   528    // f32 staging [128][132 words]
#define PE1  272    // fp16 E1 staging [128][136 halfs]

// ---- edge-kernel SMEM offsets
#define SM_W2   0           // 34816
#define SM_HDN  34816       // 34816
#define SM_D    69632       // 67584 (E1 fp16, then D f32 staging)
#define SM_E1   SM_D
#define SM_EA   137216      // 6144
#define SM_W1C  143360      // 6144
#define SM_B2   149504      // 512
#define SM_SIDX 150016      // 512
#define SM_DIDX 150528      // 512
#define SMEM_E  151040

// ---- node-kernel SMEM offsets
#define NSM_X   0           // 34816
#define NSM_B0  34816       // 34816
#define NSM_B1  69632       // 34816
#define NSM_OUT 104448      // 34816
#define NSM_B1S 139264      // 512
#define SMEM_N  139776

__device__ float   g_agg[(size_t)N_NODES * 128];
__device__ __half  g_pq [(size_t)N_NODES * 256];   // [node][0:128]=P=h@W1a+b1, [128:256]=Q=h@W1b

// ---------------------------------------------------------------- helpers
__device__ __forceinline__ uint32_t smem_u32(const void* p) {
    uint32_t a;
    asm("{ .reg .u64 t; cvta.to.shared.u64 t, %1; cvt.u32.u64 %0, t; }"
        : "=r"(a) : "l"(p));
    return a;
}
__device__ __forceinline__ void ldsm4(uint32_t* r, uint32_t addr) {
    asm volatile("ldmatrix.sync.aligned.m8n8.x4.shared.b16 {%0,%1,%2,%3}, [%4];"
                 : "=r"(r[0]), "=r"(r[1]), "=r"(r[2]), "=r"(r[3]) : "r"(addr));
}
__device__ __forceinline__ void mma16816(float* c, const uint32_t* a,
                                         const uint32_t* b) {
    asm volatile("mma.sync.aligned.m16n8k16.row.col.f32.f16.f16.f32 "
                 "{%0,%1,%2,%3}, {%4,%5,%6,%7}, {%8,%9}, {%0,%1,%2,%3};"
                 : "+f"(c[0]), "+f"(c[1]), "+f"(c[2]), "+f"(c[3])
                 : "r"(a[0]), "r"(a[1]), "r"(a[2]), "r"(a[3]),
                   "r"(b[0]), "r"(b[1]));
}
__device__ __forceinline__ uint32_t h2bits(float a, float b) {
    __half2 h = __floats2half2_rn(a, b);
    return *reinterpret_cast<uint32_t*>(&h);
}
// branchless exact-GELU: Abramowitz-Stegun 7.1.26 erf (abs err 1.5e-7)
__device__ __forceinline__ float gelu_fast(float v) {
    const float x = v * 0.70710678118654752440f;
    const float s = fabsf(x);
    const float t = __fdividef(1.0f, fmaf(0.3275911f, s, 1.0f));
    const float e = __expf(-s * s);
    float p = fmaf(t, 1.061405429f, -1.453152027f);
    p = fmaf(t, p, 1.421413741f);
    p = fmaf(t, p, -0.284496736f);
    p = fmaf(t, p, 0.254829592f);
    p = p * t;
    const float erfs = fmaf(-p, e, 1.0f);
    const float erfx = copysignf(erfs, x);
    return 0.5f * v * (1.0f + erfx);
}

// 4x2 warp-grid pass (node kernel, 8 warps): warp tile 32m x 64n
template <int NCH>
__device__ __forceinline__ void gemm_pass42(float (&c)[2][8][4],
                                            uint32_t abase, uint32_t amstep,
                                            uint32_t bbase, uint32_t bnstep) {
    #pragma unroll
    for (int kc = 0; kc < NCH; ++kc) {
        uint32_t a[2][4], b[4][4];
        ldsm4(a[0], abase);
        ldsm4(a[1], abase + amstep);
        ldsm4(b[0], bbase);
        ldsm4(b[1], bbase + bnstep);
        ldsm4(b[2], bbase + 2 * bnstep);
        ldsm4(b[3], bbase + 3 * bnstep);
        #pragma unroll
        for (int mt = 0; mt < 2; ++mt)
            #pragma unroll
            for (int j = 0; j < 8; ++j)
                mma16816(c[mt][j], a[mt], &b[j >> 1][(j & 1) * 2]);
        abase += 32;
        bbase += 32;
    }
}
__device__ __forceinline__ void zero_c44(float (&c)[2][4][4]) {
    #pragma unroll
    for (int mt = 0; mt < 2; ++mt)
        #pragma unroll
        for (int j = 0; j < 4; ++j)
            #pragma unroll
            for (int i = 0; i < 4; ++i) c[mt][j][i] = 0.f;
}

// ---------------------------------------------------------------- prep: zero agg
__global__ void prep_kernel() {
    float4* p = reinterpret_cast<float4*>(g_agg);
    const int n = N_NODES * 128 / 4;
    for (int i = blockIdx.x * blockDim.x + threadIdx.x; i < n;
         i += gridDim.x * blockDim.x)
        p[i] = make_float4(0.f, 0.f, 0.f, 0.f);
}

// ---------------------------------------------------------------- node kernel
__global__ __launch_bounds__(256, 1)
void node_kernel(const float* __restrict__ h,
                 const float* __restrict__ W1, const float* __restrict__ b1) {
    extern __shared__ char smbuf[];
    const uint32_t sb = smem_u32(smbuf);
    float* b1s = reinterpret_cast<float*>(smbuf + NSM_B1S);

    const int t = threadIdx.x, l = t & 31, warp = t >> 5;
    const int wm = warp & 3, wn = warp >> 2;
    const int grow = t & 127, ghf = t >> 7;

    for (int i = t; i < 128 * 128; i += 256) {
        int k = i >> 7, n = i & 127;
        *reinterpret_cast<__half*>(smbuf + NSM_B0 + n * PB2 + k * 2) =
            __float2half_rn(W1[k * 128 + n]);
        *reinterpret_cast<__half*>(smbuf + NSM_B1 + n * PB2 + k * 2) =
            __float2half_rn(W1[(k + 128) * 128 + n]);
    }
    if (t < 128) b1s[t] = b1[t];

    const uint32_t aoff = ((l & 7) + 8 * ((l >> 3) & 1)) * PB2 + (l >> 4) * 16;
    const uint32_t boff = ((l & 7) + 8 * (l >> 4)) * PB2 + ((l >> 3) & 1) * 16;
    const uint32_t aX  = sb + NSM_X + 32 * wm * PB2 + aoff;
    const uint32_t bB0 = sb + NSM_B0 + 64 * wn * PB2 + boff;
    const uint32_t bB1 = sb + NSM_B1 + 64 * wn * PB2 + boff;
    const int rbase = 32 * wm + (l >> 2);
    const int cbase = 64 * wn + 2 * (l & 3);

    const int m0 = blockIdx.x * 128;
    const int node = m0 + grow;
    const int nc = node < N_NODES ? node : N_NODES - 1;

    {
        const float4* ps = reinterpret_cast<const float4*>(
            h + (size_t)nc * 128 + ghf * 64);
        char* xr = smbuf + NSM_X + grow * PB2 + ghf * 128;
        #pragma unroll
        for (int q = 0; q < 16; ++q) {
            float4 v = ps[q];
            *reinterpret_cast<uint2*>(xr + q * 8) =
                make_uint2(h2bits(v.x, v.y), h2bits(v.z, v.w));
        }
    }
    __syncthreads();

    #pragma unroll
    for (int pass = 0; pass < 2; ++pass) {
        float c[2][8][4];
        #pragma unroll
        for (int mt = 0; mt < 2; ++mt)
            #pragma unroll
            for (int j = 0; j < 8; ++j)
                #pragma unroll
                for (int i = 0; i < 4; ++i) c[mt][j][i] = 0.f;
        gemm_pass42<8>(c, aX, 16 * PB2, pass ? bB1 : bB0, 16 * PB2);
        #pragma unroll
        for (int mt = 0; mt < 2; ++mt)
            #pragma unroll
            for (int j = 0; j < 8; ++j) {
                const int col = cbase + 8 * j;
                const float bb0 = pass ? 0.f : b1s[col];
                const float bb1 = pass ? 0.f : b1s[col + 1];
                #pragma unroll
                for (int rh = 0; rh < 2; ++rh) {
                    const int row = rbase + 16 * mt + 8 * rh;
                    *reinterpret_cast<uint32_t*>(
                        smbuf + NSM_OUT + row * PB2 + col * 2) =
                        h2bits(c[mt][j][2 * rh] + bb0, c[mt][j][2 * rh + 1] + bb1);
                }
            }
        __syncthreads();
        if (node < N_NODES) {
            const uint4* os = reinterpret_cast<const uint4*>(
                smbuf + NSM_OUT + grow * PB2 + ghf * 128);
            uint4* po = reinterpret_cast<uint4*>(
                g_pq + (size_t)node * 256 + pass * 128 + ghf * 64);
            #pragma unroll
            for (int q = 0; q < 8; ++q) po[q] = os[q];
        }
        __syncthreads();
    }
}

// ---------------------------------------------------------------- edge kernel (512 thr)
__global__ __launch_bounds__(512, 1)
void edge_mma_kernel(const int*   __restrict__ src,
                     const int*   __restrict__ dst,
                     const float* __restrict__ ea,
                     const float* __restrict__ W1,
                     const float* __restrict__ W2,
                     const float* __restrict__ b2) {
    extern __shared__ char smbuf[];
    const uint32_t sb = smem_u32(smbuf);
    float* b2s = reinterpret_cast<float*>(smbuf + SM_B2);
    int* sidx  = reinterpret_cast<int*>(smbuf + SM_SIDX);
    int* didx  = reinterpret_cast<int*>(smbuf + SM_DIDX);

    const int t = threadIdx.x, l = t & 31, warp = t >> 5;
    const int wm = warp & 3, wn = warp >> 2;     // 4x4 warp grid
    const int grow = t & 127, gq = t >> 7;       // row + quarter

    // ---- stage W2^T and W1c^T (fp16) + b2 ----
    for (int i = t; i < 128 * 128; i += 512) {
        int k = i >> 7, n = i & 127;
        *reinterpret_cast<__half*>(smbuf + SM_W2 + n * PB2 + k * 2) =
            __float2half_rn(W2[i]);
    }
    for (int i = t; i < 16 * 128; i += 512) {
        int k = i >> 7, n = i & 127;
        *reinterpret_cast<__half*>(smbuf + SM_W1C + n * PBEA + k * 2) =
            __float2half_rn(W1[(k + 256) * 128 + n]);
    }
    if (t < 128) b2s[t] = b2[t];

    const uint32_t aoff272 = ((l & 7) + 8 * ((l >> 3) & 1)) * PB2 + (l >> 4) * 16;
    const uint32_t aoff48  = ((l & 7) + 8 * ((l >> 3) & 1)) * PBEA + (l >> 4) * 16;
    const uint32_t boff272 = ((l & 7) + 8 * (l >> 4)) * PB2 + ((l >> 3) & 1) * 16;
    const uint32_t boff48  = ((l & 7) + 8 * (l >> 4)) * PBEA + ((l >> 3) & 1) * 16;

    const uint32_t aEA  = sb + SM_EA  + 32 * wm * PBEA + aoff48;
    const uint32_t aHDN = sb + SM_HDN + 32 * wm * PB2 + aoff272;
    const uint32_t bW1C = sb + SM_W1C + 32 * wn * PBEA + boff48;
    const uint32_t bW2  = sb + SM_W2  + 32 * wn * PB2 + boff272;
    const int rbase = 32 * wm + (l >> 2);
    const int cbase = 32 * wn + 2 * (l & 3);

    __syncthreads();

    // ---- preload ALL W2 B-fragments for this warp's 32n (constant over tiles)
    uint32_t bw[8][8];
    #pragma unroll
    for (int kc = 0; kc < 8; ++kc) {
        ldsm4(&bw[kc][0], bW2 + kc * 32);
        ldsm4(&bw[kc][4], bW2 + kc * 32 + 16 * PB2);
    }

    for (int tile = blockIdx.x; tile < NT; tile += gridDim.x) {
        const int e0 = tile << 7;
        __syncthreads();                       // prev tile fully consumed
        if (t < 128) sidx[t] = src[e0 + t];
        else if (t < 256) didx[t - 128] = dst[e0 + t - 128];
        __syncthreads();

        // ---- gather EA -> SMEM fp16 (1 float4/thread) ----
        {
            const int ee = t >> 2, qq = t & 3;
            float4 v = reinterpret_cast<const float4*>(
                ea + (size_t)(e0 + ee) * 16)[qq];
            *reinterpret_cast<uint2*>(smbuf + SM_EA + ee * PBEA + qq * 8) =
                make_uint2(h2bits(v.x, v.y), h2bits(v.z, v.w));
        }
        __syncthreads();

        // ---- E1 = ea @ W1c^T (K=16), stage fp16 in SM_E1 ----
        float c[2][4][4];
        zero_c44(c);
        {
            uint32_t a[2][4], bE1[8];
            ldsm4(&bE1[0], bW1C);
            ldsm4(&bE1[4], bW1C + 16 * PBEA);
            ldsm4(a[0], aEA);
            ldsm4(a[1], aEA + 16 * PBEA);
            #pragma unroll
            for (int mt = 0; mt < 2; ++mt)
                #pragma unroll
                for (int j = 0; j < 4; ++j)
                    mma16816(c[mt][j], a[mt], &bE1[(j >> 1) * 4 + (j & 1) * 2]);
        }
        #pragma unroll
        for (int mt = 0; mt < 2; ++mt)
            #pragma unroll
            for (int j = 0; j < 4; ++j) {
                const int col = cbase + 8 * j;
                #pragma unroll
                for (int rh = 0; rh < 2; ++rh) {
                    const int row = rbase + 16 * mt + 8 * rh;
                    *reinterpret_cast<uint32_t*>(
                        smbuf + SM_E1 + row * PE1 + col * 2) =
                        h2bits(c[mt][j][2 * rh], c[mt][j][2 * rh + 1]);
                }
            }
        __syncthreads();

        // ---- elementwise: hdn = gelu(P[src] + Q[dst] + E1) (fp16) ----
        {
            const uint4* pp = reinterpret_cast<const uint4*>(
                g_pq + (size_t)sidx[grow] * 256 + gq * 32);
            const uint4* qq = reinterpret_cast<const uint4*>(
                g_pq + (size_t)didx[grow] * 256 + 128 + gq * 32);
            const uint4* e1 = reinterpret_cast<const uint4*>(
                smbuf + SM_E1 + grow * PE1 + gq * 64);
            char* hr = smbuf + SM_HDN + grow * PB2 + gq * 64;
            #pragma unroll
            for (int q = 0; q < 4; ++q) {
                const uint4 pv = pp[q];
                const uint4 qv = qq[q];
                const uint4 ev = e1[q];
                const __half2* ph = reinterpret_cast<const __half2*>(&pv);
                const __half2* qh = reinterpret_cast<const __half2*>(&qv);
                const __half2* eh = reinterpret_cast<const __half2*>(&ev);
                uint4 o;
                uint32_t* op = reinterpret_cast<uint32_t*>(&o);
                #pragma unroll
                for (int w = 0; w < 4; ++w) {
                    float2 pf = __half22float2(ph[w]);
                    float2 qf = __half22float2(qh[w]);
                    float2 ef = __half22float2(eh[w]);
                    op[w] = h2bits(gelu_fast(pf.x + qf.x + ef.x),
                                   gelu_fast(pf.y + qf.y + ef.y));
                }
                *reinterpret_cast<uint4*>(hr + q * 16) = o;
            }
        }
        __syncthreads();

        // ---- GEMM2: D = hdn @ W2^T (B from registers) ----
        zero_c44(c);
        {
            uint32_t abase = aHDN;
            #pragma unroll
            for (int kc = 0; kc < 8; ++kc) {
                uint32_t a[2][4];
                ldsm4(a[0], abase);
                ldsm4(a[1], abase + 16 * PB2);
                #pragma unroll
                for (int mt = 0; mt < 2; ++mt)
                    #pragma unroll
                    for (int j = 0; j < 4; ++j)
                        mma16816(c[mt][j], a[mt],
                                 &bw[kc][(j >> 1) * 4 + (j & 1) * 2]);
                abase += 32;
            }
        }

        // ---- +b2, stage D f32 ----
        #pragma unroll
        for (int mt = 0; mt < 2; ++mt)
            #pragma unroll
            for (int j = 0; j < 4; ++j) {
                const int col = cbase + 8 * j;
                const float bb0 = b2s[col], bb1 = b2s[col + 1];
                #pragma unroll
                for (int rh = 0; rh < 2; ++rh) {
                    const int row = rbase + 16 * mt + 8 * rh;
                    *reinterpret_cast<float2*>(
                        smbuf + SM_D + row * PD + col * 4) =
                        make_float2(c[mt][j][2 * rh] + bb0,
                                    c[mt][j][2 * rh + 1] + bb1);
                }
            }
        __syncthreads();

        // ---- scatter red.global.add.v4 (8 per thread) ----
        {
            float* gb = g_agg + (size_t)didx[grow] * 128 + gq * 32;
            const float4* ds = reinterpret_cast<const float4*>(
                smbuf + SM_D + grow * PD + gq * 128);
            #pragma unroll
            for (int q = 0; q < 8; ++q) {
                float4 v = ds[q];
                asm volatile("red.global.add.v4.f32 [%0], {%1,%2,%3,%4};"
                             :: "l"(gb + 4 * q),
                                "f"(v.x), "f"(v.y), "f"(v.z), "f"(v.w)
                             : "memory");
            }
        }
    }
}

// ---------------------------------------------------------------- LayerNorm
__global__ __launch_bounds__(256)
void ln_kernel(const float* __restrict__ h,
               const float* __restrict__ gamma,
               const float* __restrict__ beta,
               float* __restrict__ out) {
    const int row  = (blockIdx.x * blockDim.x + threadIdx.x) >> 5;
    const int lane = threadIdx.x & 31;
    if (row >= N_NODES) return;

    const float4 hv = reinterpret_cast<const float4*>(h)[(size_t)row * 32 + lane];
    const float4 av = reinterpret_cast<const float4*>(g_agg)[(size_t)row * 32 + lane];
    float4 x;
    x.x = hv.x + av.x; x.y = hv.y + av.y; x.z = hv.z + av.z; x.w = hv.w + av.w;

    float s = x.x + x.y + x.z + x.w;
    #pragma unroll
    for (int o = 16; o > 0; o >>= 1) s += __shfl_xor_sync(0xffffffffu, s, o);
    const float mu = s * (1.0f / 128.0f);

    const float dx = x.x - mu, dy = x.y - mu, dz = x.z - mu, dw = x.w - mu;
    float q = dx * dx + dy * dy + dz * dz + dw * dw;
    #pragma unroll
    for (int o = 16; o > 0; o >>= 1) q += __shfl_xor_sync(0xffffffffu, q, o);
    const float inv = rsqrtf(q * (1.0f / 128.0f) + 1e-5f);

    const float4 g = reinterpret_cast<const float4*>(gamma)[lane];
    const float4 b = reinterpret_cast<const float4*>(beta)[lane];
    float4 o4;
    o4.x = dx * inv * g.x + b.x;
    o4.y = dy * inv * g.y + b.y;
    o4.z = dz * inv * g.z + b.z;
    o4.w = dw * inv * g.w + b.w;
    reinterpret_cast<float4*>(out)[(size_t)row * 32 + lane] = o4;
}

// ----------------------------------------------------------------
extern "C" void kernel_launch(void* const* d_in, const int* in_sizes, int n_in,
                              void* d_out, int out_size) {
    const float* h     = (const float*)d_in[0];
    const int*   src   = (const int*)  d_in[1];
    const int*   dst   = (const int*)  d_in[2];
    const float* ea    = (const float*)d_in[3];
    const float* W1    = (const float*)d_in[4];
    const float* b1    = (const float*)d_in[5];
    const float* W2    = (const float*)d_in[6];
    const float* b2    = (const float*)d_in[7];
    const float* gamma = (const float*)d_in[8];
    const float* beta  = (const float*)d_in[9];
    float*       out   = (float*)d_out;

    static int sm_count = []() {
        int dev = 0, c = 148;
        cudaGetDevice(&dev);
        cudaDeviceGetAttribute(&c, cudaDevAttrMultiProcessorCount, dev);
        return c;
    }();
    static bool attr_ok = []() {
        cudaFuncSetAttribute(edge_mma_kernel,
                             cudaFuncAttributeMaxDynamicSharedMemorySize, SMEM_E);
        cudaFuncSetAttribute(node_kernel,
                             cudaFuncAttributeMaxDynamicSharedMemorySize, SMEM_N);
        return true;
    }();
    (void)attr_ok;

    prep_kernel<<<2048, 256>>>();
    node_kernel<<<NNT, 256, SMEM_N>>>(h, W1, b1);
    edge_mma_kernel<<<sm_count, 512, SMEM_E>>>(src, dst, ea, W1, W2, b2);
    ln_kernel<<<(N_NODES * 32 + 255) / 256, 256>>>(h, gamma, beta, out);
}

// round 8
// speedup vs baseline: 7.4996x; 1.0036x over previous
#include <cuda_runtime.h>
#include <cuda_fp16.h>
#include <math.h>
#include <stdint.h>

#define N_NODES 50000
#define N_EDGES 1600000
#define NT      12500       // edge tiles of 128
#define NNT     391         // node tiles of 128

// ---- pitches (bytes)
#define PB2  272    // fp16 [128][k=128 pad]
#define PBEA 48     // fp16 [128][k=16 pad]
#define PD   528    // f32 staging [128][132 words]
#define PE1  272    // fp16 E1 staging

// ---- edge-kernel SMEM offsets
#define SM_W2    0           // 34816
#define SM_HDN   34816       // 34816
#define SM_D     69632       // 67584 (E1 fp16, then D f32 staging)
#define SM_E1    SM_D
#define SM_EA    137216      // 6144
#define SM_W1C   143360      // 6144
#define SM_B2    149504      // 512
#define SM_SIDX  150016      // 512
#define SM_DIDX  150528      // 512
#define SM_EIDX  151040      // 512
#define SMEM_E   151552

// ---- node-kernel SMEM offsets
#define NSM_X   0
#define NSM_B0  34816
#define NSM_B1  69632
#define NSM_OUT 104448
#define NSM_B1S 139264
#define SMEM_N  139776

__device__ float   g_agg[(size_t)N_NODES * 128];
__device__ __half  g_pq [(size_t)N_NODES * 256];
__device__ int     g_deg [N_NODES];
__device__ int     g_off [N_NODES];     // offsets, then cursors during fill
__device__ int     g_eidx[N_EDGES];     // edge ids sorted by dst

// ---------------------------------------------------------------- helpers
__device__ __forceinline__ uint32_t smem_u32(const void* p) {
    uint32_t a;
    asm("{ .reg .u64 t; cvta.to.shared.u64 t, %1; cvt.u32.u64 %0, t; }"
        : "=r"(a) : "l"(p));
    return a;
}
__device__ __forceinline__ void ldsm4(uint32_t* r, uint32_t addr) {
    asm volatile("ldmatrix.sync.aligned.m8n8.x4.shared.b16 {%0,%1,%2,%3}, [%4];"
                 : "=r"(r[0]), "=r"(r[1]), "=r"(r[2]), "=r"(r[3]) : "r"(addr));
}
__device__ __forceinline__ void mma16816(float* c, const uint32_t* a,
                                         const uint32_t* b) {
    asm volatile("mma.sync.aligned.m16n8k16.row.col.f32.f16.f16.f32 "
                 "{%0,%1,%2,%3}, {%4,%5,%6,%7}, {%8,%9}, {%0,%1,%2,%3};"
                 : "+f"(c[0]), "+f"(c[1]), "+f"(c[2]), "+f"(c[3])
                 : "r"(a[0]), "r"(a[1]), "r"(a[2]), "r"(a[3]),
                   "r"(b[0]), "r"(b[1]));
}
__device__ __forceinline__ uint32_t h2bits(float a, float b) {
    __half2 h = __floats2half2_rn(a, b);
    return *reinterpret_cast<uint32_t*>(&h);
}
// branchless exact-GELU: Abramowitz-Stegun 7.1.26 erf (abs err 1.5e-7)
__device__ __forceinline__ float gelu_fast(float v) {
    const float x = v * 0.70710678118654752440f;
    const float s = fabsf(x);
    const float t = __fdividef(1.0f, fmaf(0.3275911f, s, 1.0f));
    const float e = __expf(-s * s);
    float p = fmaf(t, 1.061405429f, -1.453152027f);
    p = fmaf(t, p, 1.421413741f);
    p = fmaf(t, p, -0.284496736f);
    p = fmaf(t, p, 0.254829592f);
    p = p * t;
    const float erfs = fmaf(-p, e, 1.0f);
    return 0.5f * v * (1.0f + copysignf(erfs, x));
}

template <int NCH>
__device__ __forceinline__ void gemm_pass42(float (&c)[2][8][4],
                                            uint32_t abase, uint32_t amstep,
                                            uint32_t bbase, uint32_t bnstep) {
    #pragma unroll
    for (int kc = 0; kc < NCH; ++kc) {
        uint32_t a[2][4], b[4][4];
        ldsm4(a[0], abase);
        ldsm4(a[1], abase + amstep);
        ldsm4(b[0], bbase);
        ldsm4(b[1], bbase + bnstep);
        ldsm4(b[2], bbase + 2 * bnstep);
        ldsm4(b[3], bbase + 3 * bnstep);
        #pragma unroll
        for (int mt = 0; mt < 2; ++mt)
            #pragma unroll
            for (int j = 0; j < 8; ++j)
                mma16816(c[mt][j], a[mt], &b[j >> 1][(j & 1) * 2]);
        abase += 32;
        bbase += 32;
    }
}
__device__ __forceinline__ void zero_c44(float (&c)[2][4][4]) {
    #pragma unroll
    for (int mt = 0; mt < 2; ++mt)
        #pragma unroll
        for (int j = 0; j < 4; ++j)
            #pragma unroll
            for (int i = 0; i < 4; ++i) c[mt][j][i] = 0.f;
}

// ---------------------------------------------------------------- CSR build
__global__ void prep_kernel() {      // zero agg + deg
    const int n = N_NODES * 128 / 4;
    for (int i = blockIdx.x * blockDim.x + threadIdx.x; i < n;
         i += gridDim.x * blockDim.x) {
        reinterpret_cast<float4*>(g_agg)[i] = make_float4(0.f, 0.f, 0.f, 0.f);
        if (i < N_NODES) g_deg[i] = 0;
    }
}
__global__ void hist_kernel(const int* __restrict__ dst) {
    int e = blockIdx.x * blockDim.x + threadIdx.x;
    if (e < N_EDGES) atomicAdd(&g_deg[dst[e]], 1);
}
__global__ __launch_bounds__(1024) void scan_kernel() {
    __shared__ int part[1024];
    const int t = threadIdx.x;
    const int start = t * 49;
    const int end   = (start + 49 < N_NODES) ? start + 49 : N_NODES;
    int s = 0;
    for (int i = start; i < end; ++i) s += g_deg[i];
    part[t] = s;
    __syncthreads();
    for (int o = 1; o < 1024; o <<= 1) {
        int v = (t >= o) ? part[t - o] : 0;
        __syncthreads();
        part[t] += v;
        __syncthreads();
    }
    int run = (t == 0) ? 0 : part[t - 1];
    for (int i = start; i < end; ++i) {
        int d = g_deg[i];
        g_off[i] = run;
        run += d;
    }
}
__global__ void fill_kernel(const int* __restrict__ dst) {
    int e = blockIdx.x * blockDim.x + threadIdx.x;
    if (e < N_EDGES) {
        int p = atomicAdd(&g_off[dst[e]], 1);
        g_eidx[p] = e;
    }
}

// ---------------------------------------------------------------- node kernel
__global__ __launch_bounds__(256, 1)
void node_kernel(const float* __restrict__ h,
                 const float* __restrict__ W1, const float* __restrict__ b1) {
    extern __shared__ char smbuf[];
    const uint32_t sb = smem_u32(smbuf);
    float* b1s = reinterpret_cast<float*>(smbuf + NSM_B1S);

    const int t = threadIdx.x, l = t & 31, warp = t >> 5;
    const int wm = warp & 3, wn = warp >> 2;
    const int grow = t & 127, ghf = t >> 7;

    for (int i = t; i < 128 * 128; i += 256) {
        int k = i >> 7, n = i & 127;
        *reinterpret_cast<__half*>(smbuf + NSM_B0 + n * PB2 + k * 2) =
            __float2half_rn(W1[k * 128 + n]);
        *reinterpret_cast<__half*>(smbuf + NSM_B1 + n * PB2 + k * 2) =
            __float2half_rn(W1[(k + 128) * 128 + n]);
    }
    if (t < 128) b1s[t] = b1[t];

    const uint32_t aoff = ((l & 7) + 8 * ((l >> 3) & 1)) * PB2 + (l >> 4) * 16;
    const uint32_t boff = ((l & 7) + 8 * (l >> 4)) * PB2 + ((l >> 3) & 1) * 16;
    const uint32_t aX  = sb + NSM_X + 32 * wm * PB2 + aoff;
    const uint32_t bB0 = sb + NSM_B0 + 64 * wn * PB2 + boff;
    const uint32_t bB1 = sb + NSM_B1 + 64 * wn * PB2 + boff;
    const int rbase = 32 * wm + (l >> 2);
    const int cbase = 64 * wn + 2 * (l & 3);

    const int node = blockIdx.x * 128 + grow;
    const int nc = node < N_NODES ? node : N_NODES - 1;

    {
        const float4* ps = reinterpret_cast<const float4*>(
            h + (size_t)nc * 128 + ghf * 64);
        char* xr = smbuf + NSM_X + grow * PB2 + ghf * 128;
        #pragma unroll
        for (int q = 0; q < 16; ++q) {
            float4 v = ps[q];
            *reinterpret_cast<uint2*>(xr + q * 8) =
                make_uint2(h2bits(v.x, v.y), h2bits(v.z, v.w));
        }
    }
    __syncthreads();

    #pragma unroll
    for (int pass = 0; pass < 2; ++pass) {
        float c[2][8][4];
        #pragma unroll
        for (int mt = 0; mt < 2; ++mt)
            #pragma unroll
            for (int j = 0; j < 8; ++j)
                #pragma unroll
                for (int i = 0; i < 4; ++i) c[mt][j][i] = 0.f;
        gemm_pass42<8>(c, aX, 16 * PB2, pass ? bB1 : bB0, 16 * PB2);
        #pragma unroll
        for (int mt = 0; mt < 2; ++mt)
            #pragma unroll
            for (int j = 0; j < 8; ++j) {
                const int col = cbase + 8 * j;
                const float bb0 = pass ? 0.f : b1s[col];
                const float bb1 = pass ? 0.f : b1s[col + 1];
                #pragma unroll
                for (int rh = 0; rh < 2; ++rh) {
                    const int row = rbase + 16 * mt + 8 * rh;
                    *reinterpret_cast<uint32_t*>(
                        smbuf + NSM_OUT + row * PB2 + col * 2) =
                        h2bits(c[mt][j][2 * rh] + bb0, c[mt][j][2 * rh + 1] + bb1);
                }
            }
        __syncthreads();
        if (node < N_NODES) {
            const uint4* os = reinterpret_cast<const uint4*>(
                smbuf + NSM_OUT + grow * PB2 + ghf * 128);
            uint4* po = reinterpret_cast<uint4*>(
                g_pq + (size_t)node * 256 + pass * 128 + ghf * 64);
            #pragma unroll
            for (int q = 0; q < 8; ++q) po[q] = os[q];
        }
        __syncthreads();
    }
}

// ---------------------------------------------------------------- edge kernel (512 thr)
__global__ __launch_bounds__(512, 1)
void edge_mma_kernel(const int*   __restrict__ src,
                     const int*   __restrict__ dst,
                     const float* __restrict__ ea,
                     const float* __restrict__ W1,
                     const float* __restrict__ W2,
                     const float* __restrict__ b2) {
    extern __shared__ char smbuf[];
    const uint32_t sb = smem_u32(smbuf);
    float* b2s = reinterpret_cast<float*>(smbuf + SM_B2);
    int* sidx  = reinterpret_cast<int*>(smbuf + SM_SIDX);
    int* didx  = reinterpret_cast<int*>(smbuf + SM_DIDX);
    int* eidxs = reinterpret_cast<int*>(smbuf + SM_EIDX);

    const int t = threadIdx.x, l = t & 31, warp = t >> 5;
    const int wm = warp & 3, wn = warp >> 2;
    const int grow = t & 127, gq = t >> 7;

    // ---- stage W2^T, W1c^T, b2 ----
    for (int i = t; i < 128 * 128; i += 512) {
        int k = i >> 7, n = i & 127;
        *reinterpret_cast<__half*>(smbuf + SM_W2 + n * PB2 + k * 2) =
            __float2half_rn(W2[i]);
    }
    for (int i = t; i < 16 * 128; i += 512) {
        int k = i >> 7, n = i & 127;
        *reinterpret_cast<__half*>(smbuf + SM_W1C + n * PBEA + k * 2) =
            __float2half_rn(W1[(k + 256) * 128 + n]);
    }
    if (t < 128) b2s[t] = b2[t];

    const uint32_t aoff272 = ((l & 7) + 8 * ((l >> 3) & 1)) * PB2 + (l >> 4) * 16;
    const uint32_t aoff48  = ((l & 7) + 8 * ((l >> 3) & 1)) * PBEA + (l >> 4) * 16;
    const uint32_t boff272 = ((l & 7) + 8 * (l >> 4)) * PB2 + ((l >> 3) & 1) * 16;
    const uint32_t boff48  = ((l & 7) + 8 * (l >> 4)) * PBEA + ((l >> 3) & 1) * 16;

    const uint32_t aEA  = sb + SM_EA  + 32 * wm * PBEA + aoff48;
    const uint32_t aHDN = sb + SM_HDN + 32 * wm * PB2 + aoff272;
    const uint32_t bW1C = sb + SM_W1C + 32 * wn * PBEA + boff48;
    const uint32_t bW2  = sb + SM_W2  + 32 * wn * PB2 + boff272;
    const int rbase = 32 * wm + (l >> 2);
    const int cbase = 32 * wn + 2 * (l & 3);

    __syncthreads();

    // preload all W2 B-fragments for this warp's 32 columns
    uint32_t bw[8][8];
    #pragma unroll
    for (int kc = 0; kc < 8; ++kc) {
        ldsm4(&bw[kc][0], bW2 + kc * 32);
        ldsm4(&bw[kc][4], bW2 + kc * 32 + 16 * PB2);
    }

    for (int tile = blockIdx.x; tile < NT; tile += gridDim.x) {
        const int e0 = tile << 7;
        __syncthreads();                       // prev tile fully consumed
        if (t < 128) {
            const int e = g_eidx[e0 + t];      // dst-sorted permutation
            eidxs[t] = e;
            sidx[t]  = src[e];
            didx[t]  = dst[e];
        }
        __syncthreads();

        // ---- gather EA (permuted) -> SMEM fp16 ----
        {
            const int ee = t >> 2, qq = t & 3;
            float4 v = reinterpret_cast<const float4*>(
                ea + (size_t)eidxs[ee] * 16)[qq];
            *reinterpret_cast<uint2*>(smbuf + SM_EA + ee * PBEA + qq * 8) =
                make_uint2(h2bits(v.x, v.y), h2bits(v.z, v.w));
        }
        __syncthreads();

        // ---- E1 = ea @ W1c^T (K=16), stage fp16 ----
        float c[2][4][4];
        zero_c44(c);
        {
            uint32_t a[2][4], bE1[8];
            ldsm4(&bE1[0], bW1C);
            ldsm4(&bE1[4], bW1C + 16 * PBEA);
            ldsm4(a[0], aEA);
            ldsm4(a[1], aEA + 16 * PBEA);
            #pragma unroll
            for (int mt = 0; mt < 2; ++mt)
                #pragma unroll
                for (int j = 0; j < 4; ++j)
                    mma16816(c[mt][j], a[mt], &bE1[(j >> 1) * 4 + (j & 1) * 2]);
        }
        #pragma unroll
        for (int mt = 0; mt < 2; ++mt)
            #pragma unroll
            for (int j = 0; j < 4; ++j) {
                const int col = cbase + 8 * j;
                #pragma unroll
                for (int rh = 0; rh < 2; ++rh) {
                    const int row = rbase + 16 * mt + 8 * rh;
                    *reinterpret_cast<uint32_t*>(
                        smbuf + SM_E1 + row * PE1 + col * 2) =
                        h2bits(c[mt][j][2 * rh], c[mt][j][2 * rh + 1]);
                }
            }
        __syncthreads();

        // ---- hdn = gelu(P[src] + Q[dst] + E1) ----
        {
            const uint4* pp = reinterpret_cast<const uint4*>(
                g_pq + (size_t)sidx[grow] * 256 + gq * 32);
            const uint4* qq = reinterpret_cast<const uint4*>(
                g_pq + (size_t)didx[grow] * 256 + 128 + gq * 32);
            const uint4* e1 = reinterpret_cast<const uint4*>(
                smbuf + SM_E1 + grow * PE1 + gq * 64);
            char* hr = smbuf + SM_HDN + grow * PB2 + gq * 64;
            #pragma unroll
            for (int q = 0; q < 4; ++q) {
                const uint4 pv = pp[q];
                const uint4 qv = qq[q];
                const uint4 ev = e1[q];
                const __half2* ph = reinterpret_cast<const __half2*>(&pv);
                const __half2* qh = reinterpret_cast<const __half2*>(&qv);
                const __half2* eh = reinterpret_cast<const __half2*>(&ev);
                uint4 o;
                uint32_t* op = reinterpret_cast<uint32_t*>(&o);
                #pragma unroll
                for (int w = 0; w < 4; ++w) {
                    float2 pf = __half22float2(ph[w]);
                    float2 qf = __half22float2(qh[w]);
                    float2 ef = __half22float2(eh[w]);
                    op[w] = h2bits(gelu_fast(pf.x + qf.x + ef.x),
                                   gelu_fast(pf.y + qf.y + ef.y));
                }
                *reinterpret_cast<uint4*>(hr + q * 16) = o;
            }
        }
        __syncthreads();

        // ---- GEMM2: D = hdn @ W2^T (B in registers) ----
        zero_c44(c);
        {
            uint32_t abase = aHDN;
            #pragma unroll
            for (int kc = 0; kc < 8; ++kc) {
                uint32_t a[2][4];
                ldsm4(a[0], abase);
                ldsm4(a[1], abase + 16 * PB2);
                #pragma unroll
                for (int mt = 0; mt < 2; ++mt)
                    #pragma unroll
                    for (int j = 0; j < 4; ++j)
                        mma16816(c[mt][j], a[mt],
                                 &bw[kc][(j >> 1) * 4 + (j & 1) * 2]);
                abase += 32;
            }
        }

        // ---- +b2, stage D f32 ----
        #pragma unroll
        for (int mt = 0; mt < 2; ++mt)
            #pragma unroll
            for (int j = 0; j < 4; ++j) {
                const int col = cbase + 8 * j;
                const float bb0 = b2s[col], bb1 = b2s[col + 1];
                #pragma unroll
                for (int rh = 0; rh < 2; ++rh) {
                    const int row = rbase + 16 * mt + 8 * rh;
                    *reinterpret_cast<float2*>(
                        smbuf + SM_D + row * PD + col * 4) =
                        make_float2(c[mt][j][2 * rh] + bb0,
                                    c[mt][j][2 * rh + 1] + bb1);
                }
            }
        __syncthreads();

        // ---- segmented column reduction over dst runs, sparse red.f32 ----
        {
            const int col = t & 127;
            const int base = (t >> 7) * 32;
            const float* Dp = reinterpret_cast<const float*>(smbuf + SM_D) + col;
            float acc = 0.f;
            #pragma unroll 8
            for (int r = 0; r < 32; ++r) {
                const int row = base + r;
                acc += Dp[row * (PD / 4)];
                const bool flush =
                    (r == 31) || (row == 127) || (didx[row] != didx[row + 1]);
                if (flush) {
                    asm volatile("red.global.add.f32 [%0], %1;"
                                 :: "l"(g_agg + (size_t)didx[row] * 128 + col),
                                    "f"(acc) : "memory");
                    acc = 0.f;
                }
            }
        }
    }
}

// ---------------------------------------------------------------- LayerNorm
__global__ __launch_bounds__(256)
void ln_kernel(const float* __restrict__ h,
               const float* __restrict__ gamma,
               const float* __restrict__ beta,
               float* __restrict__ out) {
    const int row  = (blockIdx.x * blockDim.x + threadIdx.x) >> 5;
    const int lane = threadIdx.x & 31;
    if (row >= N_NODES) return;

    const float4 hv = reinterpret_cast<const float4*>(h)[(size_t)row * 32 + lane];
    const float4 av = reinterpret_cast<const float4*>(g_agg)[(size_t)row * 32 + lane];
    float4 x;
    x.x = hv.x + av.x; x.y = hv.y + av.y; x.z = hv.z + av.z; x.w = hv.w + av.w;

    float s = x.x + x.y + x.z + x.w;
    #pragma unroll
    for (int o = 16; o > 0; o >>= 1) s += __shfl_xor_sync(0xffffffffu, s, o);
    const float mu = s * (1.0f / 128.0f);

    const float dx = x.x - mu, dy = x.y - mu, dz = x.z - mu, dw = x.w - mu;
    float q = dx * dx + dy * dy + dz * dz + dw * dw;
    #pragma unroll
    for (int o = 16; o > 0; o >>= 1) q += __shfl_xor_sync(0xffffffffu, q, o);
    const float inv = rsqrtf(q * (1.0f / 128.0f) + 1e-5f);

    const float4 g = reinterpret_cast<const float4*>(gamma)[lane];
    const float4 b = reinterpret_cast<const float4*>(beta)[lane];
    float4 o4;
    o4.x = dx * inv * g.x + b.x;
    o4.y = dy * inv * g.y + b.y;
    o4.z = dz * inv * g.z + b.z;
    o4.w = dw * inv * g.w + b.w;
    reinterpret_cast<float4*>(out)[(size_t)row * 32 + lane] = o4;
}

// ----------------------------------------------------------------
extern "C" void kernel_launch(void* const* d_in, const int* in_sizes, int n_in,
                              void* d_out, int out_size) {
    const float* h     = (const float*)d_in[0];
    const int*   src   = (const int*)  d_in[1];
    const int*   dst   = (const int*)  d_in[2];
    const float* ea    = (const float*)d_in[3];
    const float* W1    = (const float*)d_in[4];
    const float* b1    = (const float*)d_in[5];
    const float* W2    = (const float*)d_in[6];
    const float* b2    = (const float*)d_in[7];
    const float* gamma = (const float*)d_in[8];
    const float* beta  = (const float*)d_in[9];
    float*       out   = (float*)d_out;

    static int sm_count = []() {
        int dev = 0, c = 148;
        cudaGetDevice(&dev);
        cudaDeviceGetAttribute(&c, cudaDevAttrMultiProcessorCount, dev);
        return c;
    }();
    static bool attr_ok = []() {
        cudaFuncSetAttribute(edge_mma_kernel,
                             cudaFuncAttributeMaxDynamicSharedMemorySize, SMEM_E);
        cudaFuncSetAttribute(node_kernel,
                             cudaFuncAttributeMaxDynamicSharedMemorySize, SMEM_N);
        return true;
    }();
    (void)attr_ok;

    prep_kernel<<<2048, 256>>>();
    hist_kernel<<<(N_EDGES + 255) / 256, 256>>>(dst);
    scan_kernel<<<1, 1024>>>();
    fill_kernel<<<(N_EDGES + 255) / 256, 256>>>(dst);
    node_kernel<<<NNT, 256, SMEM_N>>>(h, W1, b1);
    edge_mma_kernel<<<sm_count, 512, SMEM_E>>>(src, dst, ea, W1, W2, b2);
    ln_kernel<<<(N_NODES * 32 + 255) / 256, 256>>>(h, gamma, beta, out);
}

// round 9
// speedup vs baseline: 11.4302x; 1.5241x over previous
#include <cuda_runtime.h>
#include <cuda_fp16.h>
#include <math.h>
#include <stdint.h>

#define N_NODES 50000
#define N_EDGES 1600000
#define NT      12500       // edge tiles of 128
#define NNT     391         // node tiles of 128

// ---- pitches
#define PB2  272    // fp16 [128][k=128 pad] (ldmatrix layout)
#define PBEA 48     // fp16 [128][k=16 pad]
#define PD   528    // f32 staging [128][132 words]

// ---- edge-kernel SMEM offsets (bytes)
#define SM_D     0           // 67584 : E1 f32, then hdn f32
#define SM_EA    67584       // 6144
#define SM_W1C   73728       // 6144
#define SM_SIDX  79872       // 512
#define SM_DIDX  80384       // 512
#define SM_EIDX  80896       // 512
#define SMEM_E   81408

// ---- node1 (P/Q) SMEM offsets
#define NSM_X   0
#define NSM_B0  34816
#define NSM_B1  69632
#define NSM_OUT 104448
#define NSM_B1S 139264
#define SMEM_N  139776

// ---- node2 (GEMM2+LN) SMEM offsets
#define N2_W2   0            // 34816
#define N2_X    34816        // 34816
#define N2_OUT  69632        // 67584 f32 [128][132]
#define N2_B2   137216       // 512
#define N2_GAM  137728       // 512
#define N2_BET  138240       // 512
#define N2_DEG  138752       // 512
#define SMEM_N2 139264

__device__ float   g_hsum[(size_t)N_NODES * 128];
__device__ __half  g_pq [(size_t)N_NODES * 256];  // [0:128]=P=h@W1a+b1, [128:256]=Q=h@W1b
__device__ int     g_deg [N_NODES];
__device__ int     g_off [N_NODES];
__device__ int     g_eidx[N_EDGES];

// ---------------------------------------------------------------- helpers
__device__ __forceinline__ uint32_t smem_u32(const void* p) {
    uint32_t a;
    asm("{ .reg .u64 t; cvta.to.shared.u64 t, %1; cvt.u32.u64 %0, t; }"
        : "=r"(a) : "l"(p));
    return a;
}
__device__ __forceinline__ void ldsm4(uint32_t* r, uint32_t addr) {
    asm volatile("ldmatrix.sync.aligned.m8n8.x4.shared.b16 {%0,%1,%2,%3}, [%4];"
                 : "=r"(r[0]), "=r"(r[1]), "=r"(r[2]), "=r"(r[3]) : "r"(addr));
}
__device__ __forceinline__ void mma16816(float* c, const uint32_t* a,
                                         const uint32_t* b) {
    asm volatile("mma.sync.aligned.m16n8k16.row.col.f32.f16.f16.f32 "
                 "{%0,%1,%2,%3}, {%4,%5,%6,%7}, {%8,%9}, {%0,%1,%2,%3};"
                 : "+f"(c[0]), "+f"(c[1]), "+f"(c[2]), "+f"(c[3])
                 : "r"(a[0]), "r"(a[1]), "r"(a[2]), "r"(a[3]),
                   "r"(b[0]), "r"(b[1]));
}
__device__ __forceinline__ uint32_t h2bits(float a, float b) {
    __half2 h = __floats2half2_rn(a, b);
    return *reinterpret_cast<uint32_t*>(&h);
}
// branchless exact-GELU: Abramowitz-Stegun 7.1.26 erf (abs err 1.5e-7)
__device__ __forceinline__ float gelu_fast(float v) {
    const float x = v * 0.70710678118654752440f;
    const float s = fabsf(x);
    const float t = __fdividef(1.0f, fmaf(0.3275911f, s, 1.0f));
    const float e = __expf(-s * s);
    float p = fmaf(t, 1.061405429f, -1.453152027f);
    p = fmaf(t, p, 1.421413741f);
    p = fmaf(t, p, -0.284496736f);
    p = fmaf(t, p, 0.254829592f);
    p = p * t;
    const float erfs = fmaf(-p, e, 1.0f);
    return 0.5f * v * (1.0f + copysignf(erfs, x));
}

template <int NCH>
__device__ __forceinline__ void gemm_pass42(float (&c)[2][8][4],
                                            uint32_t abase, uint32_t amstep,
                                            uint32_t bbase, uint32_t bnstep) {
    #pragma unroll
    for (int kc = 0; kc < NCH; ++kc) {
        uint32_t a[2][4], b[4][4];
        ldsm4(a[0], abase);
        ldsm4(a[1], abase + amstep);
        ldsm4(b[0], bbase);
        ldsm4(b[1], bbase + bnstep);
        ldsm4(b[2], bbase + 2 * bnstep);
        ldsm4(b[3], bbase + 3 * bnstep);
        #pragma unroll
        for (int mt = 0; mt < 2; ++mt)
            #pragma unroll
            for (int j = 0; j < 8; ++j)
                mma16816(c[mt][j], a[mt], &b[j >> 1][(j & 1) * 2]);
        abase += 32;
        bbase += 32;
    }
}

// ---------------------------------------------------------------- CSR build
__global__ void prep_kernel() {      // zero hsum + deg
    const int n = N_NODES * 128 / 4;
    for (int i = blockIdx.x * blockDim.x + threadIdx.x; i < n;
         i += gridDim.x * blockDim.x) {
        reinterpret_cast<float4*>(g_hsum)[i] = make_float4(0.f, 0.f, 0.f, 0.f);
        if (i < N_NODES) g_deg[i] = 0;
    }
}
__global__ void hist_kernel(const int* __restrict__ dst) {
    int e = blockIdx.x * blockDim.x + threadIdx.x;
    if (e < N_EDGES) atomicAdd(&g_deg[dst[e]], 1);
}
__global__ __launch_bounds__(1024) void scan_kernel() {
    __shared__ int part[1024];
    const int t = threadIdx.x;
    const int start = t * 49;
    const int end   = (start + 49 < N_NODES) ? start + 49 : N_NODES;
    int s = 0;
    for (int i = start; i < end; ++i) s += g_deg[i];
    part[t] = s;
    __syncthreads();
    for (int o = 1; o < 1024; o <<= 1) {
        int v = (t >= o) ? part[t - o] : 0;
        __syncthreads();
        part[t] += v;
        __syncthreads();
    }
    int run = (t == 0) ? 0 : part[t - 1];
    for (int i = start; i < end; ++i) {
        int d = g_deg[i];
        g_off[i] = run;
        run += d;
    }
}
__global__ void fill_kernel(const int* __restrict__ dst) {
    int e = blockIdx.x * blockDim.x + threadIdx.x;
    if (e < N_EDGES) {
        int p = atomicAdd(&g_off[dst[e]], 1);
        g_eidx[p] = e;
    }
}

// ---------------------------------------------------------------- node1: P,Q
__global__ __launch_bounds__(256, 1)
void node_kernel(const float* __restrict__ h,
                 const float* __restrict__ W1, const float* __restrict__ b1) {
    extern __shared__ char smbuf[];
    const uint32_t sb = smem_u32(smbuf);
    float* b1s = reinterpret_cast<float*>(smbuf + NSM_B1S);

    const int t = threadIdx.x, l = t & 31, warp = t >> 5;
    const int wm = warp & 3, wn = warp >> 2;
    const int grow = t & 127, ghf = t >> 7;

    for (int i = t; i < 128 * 128; i += 256) {
        int k = i >> 7, n = i & 127;
        *reinterpret_cast<__half*>(smbuf + NSM_B0 + n * PB2 + k * 2) =
            __float2half_rn(W1[k * 128 + n]);
        *reinterpret_cast<__half*>(smbuf + NSM_B1 + n * PB2 + k * 2) =
            __float2half_rn(W1[(k + 128) * 128 + n]);
    }
    if (t < 128) b1s[t] = b1[t];

    const uint32_t aoff = ((l & 7) + 8 * ((l >> 3) & 1)) * PB2 + (l >> 4) * 16;
    const uint32_t boff = ((l & 7) + 8 * (l >> 4)) * PB2 + ((l >> 3) & 1) * 16;
    const uint32_t aX  = sb + NSM_X + 32 * wm * PB2 + aoff;
    const uint32_t bB0 = sb + NSM_B0 + 64 * wn * PB2 + boff;
    const uint32_t bB1 = sb + NSM_B1 + 64 * wn * PB2 + boff;
    const int rbase = 32 * wm + (l >> 2);
    const int cbase = 64 * wn + 2 * (l & 3);

    const int node = blockIdx.x * 128 + grow;
    const int nc = node < N_NODES ? node : N_NODES - 1;

    {
        const float4* ps = reinterpret_cast<const float4*>(
            h + (size_t)nc * 128 + ghf * 64);
        char* xr = smbuf + NSM_X + grow * PB2 + ghf * 128;
        #pragma unroll
        for (int q = 0; q < 16; ++q) {
            float4 v = ps[q];
            *reinterpret_cast<uint2*>(xr + q * 8) =
                make_uint2(h2bits(v.x, v.y), h2bits(v.z, v.w));
        }
    }
    __syncthreads();

    #pragma unroll
    for (int pass = 0; pass < 2; ++pass) {
        float c[2][8][4];
        #pragma unroll
        for (int mt = 0; mt < 2; ++mt)
            #pragma unroll
            for (int j = 0; j < 8; ++j)
                #pragma unroll
                for (int i = 0; i < 4; ++i) c[mt][j][i] = 0.f;
        gemm_pass42<8>(c, aX, 16 * PB2, pass ? bB1 : bB0, 16 * PB2);
        #pragma unroll
        for (int mt = 0; mt < 2; ++mt)
            #pragma unroll
            for (int j = 0; j < 8; ++j) {
                const int col = cbase + 8 * j;
                const float bb0 = pass ? 0.f : b1s[col];
                const float bb1 = pass ? 0.f : b1s[col + 1];
                #pragma unroll
                for (int rh = 0; rh < 2; ++rh) {
                    const int row = rbase + 16 * mt + 8 * rh;
                    *reinterpret_cast<uint32_t*>(
                        smbuf + NSM_OUT + row * PB2 + col * 2) =
                        h2bits(c[mt][j][2 * rh] + bb0, c[mt][j][2 * rh + 1] + bb1);
                }
            }
        __syncthreads();
        if (node < N_NODES) {
            const uint4* os = reinterpret_cast<const uint4*>(
                smbuf + NSM_OUT + grow * PB2 + ghf * 128);
            uint4* po = reinterpret_cast<uint4*>(
                g_pq + (size_t)node * 256 + pass * 128 + ghf * 64);
            #pragma unroll
            for (int q = 0; q < 8; ++q) po[q] = os[q];
        }
        __syncthreads();
    }
}

// ---------------------------------------------------------------- edge kernel
__global__ __launch_bounds__(512, 2)
void edge_mma_kernel(const int*   __restrict__ src,
                     const int*   __restrict__ dst,
                     const float* __restrict__ ea,
                     const float* __restrict__ W1) {
    extern __shared__ char smbuf[];
    const uint32_t sb = smem_u32(smbuf);
    int* sidx  = reinterpret_cast<int*>(smbuf + SM_SIDX);
    int* didx  = reinterpret_cast<int*>(smbuf + SM_DIDX);
    int* eidxs = reinterpret_cast<int*>(smbuf + SM_EIDX);

    const int t = threadIdx.x, l = t & 31, warp = t >> 5;
    const int wm = warp & 3, wn = warp >> 2;       // 4x4 warp grid (E1 MMA)
    const int grow = t >> 2, q4 = t & 3;           // gather mapping: 4 thr/row

    // ---- stage W1c^T (fp16) ----
    for (int i = t; i < 16 * 128; i += 512) {
        int k = i >> 7, n = i & 127;
        *reinterpret_cast<__half*>(smbuf + SM_W1C + n * PBEA + k * 2) =
            __float2half_rn(W1[(k + 256) * 128 + n]);
    }

    const uint32_t aoff48 = ((l & 7) + 8 * ((l >> 3) & 1)) * PBEA + (l >> 4) * 16;
    const uint32_t boff48 = ((l & 7) + 8 * (l >> 4)) * PBEA + ((l >> 3) & 1) * 16;
    const uint32_t aEA  = sb + SM_EA  + 32 * wm * PBEA + aoff48;
    const uint32_t bW1C = sb + SM_W1C + 32 * wn * PBEA + boff48;
    const int rbase = 32 * wm + (l >> 2);
    const int cbase = 32 * wn + 2 * (l & 3);

    __syncthreads();

    // preload W1c B-fragments (constant over tiles)
    uint32_t bE1[8];
    ldsm4(&bE1[0], bW1C);
    ldsm4(&bE1[4], bW1C + 16 * PBEA);

    for (int tile = blockIdx.x; tile < NT; tile += gridDim.x) {
        const int e0 = tile << 7;
        __syncthreads();                      // prev tile SM_D / idx consumed
        if (t < 128) {
            const int e = g_eidx[e0 + t];     // dst-sorted permutation
            eidxs[t] = e;
            sidx[t]  = src[e];
            didx[t]  = dst[e];
        }
        __syncthreads();

        // ---- gather EA (coalesced 4 thr/row) -> SMEM fp16 ----
        {
            float4 v = reinterpret_cast<const float4*>(
                ea + (size_t)eidxs[grow] * 16)[q4];
            *reinterpret_cast<uint2*>(smbuf + SM_EA + grow * PBEA + q4 * 8) =
                make_uint2(h2bits(v.x, v.y), h2bits(v.z, v.w));
        }
        __syncthreads();

        // ---- E1 = ea @ W1c^T (K=16), stage f32 into SM_D ----
        {
            float c[2][4][4];
            #pragma unroll
            for (int mt = 0; mt < 2; ++mt)
                #pragma unroll
                for (int j = 0; j < 4; ++j)
                    #pragma unroll
                    for (int i = 0; i < 4; ++i) c[mt][j][i] = 0.f;
            uint32_t a[2][4];
            ldsm4(a[0], aEA);
            ldsm4(a[1], aEA + 16 * PBEA);
            #pragma unroll
            for (int mt = 0; mt < 2; ++mt)
                #pragma unroll
                for (int j = 0; j < 4; ++j)
                    mma16816(c[mt][j], a[mt], &bE1[(j >> 1) * 4 + (j & 1) * 2]);
            #pragma unroll
            for (int mt = 0; mt < 2; ++mt)
                #pragma unroll
                for (int j = 0; j < 4; ++j) {
                    const int col = cbase + 8 * j;
                    #pragma unroll
                    for (int rh = 0; rh < 2; ++rh) {
                        const int row = rbase + 16 * mt + 8 * rh;
                        *reinterpret_cast<float2*>(
                            smbuf + SM_D + row * PD + col * 4) =
                            make_float2(c[mt][j][2 * rh], c[mt][j][2 * rh + 1]);
                    }
                }
        }
        __syncthreads();

        // ---- hdn = gelu(P[src] + Q[dst] + E1), f32 in-place in SM_D ----
        {
            const uint4* pb = reinterpret_cast<const uint4*>(g_pq) +
                              (size_t)sidx[grow] * 32 + q4;
            const uint4* qb = reinterpret_cast<const uint4*>(g_pq) +
                              (size_t)didx[grow] * 32 + 16 + q4;
            char* db = smbuf + SM_D + grow * PD + q4 * 32;
            #pragma unroll
            for (int pass = 0; pass < 4; ++pass) {
                const uint4 pv = pb[pass * 4];
                const uint4 qv = qb[pass * 4];
                float4 e0v = *reinterpret_cast<float4*>(db + pass * 128);
                float4 e1v = *reinterpret_cast<float4*>(db + pass * 128 + 16);
                const __half2* ph = reinterpret_cast<const __half2*>(&pv);
                const __half2* qh = reinterpret_cast<const __half2*>(&qv);
                float2 p0 = __half22float2(ph[0]), Q0 = __half22float2(qh[0]);
                float2 p1 = __half22float2(ph[1]), Q1 = __half22float2(qh[1]);
                float2 p2 = __half22float2(ph[2]), Q2 = __half22float2(qh[2]);
                float2 p3 = __half22float2(ph[3]), Q3 = __half22float2(qh[3]);
                float4 o0, o1;
                o0.x = gelu_fast(p0.x + Q0.x + e0v.x);
                o0.y = gelu_fast(p0.y + Q0.y + e0v.y);
                o0.z = gelu_fast(p1.x + Q1.x + e0v.z);
                o0.w = gelu_fast(p1.y + Q1.y + e0v.w);
                o1.x = gelu_fast(p2.x + Q2.x + e1v.x);
                o1.y = gelu_fast(p2.y + Q2.y + e1v.y);
                o1.z = gelu_fast(p3.x + Q3.x + e1v.z);
                o1.w = gelu_fast(p3.y + Q3.y + e1v.w);
                *reinterpret_cast<float4*>(db + pass * 128) = o0;
                *reinterpret_cast<float4*>(db + pass * 128 + 16) = o1;
            }
        }
        __syncthreads();

        // ---- segmented column reduction over dst runs -> g_hsum ----
        {
            const int col = t & 127;
            const int base = (t >> 7) * 32;
            const float* Dp = reinterpret_cast<const float*>(smbuf + SM_D) + col;
            float acc = 0.f;
            #pragma unroll 8
            for (int r = 0; r < 32; ++r) {
                const int row = base + r;
                acc += Dp[row * (PD / 4)];
                const bool flush =
                    (r == 31) || (row == 127) || (didx[row] != didx[row + 1]);
                if (flush) {
                    asm volatile("red.global.add.f32 [%0], %1;"
                                 :: "l"(g_hsum + (size_t)didx[row] * 128 + col),
                                    "f"(acc) : "memory");
                    acc = 0.f;
                }
            }
        }
    }
}

// ---------------------------------------------------------------- node2:
// out = LayerNorm(h + hsum @ W2 + deg*b2)
__global__ __launch_bounds__(256, 1)
void node2_kernel(const float* __restrict__ h,
                  const float* __restrict__ W2,
                  const float* __restrict__ b2,
                  const float* __restrict__ gamma,
                  const float* __restrict__ beta,
                  float* __restrict__ out) {
    extern __shared__ char smbuf[];
    const uint32_t sb = smem_u32(smbuf);
    float* b2s = reinterpret_cast<float*>(smbuf + N2_B2);
    float* gms = reinterpret_cast<float*>(smbuf + N2_GAM);
    float* bts = reinterpret_cast<float*>(smbuf + N2_BET);
    int*   dgs = reinterpret_cast<int*>(smbuf + N2_DEG);
    float* outs = reinterpret_cast<float*>(smbuf + N2_OUT);

    const int t = threadIdx.x, l = t & 31, warp = t >> 5;
    const int wm = warp & 3, wn = warp >> 2;
    const int grow = t & 127, ghf = t >> 7;

    for (int i = t; i < 128 * 128; i += 256) {
        int k = i >> 7, n = i & 127;
        *reinterpret_cast<__half*>(smbuf + N2_W2 + n * PB2 + k * 2) =
            __float2half_rn(W2[i]);
    }
    if (t < 128) { b2s[t] = b2[t]; gms[t] = gamma[t]; bts[t] = beta[t]; }

    const int node = blockIdx.x * 128 + grow;
    const int nc = node < N_NODES ? node : N_NODES - 1;
    if (t >= 128 && t < 256) {
        int nn = blockIdx.x * 128 + (t - 128);
        dgs[t - 128] = (nn < N_NODES) ? g_deg[nn] : 0;
    }

    // stage X = fp16(hsum[node tile])
    {
        const float4* ps = reinterpret_cast<const float4*>(
            g_hsum + (size_t)nc * 128 + ghf * 64);
        char* xr = smbuf + N2_X + grow * PB2 + ghf * 128;
        #pragma unroll
        for (int q = 0; q < 16; ++q) {
            float4 v = ps[q];
            *reinterpret_cast<uint2*>(xr + q * 8) =
                make_uint2(h2bits(v.x, v.y), h2bits(v.z, v.w));
        }
    }
    __syncthreads();

    const uint32_t aoff = ((l & 7) + 8 * ((l >> 3) & 1)) * PB2 + (l >> 4) * 16;
    const uint32_t boff = ((l & 7) + 8 * (l >> 4)) * PB2 + ((l >> 3) & 1) * 16;
    const uint32_t aX = sb + N2_X + 32 * wm * PB2 + aoff;
    const uint32_t bW = sb + N2_W2 + 64 * wn * PB2 + boff;
    const int rbase = 32 * wm + (l >> 2);
    const int cbase = 64 * wn + 2 * (l & 3);

    float c[2][8][4];
    #pragma unroll
    for (int mt = 0; mt < 2; ++mt)
        #pragma unroll
        for (int j = 0; j < 8; ++j)
            #pragma unroll
            for (int i = 0; i < 4; ++i) c[mt][j][i] = 0.f;
    gemm_pass42<8>(c, aX, 16 * PB2, bW, 16 * PB2);

    // epilogue: + deg*b2 -> stage f32
    #pragma unroll
    for (int mt = 0; mt < 2; ++mt)
        #pragma unroll
        for (int j = 0; j < 8; ++j) {
            const int col = cbase + 8 * j;
            const float bb0 = b2s[col], bb1 = b2s[col + 1];
            #pragma unroll
            for (int rh = 0; rh < 2; ++rh) {
                const int row = rbase + 16 * mt + 8 * rh;
                const float dg = (float)dgs[row];
                outs[row * 132 + col]     = c[mt][j][2 * rh] + dg * bb0;
                outs[row * 132 + col + 1] = c[mt][j][2 * rh + 1] + dg * bb1;
            }
        }
    __syncthreads();

    // LayerNorm: each warp does 16 rows; lane covers 4 cols
    for (int r = 0; r < 16; ++r) {
        const int row = warp * 16 + r;
        const int nn = blockIdx.x * 128 + row;
        if (nn >= N_NODES) break;
        const float4 hv = reinterpret_cast<const float4*>(h)[(size_t)nn * 32 + l];
        const float4 av = *reinterpret_cast<const float4*>(outs + row * 132 + l * 4);
        float4 x;
        x.x = hv.x + av.x; x.y = hv.y + av.y;
        x.z = hv.z + av.z; x.w = hv.w + av.w;
        float s = x.x + x.y + x.z + x.w;
        #pragma unroll
        for (int o = 16; o > 0; o >>= 1) s += __shfl_xor_sync(0xffffffffu, s, o);
        const float mu = s * (1.0f / 128.0f);
        const float dx = x.x - mu, dy = x.y - mu, dz = x.z - mu, dw = x.w - mu;
        float q = dx * dx + dy * dy + dz * dz + dw * dw;
        #pragma unroll
        for (int o = 16; o > 0; o >>= 1) q += __shfl_xor_sync(0xffffffffu, q, o);
        const float inv = rsqrtf(q * (1.0f / 128.0f) + 1e-5f);
        float4 o4;
        o4.x = dx * inv * gms[l * 4 + 0] + bts[l * 4 + 0];
        o4.y = dy * inv * gms[l * 4 + 1] + bts[l * 4 + 1];
        o4.z = dz * inv * gms[l * 4 + 2] + bts[l * 4 + 2];
        o4.w = dw * inv * gms[l * 4 + 3] + bts[l * 4 + 3];
        reinterpret_cast<float4*>(out)[(size_t)nn * 32 + l] = o4;
    }
}

// ----------------------------------------------------------------
extern "C" void kernel_launch(void* const* d_in, const int* in_sizes, int n_in,
                              void* d_out, int out_size) {
    const float* h     = (const float*)d_in[0];
    const int*   src   = (const int*)  d_in[1];
    const int*   dst   = (const int*)  d_in[2];
    const float* ea    = (const float*)d_in[3];
    const float* W1    = (const float*)d_in[4];
    const float* b1    = (const float*)d_in[5];
    const float* W2    = (const float*)d_in[6];
    const float* b2    = (const float*)d_in[7];
    const float* gamma = (const float*)d_in[8];
    const float* beta  = (const float*)d_in[9];
    float*       out   = (float*)d_out;

    static int sm_count = []() {
        int dev = 0, c = 148;
        cudaGetDevice(&dev);
        cudaDeviceGetAttribute(&c, cudaDevAttrMultiProcessorCount, dev);
        return c;
    }();
    static bool attr_ok = []() {
        cudaFuncSetAttribute(edge_mma_kernel,
                             cudaFuncAttributeMaxDynamicSharedMemorySize, SMEM_E);
        cudaFuncSetAttribute(node_kernel,
                             cudaFuncAttributeMaxDynamicSharedMemorySize, SMEM_N);
        cudaFuncSetAttribute(node2_kernel,
                             cudaFuncAttributeMaxDynamicSharedMemorySize, SMEM_N2);
        return true;
    }();
    (void)attr_ok;

    prep_kernel<<<2048, 256>>>();
    hist_kernel<<<(N_EDGES + 255) / 256, 256>>>(dst);
    scan_kernel<<<1, 1024>>>();
    fill_kernel<<<(N_EDGES + 255) / 256, 256>>>(dst);
    node_kernel<<<NNT, 256, SMEM_N>>>(h, W1, b1);
    edge_mma_kernel<<<2 * sm_count, 512, SMEM_E>>>(src, dst, ea, W1);
    node2_kernel<<<NNT, 256, SMEM_N2>>>(h, W2, b2, gamma, beta, out);
}

// round 10
// speedup vs baseline: 12.5736x; 1.1000x over previous
#include <cuda_runtime.h>
#include <cuda_fp16.h>
#include <math.h>
#include <stdint.h>

#define N_NODES 50000
#define N_EDGES 1600000
#define NT      6250        // edge tiles of 256
#define NNT     391         // node tiles of 128

// ---- pitches
#define PB2  272    // fp16 [.][k=128 pad] (ldmatrix layout / hdn pitch)
#define PBEA 48     // fp16 [.][k=16 pad]

// ---- edge-kernel SMEM offsets (bytes), 256-edge tiles
#define SM_HDN   0           // 256*272 = 69632 (E1 fp16, then hdn fp16)
#define SM_EA    69632       // 256*48 = 12288
#define SM_W1C   81920       // 6144
#define SM_SIDX  88064       // 1024
#define SM_DIDX  89088       // 1024
#define SM_EIDX  90112       // 1024
#define SMEM_E   91136

// ---- node1 (P/Q) SMEM offsets
#define NSM_X   0
#define NSM_B0  34816
#define NSM_B1  69632
#define NSM_OUT 104448
#define NSM_B1S 139264
#define SMEM_N  139776

// ---- node2 (GEMM2+LN) SMEM offsets
#define N2_W2   0
#define N2_X    34816
#define N2_OUT  69632        // f32 [128][132]
#define N2_B2   137216
#define N2_GAM  137728
#define N2_BET  138240
#define N2_DEG  138752
#define SMEM_N2 139264

__device__ float   g_hsum[(size_t)N_NODES * 128];
__device__ __half  g_pq [(size_t)N_NODES * 256];  // [0:128]=P=h@W1a+b1, [128:256]=Q=h@W1b
__device__ int     g_deg [N_NODES];
__device__ int     g_off [N_NODES];
__device__ int     g_eidx[N_EDGES];

// ---------------------------------------------------------------- helpers
__device__ __forceinline__ uint32_t smem_u32(const void* p) {
    uint32_t a;
    asm("{ .reg .u64 t; cvta.to.shared.u64 t, %1; cvt.u32.u64 %0, t; }"
        : "=r"(a) : "l"(p));
    return a;
}
__device__ __forceinline__ void ldsm4(uint32_t* r, uint32_t addr) {
    asm volatile("ldmatrix.sync.aligned.m8n8.x4.shared.b16 {%0,%1,%2,%3}, [%4];"
                 : "=r"(r[0]), "=r"(r[1]), "=r"(r[2]), "=r"(r[3]) : "r"(addr));
}
__device__ __forceinline__ void mma16816(float* c, const uint32_t* a,
                                         const uint32_t* b) {
    asm volatile("mma.sync.aligned.m16n8k16.row.col.f32.f16.f16.f32 "
                 "{%0,%1,%2,%3}, {%4,%5,%6,%7}, {%8,%9}, {%0,%1,%2,%3};"
                 : "+f"(c[0]), "+f"(c[1]), "+f"(c[2]), "+f"(c[3])
                 : "r"(a[0]), "r"(a[1]), "r"(a[2]), "r"(a[3]),
                   "r"(b[0]), "r"(b[1]));
}
__device__ __forceinline__ uint32_t h2bits(float a, float b) {
    __half2 h = __floats2half2_rn(a, b);
    return *reinterpret_cast<uint32_t*>(&h);
}
// exact-GELU via A&S 7.1.28 rational-power erf (abs err 3e-7), 1 MUFU only
__device__ __forceinline__ float gelu_fast(float v) {
    const float x = v * 0.70710678118654752440f;
    const float s = fabsf(x);
    float p = fmaf(s, 0.0000430638f, 0.0002765672f);
    p = fmaf(s, p, 0.0001520143f);
    p = fmaf(s, p, 0.0092705272f);
    p = fmaf(s, p, 0.0422820123f);
    p = fmaf(s, p, 0.0705230784f);
    p = fmaf(s, p, 1.0f);
    const float p2 = p * p;
    const float p4 = p2 * p2;
    const float p8 = p4 * p4;
    const float p16 = p8 * p8;
    float r;
    asm("rcp.approx.f32 %0, %1;" : "=f"(r) : "f"(p16));
    const float erfs = 1.0f - r;
    return 0.5f * v * (1.0f + copysignf(erfs, x));
}

template <int NCH>
__device__ __forceinline__ void gemm_pass42(float (&c)[2][8][4],
                                            uint32_t abase, uint32_t amstep,
                                            uint32_t bbase, uint32_t bnstep) {
    #pragma unroll
    for (int kc = 0; kc < NCH; ++kc) {
        uint32_t a[2][4], b[4][4];
        ldsm4(a[0], abase);
        ldsm4(a[1], abase + amstep);
        ldsm4(b[0], bbase);
        ldsm4(b[1], bbase + bnstep);
        ldsm4(b[2], bbase + 2 * bnstep);
        ldsm4(b[3], bbase + 3 * bnstep);
        #pragma unroll
        for (int mt = 0; mt < 2; ++mt)
            #pragma unroll
            for (int j = 0; j < 8; ++j)
                mma16816(c[mt][j], a[mt], &b[j >> 1][(j & 1) * 2]);
        abase += 32;
        bbase += 32;
    }
}

// ---------------------------------------------------------------- CSR build
__global__ void prep_kernel() {
    const int n = N_NODES * 128 / 4;
    for (int i = blockIdx.x * blockDim.x + threadIdx.x; i < n;
         i += gridDim.x * blockDim.x) {
        reinterpret_cast<float4*>(g_hsum)[i] = make_float4(0.f, 0.f, 0.f, 0.f);
        if (i < N_NODES) g_deg[i] = 0;
    }
}
__global__ void hist_kernel(const int* __restrict__ dst) {
    int e = blockIdx.x * blockDim.x + threadIdx.x;
    if (e < N_EDGES) atomicAdd(&g_deg[dst[e]], 1);
}
__global__ __launch_bounds__(1024) void scan_kernel() {
    __shared__ int part[1024];
    const int t = threadIdx.x;
    const int start = t * 49;
    const int end   = (start + 49 < N_NODES) ? start + 49 : N_NODES;
    int s = 0;
    for (int i = start; i < end; ++i) s += g_deg[i];
    part[t] = s;
    __syncthreads();
    for (int o = 1; o < 1024; o <<= 1) {
        int v = (t >= o) ? part[t - o] : 0;
        __syncthreads();
        part[t] += v;
        __syncthreads();
    }
    int run = (t == 0) ? 0 : part[t - 1];
    for (int i = start; i < end; ++i) {
        int d = g_deg[i];
        g_off[i] = run;
        run += d;
    }
}
__global__ void fill_kernel(const int* __restrict__ dst) {
    int e = blockIdx.x * blockDim.x + threadIdx.x;
    if (e < N_EDGES) {
        int p = atomicAdd(&g_off[dst[e]], 1);
        g_eidx[p] = e;
    }
}

// ---------------------------------------------------------------- node1: P,Q
__global__ __launch_bounds__(256, 1)
void node_kernel(const float* __restrict__ h,
                 const float* __restrict__ W1, const float* __restrict__ b1) {
    extern __shared__ char smbuf[];
    const uint32_t sb = smem_u32(smbuf);
    float* b1s = reinterpret_cast<float*>(smbuf + NSM_B1S);

    const int t = threadIdx.x, l = t & 31, warp = t >> 5;
    const int wm = warp & 3, wn = warp >> 2;
    const int grow = t & 127, ghf = t >> 7;

    for (int i = t; i < 128 * 128; i += 256) {
        int k = i >> 7, n = i & 127;
        *reinterpret_cast<__half*>(smbuf + NSM_B0 + n * PB2 + k * 2) =
            __float2half_rn(W1[k * 128 + n]);
        *reinterpret_cast<__half*>(smbuf + NSM_B1 + n * PB2 + k * 2) =
            __float2half_rn(W1[(k + 128) * 128 + n]);
    }
    if (t < 128) b1s[t] = b1[t];

    const uint32_t aoff = ((l & 7) + 8 * ((l >> 3) & 1)) * PB2 + (l >> 4) * 16;
    const uint32_t boff = ((l & 7) + 8 * (l >> 4)) * PB2 + ((l >> 3) & 1) * 16;
    const uint32_t aX  = sb + NSM_X + 32 * wm * PB2 + aoff;
    const uint32_t bB0 = sb + NSM_B0 + 64 * wn * PB2 + boff;
    const uint32_t bB1 = sb + NSM_B1 + 64 * wn * PB2 + boff;
    const int rbase = 32 * wm + (l >> 2);
    const int cbase = 64 * wn + 2 * (l & 3);

    const int node = blockIdx.x * 128 + grow;
    const int nc = node < N_NODES ? node : N_NODES - 1;

    {
        const float4* ps = reinterpret_cast<const float4*>(
            h + (size_t)nc * 128 + ghf * 64);
        char* xr = smbuf + NSM_X + grow * PB2 + ghf * 128;
        #pragma unroll
        for (int q = 0; q < 16; ++q) {
            float4 v = ps[q];
            *reinterpret_cast<uint2*>(xr + q * 8) =
                make_uint2(h2bits(v.x, v.y), h2bits(v.z, v.w));
        }
    }
    __syncthreads();

    #pragma unroll
    for (int pass = 0; pass < 2; ++pass) {
        float c[2][8][4];
        #pragma unroll
        for (int mt = 0; mt < 2; ++mt)
            #pragma unroll
            for (int j = 0; j < 8; ++j)
                #pragma unroll
                for (int i = 0; i < 4; ++i) c[mt][j][i] = 0.f;
        gemm_pass42<8>(c, aX, 16 * PB2, pass ? bB1 : bB0, 16 * PB2);
        #pragma unroll
        for (int mt = 0; mt < 2; ++mt)
            #pragma unroll
            for (int j = 0; j < 8; ++j) {
                const int col = cbase + 8 * j;
                const float bb0 = pass ? 0.f : b1s[col];
                const float bb1 = pass ? 0.f : b1s[col + 1];
                #pragma unroll
                for (int rh = 0; rh < 2; ++rh) {
                    const int row = rbase + 16 * mt + 8 * rh;
                    *reinterpret_cast<uint32_t*>(
                        smbuf + NSM_OUT + row * PB2 + col * 2) =
                        h2bits(c[mt][j][2 * rh] + bb0, c[mt][j][2 * rh + 1] + bb1);
                }
            }
        __syncthreads();
        if (node < N_NODES) {
            const uint4* os = reinterpret_cast<const uint4*>(
                smbuf + NSM_OUT + grow * PB2 + ghf * 128);
            uint4* po = reinterpret_cast<uint4*>(
                g_pq + (size_t)node * 256 + pass * 128 + ghf * 64);
            #pragma unroll
            for (int q = 0; q < 8; ++q) po[q] = os[q];
        }
        __syncthreads();
    }
}

// ---------------------------------------------------------------- edge kernel
__global__ __launch_bounds__(512, 2)
void edge_mma_kernel(const int*   __restrict__ src,
                     const int*   __restrict__ dst,
                     const float* __restrict__ ea,
                     const float* __restrict__ W1) {
    extern __shared__ char smbuf[];
    const uint32_t sb = smem_u32(smbuf);
    int* sidx  = reinterpret_cast<int*>(smbuf + SM_SIDX);
    int* didx  = reinterpret_cast<int*>(smbuf + SM_DIDX);
    int* eidxs = reinterpret_cast<int*>(smbuf + SM_EIDX);

    const int t = threadIdx.x, l = t & 31, warp = t >> 5;
    const int wm = warp & 3, wn = warp >> 2;       // 4x4 warp grid (E1 MMA)

    // ---- stage W1c^T (fp16) ----
    for (int i = t; i < 16 * 128; i += 512) {
        int k = i >> 7, n = i & 127;
        *reinterpret_cast<__half*>(smbuf + SM_W1C + n * PBEA + k * 2) =
            __float2half_rn(W1[(k + 256) * 128 + n]);
    }

    const uint32_t aoff48 = ((l & 7) + 8 * ((l >> 3) & 1)) * PBEA + (l >> 4) * 16;
    const uint32_t boff48 = ((l & 7) + 8 * (l >> 4)) * PBEA + ((l >> 3) & 1) * 16;
    const uint32_t aEA  = sb + SM_EA  + 64 * wm * PBEA + aoff48;   // 64 rows/warp
    const uint32_t bW1C = sb + SM_W1C + 32 * wn * PBEA + boff48;
    const int rbase = 64 * wm + (l >> 2);
    const int cbase = 32 * wn + 2 * (l & 3);

    // GELU lane map: 8 distinct rows per LDS phase
    const int gr8 = (t & 7) | ((t >> 5) << 3);     // 0..127
    const int gq  = (t >> 3) & 3;                  // col quarter

    // reduction lane map
    const int rg = t >> 6;                          // 0..7 row group
    const int cp = (t & 63) * 2;                    // col pair

    __syncthreads();

    // preload W1c B-fragments (constant over tiles)
    uint32_t bE1[8];
    ldsm4(&bE1[0], bW1C);
    ldsm4(&bE1[4], bW1C + 16 * PBEA);

    for (int tile = blockIdx.x; tile < NT; tile += gridDim.x) {
        const int e0 = tile << 8;                  // 256 edges/tile
        __syncthreads();
        if (t < 256) {
            const int e = g_eidx[e0 + t];
            eidxs[t] = e;
            sidx[t]  = src[e];
            didx[t]  = dst[e];
        }
        __syncthreads();

        // ---- gather EA (2 thr/row) -> SMEM fp16 ----
        {
            const int row = t >> 1, q2 = t & 1;
            const float4* pe = reinterpret_cast<const float4*>(
                ea + (size_t)eidxs[row] * 16 + q2 * 8);
            char* eb = smbuf + SM_EA + row * PBEA + q2 * 16;
            float4 v0 = pe[0], v1 = pe[1];
            *reinterpret_cast<uint4*>(eb) =
                make_uint4(h2bits(v0.x, v0.y), h2bits(v0.z, v0.w),
                           h2bits(v1.x, v1.y), h2bits(v1.z, v1.w));
        }
        __syncthreads();

        // ---- E1 = ea @ W1c^T (K=16), per-mt register reuse, fp16 -> HDN ----
        #pragma unroll
        for (int mt = 0; mt < 4; ++mt) {
            uint32_t a[4];
            ldsm4(a, aEA + mt * 16 * PBEA);
            float c[4][4];
            #pragma unroll
            for (int j = 0; j < 4; ++j)
                #pragma unroll
                for (int i = 0; i < 4; ++i) c[j][i] = 0.f;
            #pragma unroll
            for (int j = 0; j < 4; ++j)
                mma16816(c[j], a, &bE1[(j >> 1) * 4 + (j & 1) * 2]);
            #pragma unroll
            for (int j = 0; j < 4; ++j) {
                const int col = cbase + 8 * j;
                #pragma unroll
                for (int rh = 0; rh < 2; ++rh) {
                    const int row = rbase + 16 * mt + 8 * rh;
                    *reinterpret_cast<uint32_t*>(
                        smbuf + SM_HDN + row * PB2 + col * 2) =
                        h2bits(c[j][2 * rh], c[j][2 * rh + 1]);
                }
            }
        }
        __syncthreads();

        // ---- hdn = gelu(P[src] + Q[dst] + E1), fp16 in-place ----
        #pragma unroll
        for (int pass = 0; pass < 2; ++pass) {
            const int row = gr8 + pass * 128;
            const uint4* pb = reinterpret_cast<const uint4*>(
                g_pq + (size_t)sidx[row] * 256) + gq * 4;
            const uint4* qb = reinterpret_cast<const uint4*>(
                g_pq + (size_t)didx[row] * 256 + 128) + gq * 4;
            uint4* hb = reinterpret_cast<uint4*>(
                smbuf + SM_HDN + row * PB2 + gq * 64);
            #pragma unroll
            for (int i = 0; i < 4; ++i) {
                const uint4 pv = pb[i];
                const uint4 qv = qb[i];
                const uint4 ev = hb[i];
                const __half2* ph = reinterpret_cast<const __half2*>(&pv);
                const __half2* qh = reinterpret_cast<const __half2*>(&qv);
                const __half2* eh = reinterpret_cast<const __half2*>(&ev);
                uint4 o;
                uint32_t* op = reinterpret_cast<uint32_t*>(&o);
                #pragma unroll
                for (int w = 0; w < 4; ++w) {
                    float2 pf = __half22float2(ph[w]);
                    float2 qf = __half22float2(qh[w]);
                    float2 ef = __half22float2(eh[w]);
                    op[w] = h2bits(gelu_fast(pf.x + qf.x + ef.x),
                                   gelu_fast(pf.y + qf.y + ef.y));
                }
                hb[i] = o;
            }
        }
        __syncthreads();

        // ---- segmented column reduction over dst runs -> g_hsum ----
        {
            float ax = 0.f, ay = 0.f;
            #pragma unroll 8
            for (int r = 0; r < 32; ++r) {
                const int row = rg * 32 + r;
                const uint32_t v = *reinterpret_cast<const uint32_t*>(
                    smbuf + SM_HDN + row * PB2 + cp * 2);
                const float2 f = __half22float2(
                    *reinterpret_cast<const __half2*>(&v));
                ax += f.x;
                ay += f.y;
                const bool flush =
                    (r == 31) || (didx[row] != didx[row + 1]);
                if (flush) {
                    asm volatile("red.global.add.v2.f32 [%0], {%1,%2};"
                                 :: "l"(g_hsum + (size_t)didx[row] * 128 + cp),
                                    "f"(ax), "f"(ay) : "memory");
                    ax = 0.f; ay = 0.f;
                }
            }
        }
    }
}

// ---------------------------------------------------------------- node2:
// out = LayerNorm(h + hsum @ W2 + deg*b2)
__global__ __launch_bounds__(256, 1)
void node2_kernel(const float* __restrict__ h,
                  const float* __restrict__ W2,
                  const float* __restrict__ b2,
                  const float* __restrict__ gamma,
                  const float* __restrict__ beta,
                  float* __restrict__ out) {
    extern __shared__ char smbuf[];
    const uint32_t sb = smem_u32(smbuf);
    float* b2s = reinterpret_cast<float*>(smbuf + N2_B2);
    float* gms = reinterpret_cast<float*>(smbuf + N2_GAM);
    float* bts = reinterpret_cast<float*>(smbuf + N2_BET);
    int*   dgs = reinterpret_cast<int*>(smbuf + N2_DEG);
    float* outs = reinterpret_cast<float*>(smbuf + N2_OUT);

    const int t = threadIdx.x, l = t & 31, warp = t >> 5;
    const int wm = warp & 3, wn = warp >> 2;
    const int grow = t & 127, ghf = t >> 7;

    for (int i = t; i < 128 * 128; i += 256) {
        int k = i >> 7, n = i & 127;
        *reinterpret_cast<__half*>(smbuf + N2_W2 + n * PB2 + k * 2) =
            __float2half_rn(W2[i]);
    }
    if (t < 128) { b2s[t] = b2[t]; gms[t] = gamma[t]; bts[t] = beta[t]; }

    const int node = blockIdx.x * 128 + grow;
    const int nc = node < N_NODES ? node : N_NODES - 1;
    if (t >= 128 && t < 256) {
        int nn = blockIdx.x * 128 + (t - 128);
        dgs[t - 128] = (nn < N_NODES) ? g_deg[nn] : 0;
    }

    {
        const float4* ps = reinterpret_cast<const float4*>(
            g_hsum + (size_t)nc * 128 + ghf * 64);
        char* xr = smbuf + N2_X + grow * PB2 + ghf * 128;
        #pragma unroll
        for (int q = 0; q < 16; ++q) {
            float4 v = ps[q];
            *reinterpret_cast<uint2*>(xr + q * 8) =
                make_uint2(h2bits(v.x, v.y), h2bits(v.z, v.w));
        }
    }
    __syncthreads();

    const uint32_t aoff = ((l & 7) + 8 * ((l >> 3) & 1)) * PB2 + (l >> 4) * 16;
    const uint32_t boff = ((l & 7) + 8 * (l >> 4)) * PB2 + ((l >> 3) & 1) * 16;
    const uint32_t aX = sb + N2_X + 32 * wm * PB2 + aoff;
    const uint32_t bW = sb + N2_W2 + 64 * wn * PB2 + boff;
    const int rbase = 32 * wm + (l >> 2);
    const int cbase = 64 * wn + 2 * (l & 3);

    float c[2][8][4];
    #pragma unroll
    for (int mt = 0; mt < 2; ++mt)
        #pragma unroll
        for (int j = 0; j < 8; ++j)
            #pragma unroll
            for (int i = 0; i < 4; ++i) c[mt][j][i] = 0.f;
    gemm_pass42<8>(c, aX, 16 * PB2, bW, 16 * PB2);

    #pragma unroll
    for (int mt = 0; mt < 2; ++mt)
        #pragma unroll
        for (int j = 0; j < 8; ++j) {
            const int col = cbase + 8 * j;
            const float bb0 = b2s[col], bb1 = b2s[col + 1];
            #pragma unroll
            for (int rh = 0; rh < 2; ++rh) {
                const int row = rbase + 16 * mt + 8 * rh;
                const float dg = (float)dgs[row];
                outs[row * 132 + col]     = c[mt][j][2 * rh] + dg * bb0;
                outs[row * 132 + col + 1] = c[mt][j][2 * rh + 1] + dg * bb1;
            }
        }
    __syncthreads();

    for (int r = 0; r < 16; ++r) {
        const int row = warp * 16 + r;
        const int nn = blockIdx.x * 128 + row;
        if (nn >= N_NODES) break;
        const float4 hv = reinterpret_cast<const float4*>(h)[(size_t)nn * 32 + l];
        const float4 av = *reinterpret_cast<const float4*>(outs + row * 132 + l * 4);
        float4 x;
        x.x = hv.x + av.x; x.y = hv.y + av.y;
        x.z = hv.z + av.z; x.w = hv.w + av.w;
        float s = x.x + x.y + x.z + x.w;
        #pragma unroll
        for (int o = 16; o > 0; o >>= 1) s += __shfl_xor_sync(0xffffffffu, s, o);
        const float mu = s * (1.0f / 128.0f);
        const float dx = x.x - mu, dy = x.y - mu, dz = x.z - mu, dw = x.w - mu;
        float q = dx * dx + dy * dy + dz * dz + dw * dw;
        #pragma unroll
        for (int o = 16; o > 0; o >>= 1) q += __shfl_xor_sync(0xffffffffu, q, o);
        const float inv = rsqrtf(q * (1.0f / 128.0f) + 1e-5f);
        float4 o4;
        o4.x = dx * inv * gms[l * 4 + 0] + bts[l * 4 + 0];
        o4.y = dy * inv * gms[l * 4 + 1] + bts[l * 4 + 1];
        o4.z = dz * inv * gms[l * 4 + 2] + bts[l * 4 + 2];
        o4.w = dw * inv * gms[l * 4 + 3] + bts[l * 4 + 3];
        reinterpret_cast<float4*>(out)[(size_t)nn * 32 + l] = o4;
    }
}

// ----------------------------------------------------------------
extern "C" void kernel_launch(void* const* d_in, const int* in_sizes, int n_in,
                              void* d_out, int out_size) {
    const float* h     = (const float*)d_in[0];
    const int*   src   = (const int*)  d_in[1];
    const int*   dst   = (const int*)  d_in[2];
    const float* ea    = (const float*)d_in[3];
    const float* W1    = (const float*)d_in[4];
    const float* b1    = (const float*)d_in[5];
    const float* W2    = (const float*)d_in[6];
    const float* b2    = (const float*)d_in[7];
    const float* gamma = (const float*)d_in[8];
    const float* beta  = (const float*)d_in[9];
    float*       out   = (float*)d_out;

    static int sm_count = []() {
        int dev = 0, c = 148;
        cudaGetDevice(&dev);
        cudaDeviceGetAttribute(&c, cudaDevAttrMultiProcessorCount, dev);
        return c;
    }();
    static bool attr_ok = []() {
        cudaFuncSetAttribute(edge_mma_kernel,
                             cudaFuncAttributeMaxDynamicSharedMemorySize, SMEM_E);
        cudaFuncSetAttribute(node_kernel,
                             cudaFuncAttributeMaxDynamicSharedMemorySize, SMEM_N);
        cudaFuncSetAttribute(node2_kernel,
                             cudaFuncAttributeMaxDynamicSharedMemorySize, SMEM_N2);
        return true;
    }();
    (void)attr_ok;

    prep_kernel<<<2048, 256>>>();
    hist_kernel<<<(N_EDGES + 255) / 256, 256>>>(dst);
    scan_kernel<<<1, 1024>>>();
    fill_kernel<<<(N_EDGES + 255) / 256, 256>>>(dst);
    node_kernel<<<NNT, 256, SMEM_N>>>(h, W1, b1);
    edge_mma_kernel<<<2 * sm_count, 512, SMEM_E>>>(src, dst, ea, W1);
    node2_kernel<<<NNT, 256, SMEM_N2>>>(h, W2, b2, gamma, beta, out);
}

// round 11
// speedup vs baseline: 12.6523x; 1.0063x over previous
#include <cuda_runtime.h>
#include <cuda_fp16.h>
#include <math.h>
#include <stdint.h>

#define N_NODES 50000
#define N_EDGES 1600000
#define NT      6250        // edge tiles of 256
#define NNT     391         // node tiles of 128

// ---- pitches
#define PB2  272    // fp16 [.][k=128 pad] (ldmatrix layout / hdn pitch)
#define PBEA 48     // fp16 [.][k=16 pad]

// ---- edge-kernel SMEM offsets (bytes), 256-edge tiles
#define SM_HDN   0           // 256*272 = 69632 (E1 fp16, then hdn fp16)
#define SM_EA    69632       // 12288
#define SM_W1C   81920       // 6144
#define SM_SIDX  88064       // 1024
#define SM_DIDX  89088       // 1024
#define SM_EIDX  90112       // 1024
#define SMEM_E   91136

// ---- node1 (P/Q) SMEM offsets
#define NSM_X   0
#define NSM_B0  34816
#define NSM_B1  69632
#define NSM_OUT 104448
#define NSM_B1S 139264
#define SMEM_N  139776

// ---- node2 (GEMM2+LN) SMEM offsets
#define N2_W2   0
#define N2_X    34816
#define N2_OUT  69632        // f32 [128][132]
#define N2_B2   137216
#define N2_GAM  137728
#define N2_BET  138240
#define N2_DEG  138752
#define SMEM_N2 139264

__device__ float   g_hsum[(size_t)N_NODES * 128];
__device__ __half  g_pq [(size_t)N_NODES * 256];  // [0:128]=P=h@W1a+b1, [128:256]=Q=h@W1b
__device__ int     g_deg [N_NODES];
__device__ int     g_off [N_NODES];
__device__ int     g_eidx[N_EDGES];

// ---------------------------------------------------------------- helpers
__device__ __forceinline__ uint32_t smem_u32(const void* p) {
    uint32_t a;
    asm("{ .reg .u64 t; cvta.to.shared.u64 t, %1; cvt.u32.u64 %0, t; }"
        : "=r"(a) : "l"(p));
    return a;
}
__device__ __forceinline__ void ldsm4(uint32_t* r, uint32_t addr) {
    asm volatile("ldmatrix.sync.aligned.m8n8.x4.shared.b16 {%0,%1,%2,%3}, [%4];"
                 : "=r"(r[0]), "=r"(r[1]), "=r"(r[2]), "=r"(r[3]) : "r"(addr));
}
__device__ __forceinline__ void mma16816(float* c, const uint32_t* a,
                                         const uint32_t* b) {
    asm volatile("mma.sync.aligned.m16n8k16.row.col.f32.f16.f16.f32 "
                 "{%0,%1,%2,%3}, {%4,%5,%6,%7}, {%8,%9}, {%0,%1,%2,%3};"
                 : "+f"(c[0]), "+f"(c[1]), "+f"(c[2]), "+f"(c[3])
                 : "r"(a[0]), "r"(a[1]), "r"(a[2]), "r"(a[3]),
                   "r"(b[0]), "r"(b[1]));
}
__device__ __forceinline__ uint32_t h2bits(float a, float b) {
    __half2 h = __floats2half2_rn(a, b);
    return *reinterpret_cast<uint32_t*>(&h);
}
// exact-GELU via A&S 7.1.26 erf (abs err 1.5e-7): 2 MUFU + ~10 FMA
// (balances FMA/MUFU pipes: MUFU otherwise idle in this kernel)
__device__ __forceinline__ float gelu_fast(float v) {
    const float x = v * 0.70710678118654752440f;
    const float s = fabsf(x);
    float t;
    asm("rcp.approx.f32 %0, %1;" : "=f"(t)
        : "f"(fmaf(0.3275911f, s, 1.0f)));
    const float e = __expf(-s * s);
    float p = fmaf(t, 1.061405429f, -1.453152027f);
    p = fmaf(t, p, 1.421413741f);
    p = fmaf(t, p, -0.284496736f);
    p = fmaf(t, p, 0.254829592f);
    p = p * t;
    const float erfs = fmaf(-p, e, 1.0f);
    return 0.5f * v * (1.0f + copysignf(erfs, x));
}

template <int NCH>
__device__ __forceinline__ void gemm_pass42(float (&c)[2][8][4],
                                            uint32_t abase, uint32_t amstep,
                                            uint32_t bbase, uint32_t bnstep) {
    #pragma unroll
    for (int kc = 0; kc < NCH; ++kc) {
        uint32_t a[2][4], b[4][4];
        ldsm4(a[0], abase);
        ldsm4(a[1], abase + amstep);
        ldsm4(b[0], bbase);
        ldsm4(b[1], bbase + bnstep);
        ldsm4(b[2], bbase + 2 * bnstep);
        ldsm4(b[3], bbase + 3 * bnstep);
        #pragma unroll
        for (int mt = 0; mt < 2; ++mt)
            #pragma unroll
            for (int j = 0; j < 8; ++j)
                mma16816(c[mt][j], a[mt], &b[j >> 1][(j & 1) * 2]);
        abase += 32;
        bbase += 32;
    }
}

// ---------------------------------------------------------------- CSR build
__global__ void prep_kernel() {
    const int n = N_NODES * 128 / 4;
    for (int i = blockIdx.x * blockDim.x + threadIdx.x; i < n;
         i += gridDim.x * blockDim.x) {
        reinterpret_cast<float4*>(g_hsum)[i] = make_float4(0.f, 0.f, 0.f, 0.f);
        if (i < N_NODES) g_deg[i] = 0;
    }
}
// 4 independent edges/thread: ATOMG latency-bound -> ILP
__global__ void hist_kernel(const int* __restrict__ dst) {
    const int base = (blockIdx.x * blockDim.x + threadIdx.x) * 4;
    if (base + 3 < N_EDGES) {
        const int4 d = *reinterpret_cast<const int4*>(dst + base);
        atomicAdd(&g_deg[d.x], 1);
        atomicAdd(&g_deg[d.y], 1);
        atomicAdd(&g_deg[d.z], 1);
        atomicAdd(&g_deg[d.w], 1);
    } else {
        for (int e = base; e < N_EDGES; ++e) atomicAdd(&g_deg[dst[e]], 1);
    }
}
__global__ __launch_bounds__(1024) void scan_kernel() {
    __shared__ int part[1024];
    const int t = threadIdx.x;
    const int start = t * 49;
    const int end   = (start + 49 < N_NODES) ? start + 49 : N_NODES;
    int s = 0;
    for (int i = start; i < end; ++i) s += g_deg[i];
    part[t] = s;
    __syncthreads();
    for (int o = 1; o < 1024; o <<= 1) {
        int v = (t >= o) ? part[t - o] : 0;
        __syncthreads();
        part[t] += v;
        __syncthreads();
    }
    int run = (t == 0) ? 0 : part[t - 1];
    for (int i = start; i < end; ++i) {
        int d = g_deg[i];
        g_off[i] = run;
        run += d;
    }
}
__global__ void fill_kernel(const int* __restrict__ dst) {
    const int base = (blockIdx.x * blockDim.x + threadIdx.x) * 4;
    if (base + 3 < N_EDGES) {
        const int4 d = *reinterpret_cast<const int4*>(dst + base);
        const int p0 = atomicAdd(&g_off[d.x], 1);
        const int p1 = atomicAdd(&g_off[d.y], 1);
        const int p2 = atomicAdd(&g_off[d.z], 1);
        const int p3 = atomicAdd(&g_off[d.w], 1);
        g_eidx[p0] = base;
        g_eidx[p1] = base + 1;
        g_eidx[p2] = base + 2;
        g_eidx[p3] = base + 3;
    } else {
        for (int e = base; e < N_EDGES; ++e) {
            int p = atomicAdd(&g_off[dst[e]], 1);
            g_eidx[p] = e;
        }
    }
}

// ---------------------------------------------------------------- node1: P,Q
__global__ __launch_bounds__(256, 1)
void node_kernel(const float* __restrict__ h,
                 const float* __restrict__ W1, const float* __restrict__ b1) {
    extern __shared__ char smbuf[];
    const uint32_t sb = smem_u32(smbuf);
    float* b1s = reinterpret_cast<float*>(smbuf + NSM_B1S);

    const int t = threadIdx.x, l = t & 31, warp = t >> 5;
    const int wm = warp & 3, wn = warp >> 2;
    const int grow = t & 127, ghf = t >> 7;

    for (int i = t; i < 128 * 128; i += 256) {
        int k = i >> 7, n = i & 127;
        *reinterpret_cast<__half*>(smbuf + NSM_B0 + n * PB2 + k * 2) =
            __float2half_rn(W1[k * 128 + n]);
        *reinterpret_cast<__half*>(smbuf + NSM_B1 + n * PB2 + k * 2) =
            __float2half_rn(W1[(k + 128) * 128 + n]);
    }
    if (t < 128) b1s[t] = b1[t];

    const uint32_t aoff = ((l & 7) + 8 * ((l >> 3) & 1)) * PB2 + (l >> 4) * 16;
    const uint32_t boff = ((l & 7) + 8 * (l >> 4)) * PB2 + ((l >> 3) & 1) * 16;
    const uint32_t aX  = sb + NSM_X + 32 * wm * PB2 + aoff;
    const uint32_t bB0 = sb + NSM_B0 + 64 * wn * PB2 + boff;
    const uint32_t bB1 = sb + NSM_B1 + 64 * wn * PB2 + boff;
    const int rbase = 32 * wm + (l >> 2);
    const int cbase = 64 * wn + 2 * (l & 3);

    const int node = blockIdx.x * 128 + grow;
    const int nc = node < N_NODES ? node : N_NODES - 1;

    {
        const float4* ps = reinterpret_cast<const float4*>(
            h + (size_t)nc * 128 + ghf * 64);
        char* xr = smbuf + NSM_X + grow * PB2 + ghf * 128;
        #pragma unroll
        for (int q = 0; q < 16; ++q) {
            float4 v = ps[q];
            *reinterpret_cast<uint2*>(xr + q * 8) =
                make_uint2(h2bits(v.x, v.y), h2bits(v.z, v.w));
        }
    }
    __syncthreads();

    #pragma unroll
    for (int pass = 0; pass < 2; ++pass) {
        float c[2][8][4];
        #pragma unroll
        for (int mt = 0; mt < 2; ++mt)
            #pragma unroll
            for (int j = 0; j < 8; ++j)
                #pragma unroll
                for (int i = 0; i < 4; ++i) c[mt][j][i] = 0.f;
        gemm_pass42<8>(c, aX, 16 * PB2, pass ? bB1 : bB0, 16 * PB2);
        #pragma unroll
        for (int mt = 0; mt < 2; ++mt)
            #pragma unroll
            for (int j = 0; j < 8; ++j) {
                const int col = cbase + 8 * j;
                const float bb0 = pass ? 0.f : b1s[col];
                const float bb1 = pass ? 0.f : b1s[col + 1];
                #pragma unroll
                for (int rh = 0; rh < 2; ++rh) {
                    const int row = rbase + 16 * mt + 8 * rh;
                    *reinterpret_cast<uint32_t*>(
                        smbuf + NSM_OUT + row * PB2 + col * 2) =
                        h2bits(c[mt][j][2 * rh] + bb0, c[mt][j][2 * rh + 1] + bb1);
                }
            }
        __syncthreads();
        if (node < N_NODES) {
            const uint4* os = reinterpret_cast<const uint4*>(
                smbuf + NSM_OUT + grow * PB2 + ghf * 128);
            uint4* po = reinterpret_cast<uint4*>(
                g_pq + (size_t)node * 256 + pass * 128 + ghf * 64);
            #pragma unroll
            for (int q = 0; q < 8; ++q) po[q] = os[q];
        }
        __syncthreads();
    }
}

// ---------------------------------------------------------------- edge kernel
__global__ __launch_bounds__(512, 2)
void edge_mma_kernel(const int*   __restrict__ src,
                     const int*   __restrict__ dst,
                     const float* __restrict__ ea,
                     const float* __restrict__ W1) {
    extern __shared__ char smbuf[];
    const uint32_t sb = smem_u32(smbuf);
    int* sidx  = reinterpret_cast<int*>(smbuf + SM_SIDX);
    int* didx  = reinterpret_cast<int*>(smbuf + SM_DIDX);
    int* eidxs = reinterpret_cast<int*>(smbuf + SM_EIDX);

    const int t = threadIdx.x, l = t & 31, warp = t >> 5;
    const int wm = warp & 3, wn = warp >> 2;       // 4x4 warp grid (E1 MMA)

    // ---- stage W1c^T (fp16) ----
    for (int i = t; i < 16 * 128; i += 512) {
        int k = i >> 7, n = i & 127;
        *reinterpret_cast<__half*>(smbuf + SM_W1C + n * PBEA + k * 2) =
            __float2half_rn(W1[(k + 256) * 128 + n]);
    }

    const uint32_t aoff48 = ((l & 7) + 8 * ((l >> 3) & 1)) * PBEA + (l >> 4) * 16;
    const uint32_t boff48 = ((l & 7) + 8 * (l >> 4)) * PBEA + ((l >> 3) & 1) * 16;
    const uint32_t aEA  = sb + SM_EA  + 64 * wm * PBEA + aoff48;   // 64 rows/warp
    const uint32_t bW1C = sb + SM_W1C + 32 * wn * PBEA + boff48;
    const int rbase = 64 * wm + (l >> 2);
    const int cbase = 32 * wn + 2 * (l & 3);

    // GELU lane map: 8 distinct rows per LDS phase
    const int gr8 = (t & 7) | ((t >> 5) << 3);     // 0..127
    const int gq  = (t >> 3) & 3;                  // col quarter

    // reduction lane map
    const int rg = t >> 6;                          // 0..7 row group
    const int cp = (t & 63) * 2;                    // col pair

    __syncthreads();

    // preload W1c B-fragments (constant over tiles)
    uint32_t bE1[8];
    ldsm4(&bE1[0], bW1C);
    ldsm4(&bE1[4], bW1C + 16 * PBEA);

    for (int tile = blockIdx.x; tile < NT; tile += gridDim.x) {
        const int e0 = tile << 8;                  // 256 edges/tile
        __syncthreads();
        if (t < 256) {
            const int e = g_eidx[e0 + t];
            eidxs[t] = e;
            sidx[t]  = src[e];
            didx[t]  = dst[e];
        }
        __syncthreads();

        // ---- gather EA (2 thr/row) -> SMEM fp16 ----
        {
            const int row = t >> 1, q2 = t & 1;
            const float4* pe = reinterpret_cast<const float4*>(
                ea + (size_t)eidxs[row] * 16 + q2 * 8);
            char* eb = smbuf + SM_EA + row * PBEA + q2 * 16;
            float4 v0 = pe[0], v1 = pe[1];
            *reinterpret_cast<uint4*>(eb) =
                make_uint4(h2bits(v0.x, v0.y), h2bits(v0.z, v0.w),
                           h2bits(v1.x, v1.y), h2bits(v1.z, v1.w));
        }
        __syncthreads();

        // ---- E1 = ea @ W1c^T (K=16), per-mt register reuse, fp16 -> HDN ----
        #pragma unroll
        for (int mt = 0; mt < 4; ++mt) {
            uint32_t a[4];
            ldsm4(a, aEA + mt * 16 * PBEA);
            float c[4][4];
            #pragma unroll
            for (int j = 0; j < 4; ++j)
                #pragma unroll
                for (int i = 0; i < 4; ++i) c[j][i] = 0.f;
            #pragma unroll
            for (int j = 0; j < 4; ++j)
                mma16816(c[j], a, &bE1[(j >> 1) * 4 + (j & 1) * 2]);
            #pragma unroll
            for (int j = 0; j < 4; ++j) {
                const int col = cbase + 8 * j;
                #pragma unroll
                for (int rh = 0; rh < 2; ++rh) {
                    const int row = rbase + 16 * mt + 8 * rh;
                    *reinterpret_cast<uint32_t*>(
                        smbuf + SM_HDN + row * PB2 + col * 2) =
                        h2bits(c[j][2 * rh], c[j][2 * rh + 1]);
                }
            }
        }
        __syncthreads();

        // ---- hdn = gelu(P[src] + Q[dst] + E1), fp16 in-place; HADD2 sums ----
        #pragma unroll
        for (int pass = 0; pass < 2; ++pass) {
            const int row = gr8 + pass * 128;
            const uint4* pb = reinterpret_cast<const uint4*>(
                g_pq + (size_t)sidx[row] * 256) + gq * 4;
            const uint4* qb = reinterpret_cast<const uint4*>(
                g_pq + (size_t)didx[row] * 256 + 128) + gq * 4;
            uint4* hb = reinterpret_cast<uint4*>(
                smbuf + SM_HDN + row * PB2 + gq * 64);
            #pragma unroll
            for (int i = 0; i < 4; ++i) {
                const uint4 pv = pb[i];
                const uint4 qv = qb[i];
                const uint4 ev = hb[i];
                const __half2* ph = reinterpret_cast<const __half2*>(&pv);
                const __half2* qh = reinterpret_cast<const __half2*>(&qv);
                const __half2* eh = reinterpret_cast<const __half2*>(&ev);
                uint4 o;
                uint32_t* op = reinterpret_cast<uint32_t*>(&o);
                #pragma unroll
                for (int w = 0; w < 4; ++w) {
                    const __half2 sh = __hadd2(__hadd2(ph[w], qh[w]), eh[w]);
                    const float2 sf = __half22float2(sh);
                    op[w] = h2bits(gelu_fast(sf.x), gelu_fast(sf.y));
                }
                hb[i] = o;
            }
        }
        __syncthreads();

        // ---- segmented column reduction over dst runs -> g_hsum ----
        {
            float ax = 0.f, ay = 0.f;
            #pragma unroll 8
            for (int r = 0; r < 32; ++r) {
                const int row = rg * 32 + r;
                const uint32_t v = *reinterpret_cast<const uint32_t*>(
                    smbuf + SM_HDN + row * PB2 + cp * 2);
                const float2 f = __half22float2(
                    *reinterpret_cast<const __half2*>(&v));
                ax += f.x;
                ay += f.y;
                const bool flush =
                    (r == 31) || (didx[row] != didx[row + 1]);
                if (flush) {
                    asm volatile("red.global.add.v2.f32 [%0], {%1,%2};"
                                 :: "l"(g_hsum + (size_t)didx[row] * 128 + cp),
                                    "f"(ax), "f"(ay) : "memory");
                    ax = 0.f; ay = 0.f;
                }
            }
        }
    }
}

// ---------------------------------------------------------------- node2:
// out = LayerNorm(h + hsum @ W2 + deg*b2)
__global__ __launch_bounds__(256, 1)
void node2_kernel(const float* __restrict__ h,
                  const float* __restrict__ W2,
                  const float* __restrict__ b2,
                  const float* __restrict__ gamma,
                  const float* __restrict__ beta,
                  float* __restrict__ out) {
    extern __shared__ char smbuf[];
    const uint32_t sb = smem_u32(smbuf);
    float* b2s = reinterpret_cast<float*>(smbuf + N2_B2);
    float* gms = reinterpret_cast<float*>(smbuf + N2_GAM);
    float* bts = reinterpret_cast<float*>(smbuf + N2_BET);
    int*   dgs = reinterpret_cast<int*>(smbuf + N2_DEG);
    float* outs = reinterpret_cast<float*>(smbuf + N2_OUT);

    const int t = threadIdx.x, l = t & 31, warp = t >> 5;
    const int wm = warp & 3, wn = warp >> 2;
    const int grow = t & 127, ghf = t >> 7;

    for (int i = t; i < 128 * 128; i += 256) {
        int k = i >> 7, n = i & 127;
        *reinterpret_cast<__half*>(smbuf + N2_W2 + n * PB2 + k * 2) =
            __float2half_rn(W2[i]);
    }
    if (t < 128) { b2s[t] = b2[t]; gms[t] = gamma[t]; bts[t] = beta[t]; }

    const int node = blockIdx.x * 128 + grow;
    const int nc = node < N_NODES ? node : N_NODES - 1;
    if (t >= 128 && t < 256) {
        int nn = blockIdx.x * 128 + (t - 128);
        dgs[t - 128] = (nn < N_NODES) ? g_deg[nn] : 0;
    }

    {
        const float4* ps = reinterpret_cast<const float4*>(
            g_hsum + (size_t)nc * 128 + ghf * 64);
        char* xr = smbuf + N2_X + grow * PB2 + ghf * 128;
        #pragma unroll
        for (int q = 0; q < 16; ++q) {
            float4 v = ps[q];
            *reinterpret_cast<uint2*>(xr + q * 8) =
                make_uint2(h2bits(v.x, v.y), h2bits(v.z, v.w));
        }
    }
    __syncthreads();

    const uint32_t aoff = ((l & 7) + 8 * ((l >> 3) & 1)) * PB2 + (l >> 4) * 16;
    const uint32_t boff = ((l & 7) + 8 * (l >> 4)) * PB2 + ((l >> 3) & 1) * 16;
    const uint32_t aX = sb + N2_X + 32 * wm * PB2 + aoff;
    const uint32_t bW = sb + N2_W2 + 64 * wn * PB2 + boff;
    const int rbase = 32 * wm + (l >> 2);
    const int cbase = 64 * wn + 2 * (l & 3);

    float c[2][8][4];
    #pragma unroll
    for (int mt = 0; mt < 2; ++mt)
        #pragma unroll
        for (int j = 0; j < 8; ++j)
            #pragma unroll
            for (int i = 0; i < 4; ++i) c[mt][j][i] = 0.f;
    gemm_pass42<8>(c, aX, 16 * PB2, bW, 16 * PB2);

    #pragma unroll
    for (int mt = 0; mt < 2; ++mt)
        #pragma unroll
        for (int j = 0; j < 8; ++j) {
            const int col = cbase + 8 * j;
            const float bb0 = b2s[col], bb1 = b2s[col + 1];
            #pragma unroll
            for (int rh = 0; rh < 2; ++rh) {
                const int row = rbase + 16 * mt + 8 * rh;
                const float dg = (float)dgs[row];
                outs[row * 132 + col]     = c[mt][j][2 * rh] + dg * bb0;
                outs[row * 132 + col + 1] = c[mt][j][2 * rh + 1] + dg * bb1;
            }
        }
    __syncthreads();

    for (int r = 0; r < 16; ++r) {
        const int row = warp * 16 + r;
        const int nn = blockIdx.x * 128 + row;
        if (nn >= N_NODES) break;
        const float4 hv = reinterpret_cast<const float4*>(h)[(size_t)nn * 32 + l];
        const float4 av = *reinterpret_cast<const float4*>(outs + row * 132 + l * 4);
        float4 x;
        x.x = hv.x + av.x; x.y = hv.y + av.y;
        x.z = hv.z + av.z; x.w = hv.w + av.w;
        float s = x.x + x.y + x.z + x.w;
        #pragma unroll
        for (int o = 16; o > 0; o >>= 1) s += __shfl_xor_sync(0xffffffffu, s, o);
        const float mu = s * (1.0f / 128.0f);
        const float dx = x.x - mu, dy = x.y - mu, dz = x.z - mu, dw = x.w - mu;
        float q = dx * dx + dy * dy + dz * dz + dw * dw;
        #pragma unroll
        for (int o = 16; o > 0; o >>= 1) q += __shfl_xor_sync(0xffffffffu, q, o);
        const float inv = rsqrtf(q * (1.0f / 128.0f) + 1e-5f);
        float4 o4;
        o4.x = dx * inv * gms[l * 4 + 0] + bts[l * 4 + 0];
        o4.y = dy * inv * gms[l * 4 + 1] + bts[l * 4 + 1];
        o4.z = dz * inv * gms[l * 4 + 2] + bts[l * 4 + 2];
        o4.w = dw * inv * gms[l * 4 + 3] + bts[l * 4 + 3];
        reinterpret_cast<float4*>(out)[(size_t)nn * 32 + l] = o4;
    }
}

// ----------------------------------------------------------------
extern "C" void kernel_launch(void* const* d_in, const int* in_sizes, int n_in,
                              void* d_out, int out_size) {
    const float* h     = (const float*)d_in[0];
    const int*   src   = (const int*)  d_in[1];
    const int*   dst   = (const int*)  d_in[2];
    const float* ea    = (const float*)d_in[3];
    const float* W1    = (const float*)d_in[4];
    const float* b1    = (const float*)d_in[5];
    const float* W2    = (const float*)d_in[6];
    const float* b2    = (const float*)d_in[7];
    const float* gamma = (const float*)d_in[8];
    const float* beta  = (const float*)d_in[9];
    float*       out   = (float*)d_out;

    static int sm_count = []() {
        int dev = 0, c = 148;
        cudaGetDevice(&dev);
        cudaDeviceGetAttribute(&c, cudaDevAttrMultiProcessorCount, dev);
        return c;
    }();
    static bool attr_ok = []() {
        cudaFuncSetAttribute(edge_mma_kernel,
                             cudaFuncAttributeMaxDynamicSharedMemorySize, SMEM_E);
        cudaFuncSetAttribute(node_kernel,
                             cudaFuncAttributeMaxDynamicSharedMemorySize, SMEM_N);
        cudaFuncSetAttribute(node2_kernel,
                             cudaFuncAttributeMaxDynamicSharedMemorySize, SMEM_N2);
        return true;
    }();
    (void)attr_ok;

    prep_kernel<<<2048, 256>>>();
    hist_kernel<<<(N_EDGES / 4 + 255) / 256, 256>>>(dst);
    scan_kernel<<<1, 1024>>>();
    fill_kernel<<<(N_EDGES / 4 + 255) / 256, 256>>>(dst);
    node_kernel<<<NNT, 256, SMEM_N>>>(h, W1, b1);
    edge_mma_kernel<<<2 * sm_count, 512, SMEM_E>>>(src, dst, ea, W1);
    node2_kernel<<<NNT, 256, SMEM_N2>>>(h, W2, b2, gamma, beta, out);
}